// round 1
// baseline (speedup 1.0000x reference)
#include <cuda_runtime.h>
#include <math.h>

// ---------------- problem dims ----------------
constexpr int BSZ = 16;
constexpr int SEQ = 1024;
constexpr int DM  = 512;
constexpr int NG  = 4;
constexpr int CG  = 128;   // DM/NG
constexpr int NH  = 8;
constexpr int CH  = 64;    // DM/NH
constexpr int NP  = 127;
constexpr int PL  = 16;
constexpr int P2  = NP * PL; // 2032

// ---------------- scratch (device globals; no allocation allowed) ----------
__device__ float g_xn[(size_t)BSZ*SEQ*DM];
__device__ float g_q [(size_t)BSZ*SEQ*DM];
__device__ float g_w1[BSZ*NG*SEQ];
__device__ float g_conc[(size_t)BSZ*SEQ*2*DM];
__device__ float g_y [(size_t)BSZ*P2*DM];
__device__ float g_Weff[3*CG];
__device__ float g_beff[1];
__device__ float g_m [BSZ*DM];
__device__ float g_Kg[BSZ*NG*DM];
__device__ float g_Vg[BSZ*NG*DM];
__device__ float g_Qw[BSZ*NG*DM];
__device__ float g_Qs[BSZ*DM];
__device__ float g_Ag[BSZ*NG*DM];
__device__ float g_Ab[BSZ*DM];
__device__ float g_AgWo[BSZ*NG*DM];
__device__ float g_AbWo[BSZ*DM];
__device__ float g_wocs[DM];

__device__ __forceinline__ float warp_sum(float v) {
  #pragma unroll
  for (int o = 16; o; o >>= 1) v += __shfl_xor_sync(0xffffffffu, v, o);
  return v;
}

// ---------------- LayerNorm: one block per row ----------------
__global__ void ln_kernel(const float* __restrict__ x,
                          const float* __restrict__ lw,
                          const float* __restrict__ lb,
                          float* __restrict__ xn) {
  long row = blockIdx.x;
  const float* xr = x + row * DM;
  float* o = xn + row * DM;
  int t = threadIdx.x; // 256
  float v0 = xr[t], v1 = xr[t + 256];
  __shared__ float red[8];
  float s = warp_sum(v0 + v1);
  if ((t & 31) == 0) red[t >> 5] = s;
  __syncthreads();
  float tot = 0;
  #pragma unroll
  for (int i = 0; i < 8; i++) tot += red[i];
  float mu = tot * (1.0f / 512.0f);
  __syncthreads();
  float d0 = v0 - mu, d1 = v1 - mu;
  float sq = warp_sum(d0 * d0 + d1 * d1);
  if ((t & 31) == 0) red[t >> 5] = sq;
  __syncthreads();
  float vtot = 0;
  #pragma unroll
  for (int i = 0; i < 8; i++) vtot += red[i];
  float inv = rsqrtf(vtot * (1.0f / 512.0f) + 1e-5f);
  o[t]       = d0 * inv * lw[t]       + lb[t];
  o[t + 256] = d1 * inv * lw[t + 256] + lb[t + 256];
}

// ---------------- Tiled SGEMM 128x128x8, 256 threads, 8x8 per thread -------
// TA=0: C[m,n] = sum_k A[m*K+k] * B[k*N+n]   (A row-major MxK)
// TA=1: C[m,n] = sum_k A[k*M+m] * B[k*N+n]   (A row-major KxM)
// BIASN: += bias[n]; BIASM: += bias[m]
template<int TA, int BIASN, int BIASM>
__global__ void sgemm128(const float* __restrict__ A, const float* __restrict__ B,
                         const float* __restrict__ biasp, float* __restrict__ C,
                         int M, int N, int K, int ldc,
                         long long strideA, long long strideB, long long strideC) {
  __shared__ float As[8][128];
  __shared__ float Bs[8][128];
  A += blockIdx.z * strideA;
  B += blockIdx.z * strideB;
  C += blockIdx.z * strideC;
  int m0 = blockIdx.y * 128, n0 = blockIdx.x * 128;
  int tid = threadIdx.x;
  int ty = tid >> 4, tx = tid & 15;
  float acc[8][8];
  #pragma unroll
  for (int i = 0; i < 8; i++)
    #pragma unroll
    for (int j = 0; j < 8; j++) acc[i][j] = 0.f;

  for (int k0 = 0; k0 < K; k0 += 8) {
    if (TA) {
      int kk = tid >> 5, mm = (tid & 31) * 4;
      *(float4*)&As[kk][mm] = *(const float4*)(A + (long long)(k0 + kk) * M + m0 + mm);
    } else {
      int mm = tid >> 1, kk = (tid & 1) * 4;
      float4 av = *(const float4*)(A + (long long)(m0 + mm) * K + k0 + kk);
      As[kk + 0][mm] = av.x; As[kk + 1][mm] = av.y;
      As[kk + 2][mm] = av.z; As[kk + 3][mm] = av.w;
    }
    {
      int kk = tid >> 5, nn = (tid & 31) * 4;
      *(float4*)&Bs[kk][nn] = *(const float4*)(B + (long long)(k0 + kk) * N + n0 + nn);
    }
    __syncthreads();
    #pragma unroll
    for (int kk = 0; kk < 8; kk++) {
      float a[8], bb[8];
      *(float4*)(a)      = *(float4*)&As[kk][ty * 8];
      *(float4*)(a + 4)  = *(float4*)&As[kk][ty * 8 + 4];
      *(float4*)(bb)     = *(float4*)&Bs[kk][tx * 8];
      *(float4*)(bb + 4) = *(float4*)&Bs[kk][tx * 8 + 4];
      #pragma unroll
      for (int i = 0; i < 8; i++)
        #pragma unroll
        for (int j = 0; j < 8; j++) acc[i][j] += a[i] * bb[j];
    }
    __syncthreads();
  }
  #pragma unroll
  for (int i = 0; i < 8; i++) {
    int m = m0 + ty * 8 + i;
    float bm = BIASM ? biasp[m] : 0.f;
    #pragma unroll
    for (int j = 0; j < 8; j++) {
      int n = n0 + tx * 8 + j;
      float v = acc[i][j] + bm;
      if (BIASN) v += biasp[n];
      C[(long long)m * ldc + n] = v;
    }
  }
}

// ---------------- fold off1_w @ off2_w into 3x128 filter ----------------
__global__ void weff_kernel(const float* __restrict__ off1_w,
                            const float* __restrict__ off1_b,
                            const float* __restrict__ off2_w,
                            float* __restrict__ Weff, float* __restrict__ beff) {
  int i = threadIdx.x; // 128
  for (int w = 0; w < 3; w++) {
    float s = 0.f;
    for (int o = 0; o < CG; o++) s += off1_w[(w * CG + i) * CG + o] * off2_w[o];
    Weff[w * CG + i] = s;
  }
  if (i == 0) {
    float s = 0.f;
    for (int o = 0; o < CG; o++) s += off1_b[o] * off2_w[o];
    *beff = s;
  }
}

// ---------------- m = 0.5*(xn[:,511]+xn[:,512]) ----------------
__global__ void m_kernel(const float* __restrict__ xn, float* __restrict__ m) {
  int b = blockIdx.x, d = threadIdx.x;
  m[b * DM + d] = 0.5f * (xn[((long long)b * SEQ + 511) * DM + d] +
                          xn[((long long)b * SEQ + 512) * DM + d]);
}

// ---------------- Kg/Vg: group slice of m times wk/wv ----------------
__global__ void kgvg_kernel(const float* __restrict__ m,
                            const float* __restrict__ wk, const float* __restrict__ wv,
                            float* __restrict__ Kg, float* __restrict__ Vg) {
  int bg = blockIdx.x; int b = bg >> 2, g = bg & 3;
  int e = threadIdx.x; // 512
  __shared__ float ms[CG];
  if (threadIdx.x < CG) ms[threadIdx.x] = m[b * DM + g * CG + threadIdx.x];
  __syncthreads();
  float sk = 0.f, sv = 0.f;
  for (int c = 0; c < CG; c++) {
    float mv = ms[c];
    sk += mv * wk[(g * CG + c) * DM + e];
    sv += mv * wv[(g * CG + c) * DM + e];
  }
  Kg[bg * DM + e] = sk;
  Vg[bg * DM + e] = sv;
}

// ---------------- w1[bg,l] = 1 - |(l+off)/1023 - 0.5| ----------------
__global__ void w1_kernel(const float* __restrict__ q,
                          const float* __restrict__ Weff, const float* __restrict__ beff,
                          float* __restrict__ w1) {
  __shared__ float qs[66][129];
  __shared__ float We[3 * CG];
  int bg = blockIdx.x, chunk = blockIdx.y;
  int b = bg >> 2, g = bg & 3;
  int l0 = chunk * 64;
  int tid = threadIdx.x; // 64
  for (int idx = tid; idx < 3 * CG; idx += 64) We[idx] = Weff[idx];
  for (int idx = tid; idx < 66 * CG; idx += 64) {
    int r = idx >> 7, c = idx & 127;
    int l = l0 - 1 + r;
    qs[r][c] = (l >= 0 && l < SEQ) ? q[((long long)b * SEQ + l) * DM + g * CG + c] : 0.f;
  }
  __syncthreads();
  int l = l0 + tid;
  float acc = *beff;
  #pragma unroll
  for (int w = 0; w < 3; w++) {
    #pragma unroll 4
    for (int i = 0; i < CG; i++) acc += qs[tid + w][i] * We[w * CG + i];
  }
  float off = tanhf(acc) * 3.0f;
  float ixv = ((float)l + off) * (1.0f / 1023.0f) - 0.5f;
  w1[bg * SEQ + l] = 1.0f - fabsf(ixv);
}

// ---------------- Qw[b,g,e]=sum_l q*w1, Qs[b,e]=sum_l q ----------------
__global__ void qw_kernel(const float* __restrict__ q, const float* __restrict__ w1,
                          float* __restrict__ Qw, float* __restrict__ Qs) {
  int b = blockIdx.x, ec = blockIdx.y;
  int e = ec * 128 + threadIdx.x;
  int s = threadIdx.y; // 4 strips of 256 l's
  __shared__ float w1s[NG][SEQ];
  __shared__ float red[4][5][128];
  int t = threadIdx.y * 128 + threadIdx.x;
  for (int idx = t; idx < NG * SEQ; idx += 512) w1s[idx >> 10][idx & 1023] = w1[b * NG * SEQ + idx];
  __syncthreads();
  float a0 = 0, a1 = 0, a2 = 0, a3 = 0, as_ = 0;
  int lbeg = s * 256;
  for (int l = lbeg; l < lbeg + 256; l++) {
    float qv = q[((long long)b * SEQ + l) * DM + e];
    a0 += qv * w1s[0][l]; a1 += qv * w1s[1][l];
    a2 += qv * w1s[2][l]; a3 += qv * w1s[3][l];
    as_ += qv;
  }
  red[s][0][threadIdx.x] = a0; red[s][1][threadIdx.x] = a1;
  red[s][2][threadIdx.x] = a2; red[s][3][threadIdx.x] = a3;
  red[s][4][threadIdx.x] = as_;
  __syncthreads();
  if (s == 0) {
    #pragma unroll
    for (int g = 0; g < 4; g++) {
      float v = red[0][g][threadIdx.x] + red[1][g][threadIdx.x] +
                red[2][g][threadIdx.x] + red[3][g][threadIdx.x];
      Qw[(b * NG + g) * DM + e] = v;
    }
    float vq = red[0][4][threadIdx.x] + red[1][4][threadIdx.x] +
               red[2][4][threadIdx.x] + red[3][4][threadIdx.x];
    Qs[b * DM + e] = vq;
  }
}

// ---------------- channel attention (per b,h): sc->softmax->Ag/Ab --------
__global__ void attn_kernel(const float* __restrict__ Qw, const float* __restrict__ Qs,
                            const float* __restrict__ Kg, const float* __restrict__ Vg,
                            const float* __restrict__ bk, const float* __restrict__ bv,
                            float* __restrict__ Ag, float* __restrict__ Ab) {
  int b = blockIdx.x, h = blockIdx.y;
  int i = threadIdx.x; // 64
  __shared__ float Kgs[NG][CH], Vgs[NG][CH], bks[CH], bvs[CH];
  __shared__ float aa[CH][CH + 1];
  #pragma unroll
  for (int g = 0; g < NG; g++) {
    Kgs[g][i] = Kg[(b * NG + g) * DM + h * CH + i];
    Vgs[g][i] = Vg[(b * NG + g) * DM + h * CH + i];
  }
  bks[i] = bk[h * CH + i];
  bvs[i] = bv[h * CH + i];
  __syncthreads();
  float qw0 = Qw[(b * NG + 0) * DM + h * CH + i];
  float qw1 = Qw[(b * NG + 1) * DM + h * CH + i];
  float qw2 = Qw[(b * NG + 2) * DM + h * CH + i];
  float qw3 = Qw[(b * NG + 3) * DM + h * CH + i];
  float qsv = Qs[b * DM + h * CH + i];
  const float scale = 0.044194173824159216f; // 512^-0.5
  float mx = -1e30f;
  for (int j = 0; j < CH; j++) {
    float s = (qw0 * Kgs[0][j] + qw1 * Kgs[1][j] + qw2 * Kgs[2][j] + qw3 * Kgs[3][j]
               + qsv * bks[j]) * scale;
    aa[i][j] = s;
    mx = fmaxf(mx, s);
  }
  float sm = 0.f;
  for (int j = 0; j < CH; j++) { float e = expf(aa[i][j] - mx); aa[i][j] = e; sm += e; }
  float inv = 1.0f / sm;
  float ag0 = 0, ag1 = 0, ag2 = 0, ag3 = 0, ab = 0;
  for (int j = 0; j < CH; j++) {
    float w = aa[i][j] * inv;
    ag0 += w * Vgs[0][j]; ag1 += w * Vgs[1][j];
    ag2 += w * Vgs[2][j]; ag3 += w * Vgs[3][j];
    ab  += w * bvs[j];
  }
  Ag[(b * NG + 0) * DM + h * CH + i] = ag0;
  Ag[(b * NG + 1) * DM + h * CH + i] = ag1;
  Ag[(b * NG + 2) * DM + h * CH + i] = ag2;
  Ag[(b * NG + 3) * DM + h * CH + i] = ag3;
  Ab[b * DM + h * CH + i] = ab;
}

// ---------------- small row GEMM: C[r,e] = sum_d A[r,d]*Bm[d,e] ----------
// A == nullptr -> treat A row as all-ones (column sums of Bm)
__global__ void rowgemm(const float* __restrict__ A, const float* __restrict__ Bm,
                        float* __restrict__ C, int K, int N) {
  int r = blockIdx.x;
  int e = blockIdx.y * 128 + threadIdx.x;
  __shared__ float Ar[1024];
  for (int idx = threadIdx.x; idx < K; idx += 128)
    Ar[idx] = A ? A[(long long)r * K + idx] : 1.0f;
  __syncthreads();
  float s = 0.f;
  for (int d = 0; d < K; d++) s += Ar[d] * Bm[(long long)d * N + e];
  C[(long long)r * N + e] = s;
}

// ---------------- expand rank-4 1D branch into conc[:, :512] -------------
__global__ void expand_u(const float* __restrict__ w1, const float* __restrict__ AgWo,
                         const float* __restrict__ AbWo, const float* __restrict__ wocs,
                         const float* __restrict__ bias1d, const float* __restrict__ bo,
                         float* __restrict__ conc) {
  int row = blockIdx.x;
  int b = row >> 10, l = row & 1023;
  int e = threadIdx.x; // 512
  float w0 = w1[(b * NG + 0) * SEQ + l];
  float w1v = w1[(b * NG + 1) * SEQ + l];
  float w2 = w1[(b * NG + 2) * SEQ + l];
  float w3 = w1[(b * NG + 3) * SEQ + l];
  float bl = bias1d[l];
  float v = w0 * AgWo[(b * NG + 0) * DM + e] + w1v * AgWo[(b * NG + 1) * DM + e]
          + w2 * AgWo[(b * NG + 2) * DM + e] + w3 * AgWo[(b * NG + 3) * DM + e]
          + AbWo[b * DM + e] + bl * wocs[e] + bo[e];
  conc[(long long)row * (2 * DM) + e] = v;
}

// ---------------- per-patch 2D deformable attention -> y -----------------
struct PatchSmem {
  float P[PL][DM + 1];   // padded 513
  float XS[PL][DM + 1];
  float sc[PL][PL + 1];
  float attnb[PL];
};

__global__ void patch_kernel(const float* __restrict__ xn, float* __restrict__ y,
                             const float* __restrict__ offc1w, const float* __restrict__ offc1b,
                             const float* __restrict__ offc2w,
                             const float* __restrict__ wq2, const float* __restrict__ bq2,
                             const float* __restrict__ wk2, const float* __restrict__ bk2,
                             const float* __restrict__ wv2, const float* __restrict__ bv2,
                             const float* __restrict__ wo2, const float* __restrict__ bo2,
                             const float* __restrict__ bias2d) {
  extern __shared__ char smraw[];
  PatchSmem& S = *(PatchSmem*)smraw;
  int pb = blockIdx.x;
  int b = pb / NP, p = pb % NP;
  int tid = threadIdx.x; // 256
  const float* src = xn + ((long long)b * SEQ + p * 8) * DM;
  for (int idx = tid; idx < PL * DM; idx += 256) {
    int i = idx >> 9, j = idx & 511;
    S.P[i][j] = src[i * DM + j];
  }
  __syncthreads();

  float WQ2 = *wq2, BQ2 = *bq2;
  float cw[9];
  #pragma unroll
  for (int t = 0; t < 9; t++) cw[t] = offc1w[t];
  float c1b = *offc1b;
  float ow0 = offc2w[0], ow1 = offc2w[1];

  for (int idx = tid; idx < PL * DM; idx += 256) {
    int i = idx >> 9, j = idx & 511;
    float h2 = c1b;
    #pragma unroll
    for (int di = -1; di <= 1; di++) {
      int ii = i + di;
      if (ii < 0 || ii > PL - 1) continue;
      #pragma unroll
      for (int dj = -1; dj <= 1; dj++) {
        int jj = j + dj;
        if (jj < 0 || jj > DM - 1) continue;
        h2 += (WQ2 * S.P[ii][jj] + BQ2) * cw[(di + 1) * 3 + (dj + 1)];
      }
    }
    float ox = tanhf(h2 * ow0) * 3.0f;
    float oy = tanhf(h2 * ow1) * 3.0f;
    float ix = ((float)j + ox) * (512.0f / 511.0f) - 0.5f;
    float iy = ((float)i + oy) * (16.0f / 15.0f) - 0.5f;
    float x0f = floorf(ix), y0f = floorf(iy);
    int x0 = (int)x0f, y0 = (int)y0f;
    float wx = ix - x0f, wy = iy - y0f;
    float acc = 0.f;
    if (x0 >= 0 && x0 < DM && y0 >= 0 && y0 < PL)             acc += S.P[y0][x0]         * (1 - wx) * (1 - wy);
    if (x0 + 1 >= 0 && x0 + 1 < DM && y0 >= 0 && y0 < PL)     acc += S.P[y0][x0 + 1]     * wx * (1 - wy);
    if (x0 >= 0 && x0 < DM && y0 + 1 >= 0 && y0 + 1 < PL)     acc += S.P[y0 + 1][x0]     * (1 - wx) * wy;
    if (x0 + 1 >= 0 && x0 + 1 < DM && y0 + 1 >= 0 && y0 + 1 < PL) acc += S.P[y0 + 1][x0 + 1] * wx * wy;
    S.XS[i][j] = acc;
  }
  __syncthreads();

  // sc[i][jj] = sum_w q2[i,w]*k2[jj,w]
  {
    float WK2 = *wk2, BK2 = *bk2;
    int i = tid >> 4, jj = tid & 15;
    float s = 0.f;
    for (int w = 0; w < DM; w++)
      s += (WQ2 * S.P[i][w] + BQ2) * (WK2 * S.XS[jj][w] + BK2);
    S.sc[i][jj] = s;
  }
  __syncthreads();
  if (tid < PL) {
    int i = tid;
    float mx = -1e30f;
    for (int jj = 0; jj < PL; jj++) mx = fmaxf(mx, S.sc[i][jj]);
    float sm = 0.f;
    for (int jj = 0; jj < PL; jj++) { float e = expf(S.sc[i][jj] - mx); S.sc[i][jj] = e; sm += e; }
    float inv = 1.0f / sm;
    float ab = 0.f;
    for (int jj = 0; jj < PL; jj++) { S.sc[i][jj] *= inv; ab += S.sc[i][jj] * bias2d[jj]; }
    S.attnb[i] = ab;
  }
  __syncthreads();

  float WV2 = *wv2, BV2 = *bv2, WO2 = *wo2, BO2 = *bo2;
  float* yo = y + ((long long)b * P2 + p * PL) * DM;
  for (int idx = tid; idx < PL * DM; idx += 256) {
    int i = idx >> 9, w = idx & 511;
    float s = 0.f;
    #pragma unroll
    for (int jj = 0; jj < PL; jj++) s += S.sc[i][jj] * S.XS[jj][w];
    float o2 = WV2 * s + BV2 + S.attnb[i];
    yo[i * DM + w] = o2 * WO2 + BO2;
  }
}

// ---------------- host launcher ----------------
extern "C" void kernel_launch(void* const* d_in, const int* in_sizes, int n_in,
                              void* d_out, int out_size) {
  const float* x      = (const float*)d_in[0];
  const float* ln_w   = (const float*)d_in[1];
  const float* ln_b   = (const float*)d_in[2];
  const float* wq     = (const float*)d_in[3];
  const float* bq     = (const float*)d_in[4];
  const float* wk     = (const float*)d_in[5];
  const float* bk     = (const float*)d_in[6];
  const float* wv     = (const float*)d_in[7];
  const float* bv     = (const float*)d_in[8];
  const float* wo     = (const float*)d_in[9];
  const float* bo     = (const float*)d_in[10];
  const float* off1_w = (const float*)d_in[11];
  const float* off1_b = (const float*)d_in[12];
  const float* off2_w = (const float*)d_in[13];
  const float* bias1d = (const float*)d_in[14];
  const float* wq2    = (const float*)d_in[15];
  const float* bq2    = (const float*)d_in[16];
  const float* wk2    = (const float*)d_in[17];
  const float* bk2    = (const float*)d_in[18];
  const float* wv2    = (const float*)d_in[19];
  const float* bv2    = (const float*)d_in[20];
  const float* wo2    = (const float*)d_in[21];
  const float* bo2    = (const float*)d_in[22];
  const float* offc1w = (const float*)d_in[23];
  const float* offc1b = (const float*)d_in[24];
  const float* offc2w = (const float*)d_in[25];
  const float* bias2d = (const float*)d_in[26];
  const float* write_w= (const float*)d_in[27];
  const float* write_b= (const float*)d_in[28];
  const float* proj_w = (const float*)d_in[29];
  const float* proj_b = (const float*)d_in[30];
  float* out = (float*)d_out;

  float *xn, *q, *w1, *conc, *y, *Weff, *beff, *m, *Kg, *Vg, *Qw, *Qs, *Ag, *Ab, *AgWo, *AbWo, *wocs;
  cudaGetSymbolAddress((void**)&xn,   g_xn);
  cudaGetSymbolAddress((void**)&q,    g_q);
  cudaGetSymbolAddress((void**)&w1,   g_w1);
  cudaGetSymbolAddress((void**)&conc, g_conc);
  cudaGetSymbolAddress((void**)&y,    g_y);
  cudaGetSymbolAddress((void**)&Weff, g_Weff);
  cudaGetSymbolAddress((void**)&beff, g_beff);
  cudaGetSymbolAddress((void**)&m,    g_m);
  cudaGetSymbolAddress((void**)&Kg,   g_Kg);
  cudaGetSymbolAddress((void**)&Vg,   g_Vg);
  cudaGetSymbolAddress((void**)&Qw,   g_Qw);
  cudaGetSymbolAddress((void**)&Qs,   g_Qs);
  cudaGetSymbolAddress((void**)&Ag,   g_Ag);
  cudaGetSymbolAddress((void**)&Ab,   g_Ab);
  cudaGetSymbolAddress((void**)&AgWo, g_AgWo);
  cudaGetSymbolAddress((void**)&AbWo, g_AbWo);
  cudaGetSymbolAddress((void**)&wocs, g_wocs);

  // 1. LayerNorm
  ln_kernel<<<BSZ * SEQ, 256>>>(x, ln_w, ln_b, xn);

  // 2. q = xn @ wq + bq
  sgemm128<0,1,0><<<dim3(DM/128, BSZ*SEQ/128, 1), 256>>>(
      xn, wq, bq, q, BSZ*SEQ, DM, DM, DM, 0, 0, 0);

  // 3. fold offset network
  weff_kernel<<<1, 128>>>(off1_w, off1_b, off2_w, Weff, beff);
  m_kernel<<<BSZ, DM>>>(xn, m);
  kgvg_kernel<<<BSZ*NG, DM>>>(m, wk, wv, Kg, Vg);

  // 4. w1 weights from folded conv + tanh
  w1_kernel<<<dim3(BSZ*NG, SEQ/64), 64>>>(q, Weff, beff, w1);

  // 5. Qw/Qs reductions over L
  qw_kernel<<<dim3(BSZ, 4), dim3(128, 4)>>>(q, w1, Qw, Qs);

  // 6. channel attention -> Ag/Ab
  attn_kernel<<<dim3(BSZ, NH), CH>>>(Qw, Qs, Kg, Vg, bk, bv, Ag, Ab);

  // 7. fold through wo
  rowgemm<<<dim3(BSZ*NG, DM/128), 128>>>(Ag, wo, AgWo, DM, DM);
  rowgemm<<<dim3(BSZ,    DM/128), 128>>>(Ab, wo, AbWo, DM, DM);
  rowgemm<<<dim3(1,      DM/128), 128>>>((const float*)nullptr, wo, wocs, DM, DM);

  // 8. expand 1D branch into conc[:, :512]
  expand_u<<<BSZ*SEQ, DM>>>(w1, AgWo, AbWo, wocs, bias1d, bo, conc);

  // 9. 2D patch branch -> y
  int patch_smem = (int)sizeof(PatchSmem);
  cudaFuncSetAttribute((const void*)patch_kernel,
                       cudaFuncAttributeMaxDynamicSharedMemorySize, patch_smem);
  patch_kernel<<<BSZ*NP, 256, patch_smem>>>(xn, y, offc1w, offc1b, offc2w,
                                            wq2, bq2, wk2, bk2, wv2, bv2, wo2, bo2, bias2d);

  // 10. x2d[b,s,d] = sum_p write_w[p,s]*y[b,p,d] + write_b[s] -> conc[:, 512:]
  sgemm128<1,0,1><<<dim3(DM/128, SEQ/128, BSZ), 256>>>(
      write_w, y, write_b, conc + DM, SEQ, DM, P2, 2*DM,
      0, (long long)P2*DM, (long long)SEQ*2*DM);

  // 11. out = conc @ proj_w + proj_b
  sgemm128<0,1,0><<<dim3(DM/128, BSZ*SEQ/128, 1), 256>>>(
      conc, proj_w, proj_b, out, BSZ*SEQ, DM, 2*DM, DM, 0, 0, 0);
}

// round 2
// speedup vs baseline: 1.1127x; 1.1127x over previous
#include <cuda_runtime.h>
#include <math.h>

// ---------------- problem dims ----------------
constexpr int BSZ = 16;
constexpr int SEQ = 1024;
constexpr int DM  = 512;
constexpr int NG  = 4;
constexpr int CG  = 128;
constexpr int NH  = 8;
constexpr int CH  = 64;
constexpr int NP  = 127;
constexpr int PL  = 16;
constexpr int P2  = NP * PL; // 2032

// ---------------- scratch ----------------
__device__ float g_xn [(size_t)BSZ*SEQ*DM];
__device__ float g_y  [(size_t)BSZ*P2*DM];
__device__ float g_x2d[(size_t)BSZ*SEQ*DM];
__device__ float g_Z  [(size_t)BSZ*SEQ*12];
__device__ float g_w1 [BSZ*NG*SEQ];
__device__ float g_w1sum[BSZ*NG];
__device__ float g_W1X[BSZ*NG*DM];
__device__ float g_Xs [BSZ*DM];
__device__ float g_Qw [BSZ*NG*DM];
__device__ float g_Qs [BSZ*DM];
__device__ float g_Kg [BSZ*NG*DM];
__device__ float g_Vg [BSZ*NG*DM];
__device__ float g_Ag [BSZ*NG*DM];
__device__ float g_Ab [BSZ*DM];
__device__ float g_AgWo [BSZ*NG*DM];
__device__ float g_AbWo [BSZ*DM];
__device__ float g_wocs [DM];
__device__ float g_AgWoP[BSZ*NG*DM];
__device__ float g_AbWoP[BSZ*DM];
__device__ float g_wocsP[DM];
__device__ float g_cvec [DM];
__device__ float g_U   [DM*12];
__device__ float g_Weff[3*CG];
__device__ float g_beff[1];
__device__ float g_cB  [12];

__device__ __forceinline__ float warp_sum(float v) {
  #pragma unroll
  for (int o = 16; o; o >>= 1) v += __shfl_xor_sync(0xffffffffu, v, o);
  return v;
}

// ---------------- LayerNorm ----------------
__global__ void ln_kernel(const float* __restrict__ x,
                          const float* __restrict__ lw,
                          const float* __restrict__ lb,
                          float* __restrict__ xn) {
  long row = blockIdx.x;
  const float* xr = x + row * DM;
  float* o = xn + row * DM;
  int t = threadIdx.x; // 256
  float v0 = xr[t], v1 = xr[t + 256];
  __shared__ float red[8];
  float s = warp_sum(v0 + v1);
  if ((t & 31) == 0) red[t >> 5] = s;
  __syncthreads();
  float tot = 0;
  #pragma unroll
  for (int i = 0; i < 8; i++) tot += red[i];
  float mu = tot * (1.0f / 512.0f);
  __syncthreads();
  float d0 = v0 - mu, d1 = v1 - mu;
  float sq = warp_sum(d0 * d0 + d1 * d1);
  if ((t & 31) == 0) red[t >> 5] = sq;
  __syncthreads();
  float vtot = 0;
  #pragma unroll
  for (int i = 0; i < 8; i++) vtot += red[i];
  float inv = rsqrtf(vtot * (1.0f / 512.0f) + 1e-5f);
  o[t]       = d0 * inv * lw[t]       + lb[t];
  o[t + 256] = d1 * inv * lw[t + 256] + lb[t + 256];
}

// ---------------- fold offset net: Weff, beff, cB ----------------
__global__ void weff_kernel(const float* __restrict__ off1_w,
                            const float* __restrict__ off1_b,
                            const float* __restrict__ off2_w,
                            const float* __restrict__ bq,
                            float* __restrict__ Weff, float* __restrict__ beff,
                            float* __restrict__ cB) {
  int i = threadIdx.x; // 128
  for (int w = 0; w < 3; w++) {
    float s = 0.f;
    for (int o = 0; o < CG; o++) s += off1_w[(w * CG + i) * CG + o] * off2_w[o];
    Weff[w * CG + i] = s;
  }
  if (i == 0) {
    float s = 0.f;
    for (int o = 0; o < CG; o++) s += off1_b[o] * off2_w[o];
    *beff = s;
  }
  __syncthreads();
  if (i < 12) {
    int w = i >> 2, g = i & 3;
    float s = 0.f;
    for (int c = 0; c < CG; c++) s += bq[g * CG + c] * Weff[w * CG + c];
    cB[i] = s;
  }
}

// ---------------- U[d, w*4+g] = sum_i wq[d, g*128+i]*Weff[w,i] ----------------
__global__ void u_kernel(const float* __restrict__ wq, const float* __restrict__ Weff,
                         float* __restrict__ U) {
  int d = blockIdx.x;
  int t = threadIdx.x; // 128
  __shared__ float red[4];
  int warp = t >> 5, lane = t & 31;
  #pragma unroll
  for (int g = 0; g < 4; g++) {
    float wqv = wq[d * DM + g * CG + t];
    #pragma unroll
    for (int w = 0; w < 3; w++) {
      float p = wqv * Weff[w * CG + t];
      p = warp_sum(p);
      if (lane == 0) red[warp] = p;
      __syncthreads();
      if (t == 0) U[d * 12 + w * 4 + g] = red[0] + red[1] + red[2] + red[3];
      __syncthreads();
    }
  }
}

// ---------------- Z[row, j] = xn[row,:] @ U[:, j] ----------------
__global__ void z_kernel(const float* __restrict__ xn, const float* __restrict__ U,
                         float* __restrict__ Z) {
  long row = blockIdx.x;
  __shared__ float r[DM];
  int t = threadIdx.x; // 128
  *(float4*)&r[t * 4] = *(const float4*)(xn + row * DM + t * 4);
  __syncthreads();
  int warp = t >> 5, lane = t & 31;
  #pragma unroll
  for (int jj = 0; jj < 3; jj++) {
    int j = warp * 3 + jj;
    float s = 0.f;
    for (int i = lane; i < DM; i += 32) s += r[i] * U[i * 12 + j];
    s = warp_sum(s);
    if (lane == 0) Z[row * 12 + j] = s;
  }
}

// ---------------- w1 from Z (edge-aware bias) ----------------
__global__ void w1_kernel(const float* __restrict__ Z, const float* __restrict__ beff,
                          const float* __restrict__ cB, float* __restrict__ w1) {
  int bg = blockIdx.x;
  int b = bg >> 2, g = bg & 3;
  int l = blockIdx.y * 256 + threadIdx.x;
  float s = *beff;
  #pragma unroll
  for (int w = 0; w < 3; w++) {
    int lw = l + w - 1;
    if (lw >= 0 && lw < SEQ)
      s += Z[((long)b * SEQ + lw) * 12 + w * 4 + g] + cB[w * 4 + g];
  }
  float off = tanhf(s) * 3.0f;
  float ixv = ((float)l + off) * (1.0f / 1023.0f) - 0.5f;
  w1[bg * SEQ + l] = 1.0f - fabsf(ixv);
}

// ---------------- W1X, Xs, w1sum reductions over L ----------------
__global__ void w1x_kernel(const float* __restrict__ xn, const float* __restrict__ w1,
                           float* __restrict__ W1X, float* __restrict__ Xs,
                           float* __restrict__ w1sum) {
  int b = blockIdx.x, ec = blockIdx.y;
  int e = ec * 128 + threadIdx.x;
  int s = threadIdx.y; // 4 strips
  __shared__ float w1s[NG][SEQ];
  __shared__ float red[4][5][128];
  int t = threadIdx.y * 128 + threadIdx.x;
  for (int idx = t; idx < NG * SEQ; idx += 512) w1s[idx >> 10][idx & 1023] = w1[b * NG * SEQ + idx];
  __syncthreads();
  float a0 = 0, a1 = 0, a2 = 0, a3 = 0, as_ = 0;
  int lbeg = s * 256;
  for (int l = lbeg; l < lbeg + 256; l++) {
    float xv = xn[((long)b * SEQ + l) * DM + e];
    a0 += xv * w1s[0][l]; a1 += xv * w1s[1][l];
    a2 += xv * w1s[2][l]; a3 += xv * w1s[3][l];
    as_ += xv;
  }
  red[s][0][threadIdx.x] = a0; red[s][1][threadIdx.x] = a1;
  red[s][2][threadIdx.x] = a2; red[s][3][threadIdx.x] = a3;
  red[s][4][threadIdx.x] = as_;
  __syncthreads();
  if (s == 0) {
    #pragma unroll
    for (int g = 0; g < 4; g++) {
      float v = red[0][g][threadIdx.x] + red[1][g][threadIdx.x] +
                red[2][g][threadIdx.x] + red[3][g][threadIdx.x];
      W1X[(b * NG + g) * DM + e] = v;
    }
    float vq = red[0][4][threadIdx.x] + red[1][4][threadIdx.x] +
               red[2][4][threadIdx.x] + red[3][4][threadIdx.x];
    Xs[b * DM + e] = vq;
  }
  if (ec == 0 && s == 0 && threadIdx.x < 4) {
    float acc = 0.f;
    for (int l = 0; l < SEQ; l++) acc += w1s[threadIdx.x][l];
    w1sum[b * NG + threadIdx.x] = acc;
  }
}

// ---------------- Kg/Vg (m computed inline) ----------------
__global__ void kgvg_kernel(const float* __restrict__ xn,
                            const float* __restrict__ wk, const float* __restrict__ wv,
                            float* __restrict__ Kg, float* __restrict__ Vg) {
  int bg = blockIdx.x; int b = bg >> 2, g = bg & 3;
  int e = threadIdx.x; // 512
  __shared__ float ms[CG];
  if (threadIdx.x < CG)
    ms[threadIdx.x] = 0.5f * (xn[((long)b * SEQ + 511) * DM + g * CG + threadIdx.x] +
                              xn[((long)b * SEQ + 512) * DM + g * CG + threadIdx.x]);
  __syncthreads();
  float sk = 0.f, sv = 0.f;
  for (int c = 0; c < CG; c++) {
    float mv = ms[c];
    sk += mv * wk[(g * CG + c) * DM + e];
    sv += mv * wv[(g * CG + c) * DM + e];
  }
  Kg[bg * DM + e] = sk;
  Vg[bg * DM + e] = sv;
}

// ---------------- generalized small row GEMM ----------------
// C[r,e] = sum_d A[r,d]*B[d,e] + (scalev?scalev[r]:cscale)*biasv[e]
__global__ void rowgemm2(const float* __restrict__ A, const float* __restrict__ B,
                         float* __restrict__ C, int K, int N,
                         const float* __restrict__ scalev, float cscale,
                         const float* __restrict__ biasv) {
  int r = blockIdx.x;
  int e = blockIdx.y * 128 + threadIdx.x;
  __shared__ float Ar[1024];
  for (int idx = threadIdx.x; idx < K; idx += 128)
    Ar[idx] = A ? A[(long)r * K + idx] : 1.0f;
  __syncthreads();
  float s = 0.f;
  for (int d = 0; d < K; d++) s += Ar[d] * B[(long)d * N + e];
  if (biasv) {
    float sc = scalev ? scalev[r] : cscale;
    s += sc * biasv[e];
  }
  C[(long)r * N + e] = s;
}

// ---------------- channel attention ----------------
__global__ void attn_kernel(const float* __restrict__ Qw, const float* __restrict__ Qs,
                            const float* __restrict__ Kg, const float* __restrict__ Vg,
                            const float* __restrict__ bk, const float* __restrict__ bv,
                            float* __restrict__ Ag, float* __restrict__ Ab) {
  int b = blockIdx.x, h = blockIdx.y;
  int i = threadIdx.x; // 64
  __shared__ float Kgs[NG][CH], Vgs[NG][CH], bks[CH], bvs[CH];
  __shared__ float aa[CH][CH + 1];
  #pragma unroll
  for (int g = 0; g < NG; g++) {
    Kgs[g][i] = Kg[(b * NG + g) * DM + h * CH + i];
    Vgs[g][i] = Vg[(b * NG + g) * DM + h * CH + i];
  }
  bks[i] = bk[h * CH + i];
  bvs[i] = bv[h * CH + i];
  __syncthreads();
  float qw0 = Qw[(b * NG + 0) * DM + h * CH + i];
  float qw1 = Qw[(b * NG + 1) * DM + h * CH + i];
  float qw2 = Qw[(b * NG + 2) * DM + h * CH + i];
  float qw3 = Qw[(b * NG + 3) * DM + h * CH + i];
  float qsv = Qs[b * DM + h * CH + i];
  const float scale = 0.044194173824159216f;
  float mx = -1e30f;
  for (int j = 0; j < CH; j++) {
    float s = (qw0 * Kgs[0][j] + qw1 * Kgs[1][j] + qw2 * Kgs[2][j] + qw3 * Kgs[3][j]
               + qsv * bks[j]) * scale;
    aa[i][j] = s;
    mx = fmaxf(mx, s);
  }
  float sm = 0.f;
  for (int j = 0; j < CH; j++) { float e = expf(aa[i][j] - mx); aa[i][j] = e; sm += e; }
  float inv = 1.0f / sm;
  float ag0 = 0, ag1 = 0, ag2 = 0, ag3 = 0, ab = 0;
  for (int j = 0; j < CH; j++) {
    float w = aa[i][j] * inv;
    ag0 += w * Vgs[0][j]; ag1 += w * Vgs[1][j];
    ag2 += w * Vgs[2][j]; ag3 += w * Vgs[3][j];
    ab  += w * bvs[j];
  }
  Ag[(b * NG + 0) * DM + h * CH + i] = ag0;
  Ag[(b * NG + 1) * DM + h * CH + i] = ag1;
  Ag[(b * NG + 2) * DM + h * CH + i] = ag2;
  Ag[(b * NG + 3) * DM + h * CH + i] = ag3;
  Ab[b * DM + h * CH + i] = ab;
}

// ---------------- per-patch 2D deformable attention ----------------
struct PatchSmem {
  float P[PL][DM + 1];
  float XS[PL][DM + 1];
  float sc[PL][PL + 1];
  float attnb[PL];
};

__global__ void patch_kernel(const float* __restrict__ xn, float* __restrict__ y,
                             const float* __restrict__ offc1w, const float* __restrict__ offc1b,
                             const float* __restrict__ offc2w,
                             const float* __restrict__ wq2, const float* __restrict__ bq2,
                             const float* __restrict__ wk2, const float* __restrict__ bk2,
                             const float* __restrict__ wv2, const float* __restrict__ bv2,
                             const float* __restrict__ wo2, const float* __restrict__ bo2,
                             const float* __restrict__ bias2d) {
  extern __shared__ char smraw[];
  PatchSmem& S = *(PatchSmem*)smraw;
  int pb = blockIdx.x;
  int b = pb / NP, p = pb % NP;
  int tid = threadIdx.x; // 256
  const float* src = xn + ((long)b * SEQ + p * 8) * DM;
  for (int idx = tid; idx < PL * DM; idx += 256) {
    int i = idx >> 9, j = idx & 511;
    S.P[i][j] = src[i * DM + j];
  }
  __syncthreads();

  float WQ2 = *wq2, BQ2 = *bq2;
  float cw[9];
  #pragma unroll
  for (int t = 0; t < 9; t++) cw[t] = offc1w[t];
  float c1b = *offc1b;
  float ow0 = offc2w[0], ow1 = offc2w[1];

  for (int idx = tid; idx < PL * DM; idx += 256) {
    int i = idx >> 9, j = idx & 511;
    float h2 = c1b;
    #pragma unroll
    for (int di = -1; di <= 1; di++) {
      int ii = i + di;
      if (ii < 0 || ii > PL - 1) continue;
      #pragma unroll
      for (int dj = -1; dj <= 1; dj++) {
        int jj = j + dj;
        if (jj < 0 || jj > DM - 1) continue;
        h2 += (WQ2 * S.P[ii][jj] + BQ2) * cw[(di + 1) * 3 + (dj + 1)];
      }
    }
    float ox = tanhf(h2 * ow0) * 3.0f;
    float oy = tanhf(h2 * ow1) * 3.0f;
    float ix = ((float)j + ox) * (512.0f / 511.0f) - 0.5f;
    float iy = ((float)i + oy) * (16.0f / 15.0f) - 0.5f;
    float x0f = floorf(ix), y0f = floorf(iy);
    int x0 = (int)x0f, y0 = (int)y0f;
    float wx = ix - x0f, wy = iy - y0f;
    float acc = 0.f;
    if (x0 >= 0 && x0 < DM && y0 >= 0 && y0 < PL)                 acc += S.P[y0][x0]         * (1 - wx) * (1 - wy);
    if (x0 + 1 >= 0 && x0 + 1 < DM && y0 >= 0 && y0 < PL)         acc += S.P[y0][x0 + 1]     * wx * (1 - wy);
    if (x0 >= 0 && x0 < DM && y0 + 1 >= 0 && y0 + 1 < PL)         acc += S.P[y0 + 1][x0]     * (1 - wx) * wy;
    if (x0 + 1 >= 0 && x0 + 1 < DM && y0 + 1 >= 0 && y0 + 1 < PL) acc += S.P[y0 + 1][x0 + 1] * wx * wy;
    S.XS[i][j] = acc;
  }
  __syncthreads();

  {
    float WK2 = *wk2, BK2 = *bk2;
    int i = tid >> 4, jj = tid & 15;
    float s = 0.f;
    for (int w = 0; w < DM; w++)
      s += (WQ2 * S.P[i][w] + BQ2) * (WK2 * S.XS[jj][w] + BK2);
    S.sc[i][jj] = s;
  }
  __syncthreads();
  if (tid < PL) {
    int i = tid;
    float mx = -1e30f;
    for (int jj = 0; jj < PL; jj++) mx = fmaxf(mx, S.sc[i][jj]);
    float sm = 0.f;
    for (int jj = 0; jj < PL; jj++) { float e = expf(S.sc[i][jj] - mx); S.sc[i][jj] = e; sm += e; }
    float inv = 1.0f / sm;
    float ab = 0.f;
    for (int jj = 0; jj < PL; jj++) { S.sc[i][jj] *= inv; ab += S.sc[i][jj] * bias2d[jj]; }
    S.attnb[i] = ab;
  }
  __syncthreads();

  float WV2 = *wv2, BV2 = *bv2, WO2 = *wo2, BO2 = *bo2;
  float* yo = y + ((long)b * P2 + p * PL) * DM;
  for (int idx = tid; idx < PL * DM; idx += 256) {
    int i = idx >> 9, w = idx & 511;
    float s = 0.f;
    #pragma unroll
    for (int jj = 0; jj < PL; jj++) s += S.sc[i][jj] * S.XS[jj][w];
    float o2 = WV2 * s + BV2 + S.attnb[i];
    yo[i * DM + w] = o2 * WO2 + BO2;
  }
}

// ---------------- double-buffered SGEMM 128x128, K-tile 16 ----------------
// TA=0: C = A(MxK) @ B(KxN);  TA=1: C = A^T (A is KxM) @ B(KxN)
template<int TA, int BIASN, int BIASM>
__global__ __launch_bounds__(256, 2)
void sgemm_db(const float* __restrict__ A, const float* __restrict__ B,
              const float* __restrict__ biasp, float* __restrict__ C,
              int M, int N, int K, int ldc,
              long long strideA, long long strideB, long long strideC) {
  __shared__ float As[2][16][128];
  __shared__ float Bs[2][16][128];
  A += blockIdx.z * strideA;
  B += blockIdx.z * strideB;
  C += blockIdx.z * strideC;
  int m0 = blockIdx.y * 128, n0 = blockIdx.x * 128;
  int tid = threadIdx.x;
  int ty = tid >> 4, tx = tid & 15;

  float4 ra0, ra1, rb0, rb1;
  const int bkk = tid >> 4, bnn = (tid & 15) * 8;

  auto loadg = [&](int k0) {
    if (TA) {
      int akk = tid >> 4, amm = (tid & 15) * 8;
      ra0 = *(const float4*)(A + (long long)(k0 + akk) * M + m0 + amm);
      ra1 = *(const float4*)(A + (long long)(k0 + akk) * M + m0 + amm + 4);
    } else {
      int amm = tid >> 1, ak = (tid & 1) * 8;
      ra0 = *(const float4*)(A + (long long)(m0 + amm) * K + k0 + ak);
      ra1 = *(const float4*)(A + (long long)(m0 + amm) * K + k0 + ak + 4);
    }
    rb0 = *(const float4*)(B + (long long)(k0 + bkk) * N + n0 + bnn);
    rb1 = *(const float4*)(B + (long long)(k0 + bkk) * N + n0 + bnn + 4);
  };
  auto store_s = [&](int buf) {
    if (TA) {
      int akk = tid >> 4, amm = (tid & 15) * 8;
      *(float4*)&As[buf][akk][amm]     = ra0;
      *(float4*)&As[buf][akk][amm + 4] = ra1;
    } else {
      int amm = tid >> 1, ak = (tid & 1) * 8;
      As[buf][ak + 0][amm] = ra0.x; As[buf][ak + 1][amm] = ra0.y;
      As[buf][ak + 2][amm] = ra0.z; As[buf][ak + 3][amm] = ra0.w;
      As[buf][ak + 4][amm] = ra1.x; As[buf][ak + 5][amm] = ra1.y;
      As[buf][ak + 6][amm] = ra1.z; As[buf][ak + 7][amm] = ra1.w;
    }
    *(float4*)&Bs[buf][bkk][bnn]     = rb0;
    *(float4*)&Bs[buf][bkk][bnn + 4] = rb1;
  };

  float acc[8][8];
  #pragma unroll
  for (int i = 0; i < 8; i++)
    #pragma unroll
    for (int j = 0; j < 8; j++) acc[i][j] = 0.f;

  loadg(0);
  store_s(0);
  __syncthreads();
  int KT = K / 16;
  for (int kt = 0; kt < KT; kt++) {
    int buf = kt & 1;
    if (kt + 1 < KT) loadg((kt + 1) * 16);
    #pragma unroll
    for (int kk = 0; kk < 16; kk++) {
      float a[8], bb[8];
      *(float4*)(a)      = *(float4*)&As[buf][kk][ty * 8];
      *(float4*)(a + 4)  = *(float4*)&As[buf][kk][ty * 8 + 4];
      *(float4*)(bb)     = *(float4*)&Bs[buf][kk][tx * 8];
      *(float4*)(bb + 4) = *(float4*)&Bs[buf][kk][tx * 8 + 4];
      #pragma unroll
      for (int i = 0; i < 8; i++)
        #pragma unroll
        for (int j = 0; j < 8; j++) acc[i][j] += a[i] * bb[j];
    }
    if (kt + 1 < KT) store_s(buf ^ 1);
    __syncthreads();
  }
  #pragma unroll
  for (int i = 0; i < 8; i++) {
    int m = m0 + ty * 8 + i;
    float bm = BIASM ? biasp[m] : 0.f;
    #pragma unroll
    for (int j = 0; j < 8; j++) {
      int n = n0 + tx * 8 + j;
      float v = acc[i][j] + bm;
      if (BIASN) v += biasp[n];
      C[(long long)m * ldc + n] = v;
    }
  }
}

// ---------------- final GEMM: out = x2d @ P_bot + rank-6 x1d epilogue ------
__global__ __launch_bounds__(256, 2)
void sgemm_final(const float* __restrict__ A, const float* __restrict__ B,
                 float* __restrict__ C,
                 const float* __restrict__ w1, const float* __restrict__ AgWoP,
                 const float* __restrict__ AbWoP, const float* __restrict__ wocsP,
                 const float* __restrict__ cvec, const float* __restrict__ bias1d) {
  const int K = 512, N = 512;
  __shared__ float As[2][16][128];
  __shared__ float Bs[2][16][128];
  __shared__ float E[6][128];
  int m0 = blockIdx.y * 128, n0 = blockIdx.x * 128;
  int b = m0 >> 10;
  int tid = threadIdx.x;
  int ty = tid >> 4, tx = tid & 15;

  if (tid < 128) {
    int n = n0 + tid;
    E[0][tid] = AbWoP[b * 512 + n] + cvec[n];
    E[1][tid] = wocsP[n];
    E[2][tid] = AgWoP[(b * 4 + 0) * 512 + n];
    E[3][tid] = AgWoP[(b * 4 + 1) * 512 + n];
    E[4][tid] = AgWoP[(b * 4 + 2) * 512 + n];
    E[5][tid] = AgWoP[(b * 4 + 3) * 512 + n];
  }

  float4 ra0, ra1, rb0, rb1;
  const int bkk = tid >> 4, bnn = (tid & 15) * 8;
  const int amm = tid >> 1, ak = (tid & 1) * 8;
  auto loadg = [&](int k0) {
    ra0 = *(const float4*)(A + (long long)(m0 + amm) * K + k0 + ak);
    ra1 = *(const float4*)(A + (long long)(m0 + amm) * K + k0 + ak + 4);
    rb0 = *(const float4*)(B + (long long)(k0 + bkk) * N + n0 + bnn);
    rb1 = *(const float4*)(B + (long long)(k0 + bkk) * N + n0 + bnn + 4);
  };
  auto store_s = [&](int buf) {
    As[buf][ak + 0][amm] = ra0.x; As[buf][ak + 1][amm] = ra0.y;
    As[buf][ak + 2][amm] = ra0.z; As[buf][ak + 3][amm] = ra0.w;
    As[buf][ak + 4][amm] = ra1.x; As[buf][ak + 5][amm] = ra1.y;
    As[buf][ak + 6][amm] = ra1.z; As[buf][ak + 7][amm] = ra1.w;
    *(float4*)&Bs[buf][bkk][bnn]     = rb0;
    *(float4*)&Bs[buf][bkk][bnn + 4] = rb1;
  };

  float acc[8][8];
  #pragma unroll
  for (int i = 0; i < 8; i++)
    #pragma unroll
    for (int j = 0; j < 8; j++) acc[i][j] = 0.f;

  loadg(0);
  store_s(0);
  __syncthreads();
  const int KT = K / 16;
  for (int kt = 0; kt < KT; kt++) {
    int buf = kt & 1;
    if (kt + 1 < KT) loadg((kt + 1) * 16);
    #pragma unroll
    for (int kk = 0; kk < 16; kk++) {
      float a[8], bb[8];
      *(float4*)(a)      = *(float4*)&As[buf][kk][ty * 8];
      *(float4*)(a + 4)  = *(float4*)&As[buf][kk][ty * 8 + 4];
      *(float4*)(bb)     = *(float4*)&Bs[buf][kk][tx * 8];
      *(float4*)(bb + 4) = *(float4*)&Bs[buf][kk][tx * 8 + 4];
      #pragma unroll
      for (int i = 0; i < 8; i++)
        #pragma unroll
        for (int j = 0; j < 8; j++) acc[i][j] += a[i] * bb[j];
    }
    if (kt + 1 < KT) store_s(buf ^ 1);
    __syncthreads();
  }

  #pragma unroll
  for (int i = 0; i < 8; i++) {
    int m = m0 + ty * 8 + i;
    int l = m & 1023;
    float w10 = w1[(b * 4 + 0) * 1024 + l];
    float w11 = w1[(b * 4 + 1) * 1024 + l];
    float w12 = w1[(b * 4 + 2) * 1024 + l];
    float w13 = w1[(b * 4 + 3) * 1024 + l];
    float blv = bias1d[l];
    #pragma unroll
    for (int j = 0; j < 8; j++) {
      int nn = tx * 8 + j;
      float v = acc[i][j] + E[0][nn] + blv * E[1][nn]
              + w10 * E[2][nn] + w11 * E[3][nn] + w12 * E[4][nn] + w13 * E[5][nn];
      C[(long long)m * 512 + n0 + nn] = v;
    }
  }
}

// ---------------- host launcher ----------------
extern "C" void kernel_launch(void* const* d_in, const int* in_sizes, int n_in,
                              void* d_out, int out_size) {
  const float* x      = (const float*)d_in[0];
  const float* ln_w   = (const float*)d_in[1];
  const float* ln_b   = (const float*)d_in[2];
  const float* wq     = (const float*)d_in[3];
  const float* bq     = (const float*)d_in[4];
  const float* wk     = (const float*)d_in[5];
  const float* bk     = (const float*)d_in[6];
  const float* wv     = (const float*)d_in[7];
  const float* bv     = (const float*)d_in[8];
  const float* wo     = (const float*)d_in[9];
  const float* bo     = (const float*)d_in[10];
  const float* off1_w = (const float*)d_in[11];
  const float* off1_b = (const float*)d_in[12];
  const float* off2_w = (const float*)d_in[13];
  const float* bias1d = (const float*)d_in[14];
  const float* wq2    = (const float*)d_in[15];
  const float* bq2    = (const float*)d_in[16];
  const float* wk2    = (const float*)d_in[17];
  const float* bk2    = (const float*)d_in[18];
  const float* wv2    = (const float*)d_in[19];
  const float* bv2    = (const float*)d_in[20];
  const float* wo2    = (const float*)d_in[21];
  const float* bo2    = (const float*)d_in[22];
  const float* offc1w = (const float*)d_in[23];
  const float* offc1b = (const float*)d_in[24];
  const float* offc2w = (const float*)d_in[25];
  const float* bias2d = (const float*)d_in[26];
  const float* write_w= (const float*)d_in[27];
  const float* write_b= (const float*)d_in[28];
  const float* proj_w = (const float*)d_in[29];
  const float* proj_b = (const float*)d_in[30];
  float* out = (float*)d_out;

  float *xn, *y, *x2d, *Z, *w1, *w1sum, *W1X, *Xs, *Qw, *Qs, *Kg, *Vg, *Ag, *Ab;
  float *AgWo, *AbWo, *wocs, *AgWoP, *AbWoP, *wocsP, *cvec, *U, *Weff, *beff, *cB;
  cudaGetSymbolAddress((void**)&xn,    g_xn);
  cudaGetSymbolAddress((void**)&y,     g_y);
  cudaGetSymbolAddress((void**)&x2d,   g_x2d);
  cudaGetSymbolAddress((void**)&Z,     g_Z);
  cudaGetSymbolAddress((void**)&w1,    g_w1);
  cudaGetSymbolAddress((void**)&w1sum, g_w1sum);
  cudaGetSymbolAddress((void**)&W1X,   g_W1X);
  cudaGetSymbolAddress((void**)&Xs,    g_Xs);
  cudaGetSymbolAddress((void**)&Qw,    g_Qw);
  cudaGetSymbolAddress((void**)&Qs,    g_Qs);
  cudaGetSymbolAddress((void**)&Kg,    g_Kg);
  cudaGetSymbolAddress((void**)&Vg,    g_Vg);
  cudaGetSymbolAddress((void**)&Ag,    g_Ag);
  cudaGetSymbolAddress((void**)&Ab,    g_Ab);
  cudaGetSymbolAddress((void**)&AgWo,  g_AgWo);
  cudaGetSymbolAddress((void**)&AbWo,  g_AbWo);
  cudaGetSymbolAddress((void**)&wocs,  g_wocs);
  cudaGetSymbolAddress((void**)&AgWoP, g_AgWoP);
  cudaGetSymbolAddress((void**)&AbWoP, g_AbWoP);
  cudaGetSymbolAddress((void**)&wocsP, g_wocsP);
  cudaGetSymbolAddress((void**)&cvec,  g_cvec);
  cudaGetSymbolAddress((void**)&U,     g_U);
  cudaGetSymbolAddress((void**)&Weff,  g_Weff);
  cudaGetSymbolAddress((void**)&beff,  g_beff);
  cudaGetSymbolAddress((void**)&cB,    g_cB);

  // LayerNorm
  ln_kernel<<<BSZ * SEQ, 256>>>(x, ln_w, ln_b, xn);

  // offset-net folding (tiny)
  weff_kernel<<<1, 128>>>(off1_w, off1_b, off2_w, bq, Weff, beff, cB);
  u_kernel<<<DM, 128>>>(wq, Weff, U);

  // Z = xn @ U, then w1
  z_kernel<<<BSZ * SEQ, 128>>>(xn, U, Z);
  w1_kernel<<<dim3(BSZ * NG, SEQ / 256), 256>>>(Z, beff, cB, w1);

  // reductions over L
  w1x_kernel<<<dim3(BSZ, 4), dim3(128, 4)>>>(xn, w1, W1X, Xs, w1sum);

  // Kg/Vg
  kgvg_kernel<<<BSZ * NG, DM>>>(xn, wk, wv, Kg, Vg);

  // Qw = W1X@wq + w1sum*bq ; Qs = Xs@wq + 1024*bq
  rowgemm2<<<dim3(BSZ * NG, DM / 128), 128>>>(W1X, wq, Qw, DM, DM, w1sum, 0.f, bq);
  rowgemm2<<<dim3(BSZ,      DM / 128), 128>>>(Xs,  wq, Qs, DM, DM, nullptr, 1024.f, bq);

  // channel attention
  attn_kernel<<<dim3(BSZ, NH), CH>>>(Qw, Qs, Kg, Vg, bk, bv, Ag, Ab);

  // fold through wo then P_top (= proj_w rows [0,512))
  rowgemm2<<<dim3(BSZ * NG, DM / 128), 128>>>(Ag, wo, AgWo, DM, DM, nullptr, 0.f, nullptr);
  rowgemm2<<<dim3(BSZ,      DM / 128), 128>>>(Ab, wo, AbWo, DM, DM, nullptr, 0.f, nullptr);
  rowgemm2<<<dim3(1,        DM / 128), 128>>>((const float*)nullptr, wo, wocs, DM, DM, nullptr, 0.f, nullptr);
  rowgemm2<<<dim3(BSZ * NG, DM / 128), 128>>>(AgWo, proj_w, AgWoP, DM, DM, nullptr, 0.f, nullptr);
  rowgemm2<<<dim3(BSZ,      DM / 128), 128>>>(AbWo, proj_w, AbWoP, DM, DM, nullptr, 0.f, nullptr);
  rowgemm2<<<dim3(1,        DM / 128), 128>>>(wocs, proj_w, wocsP, DM, DM, nullptr, 0.f, nullptr);
  rowgemm2<<<dim3(1,        DM / 128), 128>>>(bo,   proj_w, cvec,  DM, DM, nullptr, 1.f, proj_b);

  // 2D patch branch -> y
  int patch_smem = (int)sizeof(PatchSmem);
  cudaFuncSetAttribute((const void*)patch_kernel,
                       cudaFuncAttributeMaxDynamicSharedMemorySize, patch_smem);
  patch_kernel<<<BSZ * NP, 256, patch_smem>>>(xn, y, offc1w, offc1b, offc2w,
                                              wq2, bq2, wk2, bk2, wv2, bv2, wo2, bo2, bias2d);

  // x2d = write_w^T @ y + write_b  (per batch)
  sgemm_db<1, 0, 1><<<dim3(DM / 128, SEQ / 128, BSZ), 256>>>(
      write_w, y, write_b, x2d, SEQ, DM, P2, DM,
      0, (long long)P2 * DM, (long long)SEQ * DM);

  // out = x2d @ P_bot + x1d-epilogue
  sgemm_final<<<dim3(DM / 128, BSZ * SEQ / 128), 256>>>(
      x2d, proj_w + (long long)DM * DM, out,
      w1, AgWoP, AbWoP, wocsP, cvec, bias1d);
}

// round 3
// speedup vs baseline: 1.3325x; 1.1976x over previous
#include <cuda_runtime.h>
#include <math.h>
#include <stdint.h>

// ---------------- problem dims ----------------
constexpr int BSZ = 16;
constexpr int SEQ = 1024;
constexpr int DM  = 512;
constexpr int NG  = 4;
constexpr int CG  = 128;
constexpr int NH  = 8;
constexpr int CH  = 64;
constexpr int NP  = 127;
constexpr int PL  = 16;
constexpr int P2  = NP * PL; // 2032

// ---------------- scratch ----------------
__device__ float g_xn [(size_t)BSZ*SEQ*DM];
__device__ float g_y  [(size_t)BSZ*P2*DM];
__device__ float g_x2d[(size_t)BSZ*SEQ*DM];
__device__ float g_Z  [(size_t)BSZ*SEQ*12];
__device__ float g_w1 [BSZ*NG*SEQ];
__device__ float g_w1sum[BSZ*NG];
__device__ float g_W1X[BSZ*NG*DM];
__device__ float g_Xs [BSZ*DM];
__device__ float g_Qw [BSZ*NG*DM];
__device__ float g_Qs [BSZ*DM];
__device__ float g_Kg [BSZ*NG*DM];
__device__ float g_Vg [BSZ*NG*DM];
__device__ float g_Ag [BSZ*NG*DM];
__device__ float g_Ab [BSZ*DM];
__device__ float g_AgWo [BSZ*NG*DM];
__device__ float g_AbWo [BSZ*DM];
__device__ float g_wocs [DM];
__device__ float g_AgWoP[BSZ*NG*DM];
__device__ float g_AbWoP[BSZ*DM];
__device__ float g_wocsP[DM];
__device__ float g_cvec [DM];
__device__ float g_U   [DM*12];
__device__ float g_Weff[3*CG];
__device__ float g_beff[1];
__device__ float g_cB  [12];

__device__ __forceinline__ float warp_sum(float v) {
  #pragma unroll
  for (int o = 16; o; o >>= 1) v += __shfl_xor_sync(0xffffffffu, v, o);
  return v;
}

// ---------------- tf32 helpers ----------------
__device__ __forceinline__ uint32_t f2tf32(float v) {
  uint32_t r;
  asm("cvt.rna.tf32.f32 %0, %1;" : "=r"(r) : "f"(v));
  return r;
}
__device__ __forceinline__ void split1(float v, float& h, float& l) {
  uint32_t hu = f2tf32(v);
  float hf = __uint_as_float(hu);
  h = hf;
  l = __uint_as_float(f2tf32(v - hf));
}
__device__ __forceinline__ void split4(float4 v, float4& h, float4& l) {
  split1(v.x, h.x, l.x); split1(v.y, h.y, l.y);
  split1(v.z, h.z, l.z); split1(v.w, h.w, l.w);
}
__device__ __forceinline__ void mma_tf32(float* c,
    uint32_t a0, uint32_t a1, uint32_t a2, uint32_t a3,
    uint32_t b0, uint32_t b1) {
  asm volatile(
    "mma.sync.aligned.m16n8k8.row.col.f32.tf32.tf32.f32 "
    "{%0,%1,%2,%3}, {%4,%5,%6,%7}, {%8,%9}, {%0,%1,%2,%3};"
    : "+f"(c[0]), "+f"(c[1]), "+f"(c[2]), "+f"(c[3])
    : "r"(a0), "r"(a1), "r"(a2), "r"(a3), "r"(b0), "r"(b1));
}

// ---------------- LayerNorm ----------------
__global__ void ln_kernel(const float* __restrict__ x,
                          const float* __restrict__ lw,
                          const float* __restrict__ lb,
                          float* __restrict__ xn) {
  long row = blockIdx.x;
  const float* xr = x + row * DM;
  float* o = xn + row * DM;
  int t = threadIdx.x; // 256
  float v0 = xr[t], v1 = xr[t + 256];
  __shared__ float red[8];
  float s = warp_sum(v0 + v1);
  if ((t & 31) == 0) red[t >> 5] = s;
  __syncthreads();
  float tot = 0;
  #pragma unroll
  for (int i = 0; i < 8; i++) tot += red[i];
  float mu = tot * (1.0f / 512.0f);
  __syncthreads();
  float d0 = v0 - mu, d1 = v1 - mu;
  float sq = warp_sum(d0 * d0 + d1 * d1);
  if ((t & 31) == 0) red[t >> 5] = sq;
  __syncthreads();
  float vtot = 0;
  #pragma unroll
  for (int i = 0; i < 8; i++) vtot += red[i];
  float inv = rsqrtf(vtot * (1.0f / 512.0f) + 1e-5f);
  o[t]       = d0 * inv * lw[t]       + lb[t];
  o[t + 256] = d1 * inv * lw[t + 256] + lb[t + 256];
}

// ---------------- fold offset net: Weff, beff, cB ----------------
__global__ void weff_kernel(const float* __restrict__ off1_w,
                            const float* __restrict__ off1_b,
                            const float* __restrict__ off2_w,
                            const float* __restrict__ bq,
                            float* __restrict__ Weff, float* __restrict__ beff,
                            float* __restrict__ cB) {
  int i = threadIdx.x; // 128
  for (int w = 0; w < 3; w++) {
    float s = 0.f;
    for (int o = 0; o < CG; o++) s += off1_w[(w * CG + i) * CG + o] * off2_w[o];
    Weff[w * CG + i] = s;
  }
  if (i == 0) {
    float s = 0.f;
    for (int o = 0; o < CG; o++) s += off1_b[o] * off2_w[o];
    *beff = s;
  }
  __syncthreads();
  if (i < 12) {
    int w = i >> 2, g = i & 3;
    float s = 0.f;
    for (int c = 0; c < CG; c++) s += bq[g * CG + c] * Weff[w * CG + c];
    cB[i] = s;
  }
}

// ---------------- U[d, w*4+g] = sum_i wq[d, g*128+i]*Weff[w,i] ----------------
__global__ void u_kernel(const float* __restrict__ wq, const float* __restrict__ Weff,
                         float* __restrict__ U) {
  int d = blockIdx.x;
  int t = threadIdx.x; // 128
  __shared__ float red[4];
  int warp = t >> 5, lane = t & 31;
  #pragma unroll
  for (int g = 0; g < 4; g++) {
    float wqv = wq[d * DM + g * CG + t];
    #pragma unroll
    for (int w = 0; w < 3; w++) {
      float p = wqv * Weff[w * CG + t];
      p = warp_sum(p);
      if (lane == 0) red[warp] = p;
      __syncthreads();
      if (t == 0) U[d * 12 + w * 4 + g] = red[0] + red[1] + red[2] + red[3];
      __syncthreads();
    }
  }
}

// ---------------- Z = xn @ U : one block per 64 rows ----------------
__global__ void z_kernel(const float* __restrict__ xn, const float* __restrict__ U,
                         float* __restrict__ Z) {
  __shared__ float Us[DM * 13];
  int tid = threadIdx.x; // 256
  for (int idx = tid; idx < DM * 12; idx += 256) {
    int d = idx / 12, j = idx - d * 12;
    Us[d * 13 + j] = U[idx];
  }
  __syncthreads();
  int warp = tid >> 5, lane = tid & 31;
  long row0 = (long)blockIdx.x * 64 + warp * 8;
  for (int r = 0; r < 8; r++) {
    long row = row0 + r;
    const float* xr = xn + row * DM;
    float acc[12];
    #pragma unroll
    for (int j = 0; j < 12; j++) acc[j] = 0.f;
    for (int i = lane; i < DM; i += 32) {
      float xv = xr[i];
      #pragma unroll
      for (int j = 0; j < 12; j++) acc[j] += xv * Us[i * 13 + j];
    }
    #pragma unroll
    for (int j = 0; j < 12; j++) acc[j] = warp_sum(acc[j]);
    if (lane == 0) {
      #pragma unroll
      for (int j = 0; j < 12; j++) Z[row * 12 + j] = acc[j];
    }
  }
}

// ---------------- w1 from Z ----------------
__global__ void w1_kernel(const float* __restrict__ Z, const float* __restrict__ beff,
                          const float* __restrict__ cB, float* __restrict__ w1) {
  int bg = blockIdx.x;
  int b = bg >> 2, g = bg & 3;
  int l = blockIdx.y * 256 + threadIdx.x;
  float s = *beff;
  #pragma unroll
  for (int w = 0; w < 3; w++) {
    int lw = l + w - 1;
    if (lw >= 0 && lw < SEQ)
      s += Z[((long)b * SEQ + lw) * 12 + w * 4 + g] + cB[w * 4 + g];
  }
  float off = tanhf(s) * 3.0f;
  float ixv = ((float)l + off) * (1.0f / 1023.0f) - 0.5f;
  w1[bg * SEQ + l] = 1.0f - fabsf(ixv);
}

// ---------------- W1X, Xs, w1sum reductions over L ----------------
__global__ void w1x_kernel(const float* __restrict__ xn, const float* __restrict__ w1,
                           float* __restrict__ W1X, float* __restrict__ Xs,
                           float* __restrict__ w1sum) {
  int b = blockIdx.x, ec = blockIdx.y;
  int e = ec * 128 + threadIdx.x;
  int s = threadIdx.y; // 4 strips
  __shared__ float w1s[NG][SEQ];
  __shared__ float red[4][5][128];
  int t = threadIdx.y * 128 + threadIdx.x;
  for (int idx = t; idx < NG * SEQ; idx += 512) w1s[idx >> 10][idx & 1023] = w1[b * NG * SEQ + idx];
  __syncthreads();
  float a0 = 0, a1 = 0, a2 = 0, a3 = 0, as_ = 0;
  int lbeg = s * 256;
  for (int l = lbeg; l < lbeg + 256; l++) {
    float xv = xn[((long)b * SEQ + l) * DM + e];
    a0 += xv * w1s[0][l]; a1 += xv * w1s[1][l];
    a2 += xv * w1s[2][l]; a3 += xv * w1s[3][l];
    as_ += xv;
  }
  red[s][0][threadIdx.x] = a0; red[s][1][threadIdx.x] = a1;
  red[s][2][threadIdx.x] = a2; red[s][3][threadIdx.x] = a3;
  red[s][4][threadIdx.x] = as_;
  __syncthreads();
  if (s == 0) {
    #pragma unroll
    for (int g = 0; g < 4; g++) {
      float v = red[0][g][threadIdx.x] + red[1][g][threadIdx.x] +
                red[2][g][threadIdx.x] + red[3][g][threadIdx.x];
      W1X[(b * NG + g) * DM + e] = v;
    }
    float vq = red[0][4][threadIdx.x] + red[1][4][threadIdx.x] +
               red[2][4][threadIdx.x] + red[3][4][threadIdx.x];
    Xs[b * DM + e] = vq;
  }
  if (ec == 0 && s == 0 && threadIdx.x < 4) {
    float acc = 0.f;
    for (int l = 0; l < SEQ; l++) acc += w1s[threadIdx.x][l];
    w1sum[b * NG + threadIdx.x] = acc;
  }
}

// ---------------- Kg/Vg ----------------
__global__ void kgvg_kernel(const float* __restrict__ xn,
                            const float* __restrict__ wk, const float* __restrict__ wv,
                            float* __restrict__ Kg, float* __restrict__ Vg) {
  int bg = blockIdx.x; int b = bg >> 2, g = bg & 3;
  int e = threadIdx.x; // 512
  __shared__ float ms[CG];
  if (threadIdx.x < CG)
    ms[threadIdx.x] = 0.5f * (xn[((long)b * SEQ + 511) * DM + g * CG + threadIdx.x] +
                              xn[((long)b * SEQ + 512) * DM + g * CG + threadIdx.x]);
  __syncthreads();
  float sk = 0.f, sv = 0.f;
  for (int c = 0; c < CG; c++) {
    float mv = ms[c];
    sk += mv * wk[(g * CG + c) * DM + e];
    sv += mv * wv[(g * CG + c) * DM + e];
  }
  Kg[bg * DM + e] = sk;
  Vg[bg * DM + e] = sv;
}

// ---------------- generalized small row GEMM ----------------
__global__ void rowgemm2(const float* __restrict__ A, const float* __restrict__ B,
                         float* __restrict__ C, int K, int N,
                         const float* __restrict__ scalev, float cscale,
                         const float* __restrict__ biasv) {
  int r = blockIdx.x;
  int e = blockIdx.y * 128 + threadIdx.x;
  __shared__ float Ar[1024];
  for (int idx = threadIdx.x; idx < K; idx += 128)
    Ar[idx] = A ? A[(long)r * K + idx] : 1.0f;
  __syncthreads();
  float s = 0.f;
  for (int d = 0; d < K; d++) s += Ar[d] * B[(long)d * N + e];
  if (biasv) {
    float sc = scalev ? scalev[r] : cscale;
    s += sc * biasv[e];
  }
  C[(long)r * N + e] = s;
}

// ---------------- channel attention ----------------
__global__ void attn_kernel(const float* __restrict__ Qw, const float* __restrict__ Qs,
                            const float* __restrict__ Kg, const float* __restrict__ Vg,
                            const float* __restrict__ bk, const float* __restrict__ bv,
                            float* __restrict__ Ag, float* __restrict__ Ab) {
  int b = blockIdx.x, h = blockIdx.y;
  int i = threadIdx.x; // 64
  __shared__ float Kgs[NG][CH], Vgs[NG][CH], bks[CH], bvs[CH];
  __shared__ float aa[CH][CH + 1];
  #pragma unroll
  for (int g = 0; g < NG; g++) {
    Kgs[g][i] = Kg[(b * NG + g) * DM + h * CH + i];
    Vgs[g][i] = Vg[(b * NG + g) * DM + h * CH + i];
  }
  bks[i] = bk[h * CH + i];
  bvs[i] = bv[h * CH + i];
  __syncthreads();
  float qw0 = Qw[(b * NG + 0) * DM + h * CH + i];
  float qw1 = Qw[(b * NG + 1) * DM + h * CH + i];
  float qw2 = Qw[(b * NG + 2) * DM + h * CH + i];
  float qw3 = Qw[(b * NG + 3) * DM + h * CH + i];
  float qsv = Qs[b * DM + h * CH + i];
  const float scale = 0.044194173824159216f;
  float mx = -1e30f;
  for (int j = 0; j < CH; j++) {
    float s = (qw0 * Kgs[0][j] + qw1 * Kgs[1][j] + qw2 * Kgs[2][j] + qw3 * Kgs[3][j]
               + qsv * bks[j]) * scale;
    aa[i][j] = s;
    mx = fmaxf(mx, s);
  }
  float sm = 0.f;
  for (int j = 0; j < CH; j++) { float e = expf(aa[i][j] - mx); aa[i][j] = e; sm += e; }
  float inv = 1.0f / sm;
  float ag0 = 0, ag1 = 0, ag2 = 0, ag3 = 0, ab = 0;
  for (int j = 0; j < CH; j++) {
    float w = aa[i][j] * inv;
    ag0 += w * Vgs[0][j]; ag1 += w * Vgs[1][j];
    ag2 += w * Vgs[2][j]; ag3 += w * Vgs[3][j];
    ab  += w * bvs[j];
  }
  Ag[(b * NG + 0) * DM + h * CH + i] = ag0;
  Ag[(b * NG + 1) * DM + h * CH + i] = ag1;
  Ag[(b * NG + 2) * DM + h * CH + i] = ag2;
  Ag[(b * NG + 3) * DM + h * CH + i] = ag3;
  Ab[b * DM + h * CH + i] = ab;
}

// ---------------- per-patch 2D deformable attention ----------------
struct PatchSmem {
  float P[PL][DM + 1];
  float XS[PL][DM + 1];
  float sc[PL][PL + 1];
  float attnb[PL];
};

__global__ void patch_kernel(const float* __restrict__ xn, float* __restrict__ y,
                             const float* __restrict__ offc1w, const float* __restrict__ offc1b,
                             const float* __restrict__ offc2w,
                             const float* __restrict__ wq2, const float* __restrict__ bq2,
                             const float* __restrict__ wk2, const float* __restrict__ bk2,
                             const float* __restrict__ wv2, const float* __restrict__ bv2,
                             const float* __restrict__ wo2, const float* __restrict__ bo2,
                             const float* __restrict__ bias2d) {
  extern __shared__ char smraw[];
  PatchSmem& S = *(PatchSmem*)smraw;
  int pb = blockIdx.x;
  int b = pb / NP, p = pb % NP;
  int tid = threadIdx.x; // 256
  const float* src = xn + ((long)b * SEQ + p * 8) * DM;
  for (int idx = tid; idx < PL * DM; idx += 256) {
    int i = idx >> 9, j = idx & 511;
    S.P[i][j] = src[i * DM + j];
  }
  __syncthreads();

  float WQ2 = *wq2, BQ2 = *bq2;
  float cw[9];
  #pragma unroll
  for (int t = 0; t < 9; t++) cw[t] = offc1w[t];
  float c1b = *offc1b;
  float ow0 = offc2w[0], ow1 = offc2w[1];

  for (int idx = tid; idx < PL * DM; idx += 256) {
    int i = idx >> 9, j = idx & 511;
    float h2 = c1b;
    #pragma unroll
    for (int di = -1; di <= 1; di++) {
      int ii = i + di;
      if (ii < 0 || ii > PL - 1) continue;
      #pragma unroll
      for (int dj = -1; dj <= 1; dj++) {
        int jj = j + dj;
        if (jj < 0 || jj > DM - 1) continue;
        h2 += (WQ2 * S.P[ii][jj] + BQ2) * cw[(di + 1) * 3 + (dj + 1)];
      }
    }
    float ox = tanhf(h2 * ow0) * 3.0f;
    float oy = tanhf(h2 * ow1) * 3.0f;
    float ix = ((float)j + ox) * (512.0f / 511.0f) - 0.5f;
    float iy = ((float)i + oy) * (16.0f / 15.0f) - 0.5f;
    float x0f = floorf(ix), y0f = floorf(iy);
    int x0 = (int)x0f, y0 = (int)y0f;
    float wx = ix - x0f, wy = iy - y0f;
    float acc = 0.f;
    if (x0 >= 0 && x0 < DM && y0 >= 0 && y0 < PL)                 acc += S.P[y0][x0]         * (1 - wx) * (1 - wy);
    if (x0 + 1 >= 0 && x0 + 1 < DM && y0 >= 0 && y0 < PL)         acc += S.P[y0][x0 + 1]     * wx * (1 - wy);
    if (x0 >= 0 && x0 < DM && y0 + 1 >= 0 && y0 + 1 < PL)         acc += S.P[y0 + 1][x0]     * (1 - wx) * wy;
    if (x0 + 1 >= 0 && x0 + 1 < DM && y0 + 1 >= 0 && y0 + 1 < PL) acc += S.P[y0 + 1][x0 + 1] * wx * wy;
    S.XS[i][j] = acc;
  }
  __syncthreads();

  {
    float WK2 = *wk2, BK2 = *bk2;
    int i = tid >> 4, jj = tid & 15;
    float s = 0.f;
    for (int w = 0; w < DM; w++)
      s += (WQ2 * S.P[i][w] + BQ2) * (WK2 * S.XS[jj][w] + BK2);
    S.sc[i][jj] = s;
  }
  __syncthreads();
  if (tid < PL) {
    int i = tid;
    float mx = -1e30f;
    for (int jj = 0; jj < PL; jj++) mx = fmaxf(mx, S.sc[i][jj]);
    float sm = 0.f;
    for (int jj = 0; jj < PL; jj++) { float e = expf(S.sc[i][jj] - mx); S.sc[i][jj] = e; sm += e; }
    float inv = 1.0f / sm;
    float ab = 0.f;
    for (int jj = 0; jj < PL; jj++) { S.sc[i][jj] *= inv; ab += S.sc[i][jj] * bias2d[jj]; }
    S.attnb[i] = ab;
  }
  __syncthreads();

  float WV2 = *wv2, BV2 = *bv2, WO2 = *wo2, BO2 = *bo2;
  float* yo = y + ((long)b * P2 + p * PL) * DM;
  for (int idx = tid; idx < PL * DM; idx += 256) {
    int i = idx >> 9, w = idx & 511;
    float s = 0.f;
    #pragma unroll
    for (int jj = 0; jj < PL; jj++) s += S.sc[i][jj] * S.XS[jj][w];
    float o2 = WV2 * s + BV2 + S.attnb[i];
    yo[i * DM + w] = o2 * WO2 + BO2;
  }
}

// ============================================================================
// Tensor-core GEMM: 3x tf32 mma.sync.m16n8k8, 128x128x16 tiles, 8 warps.
// TA=1: global A is [K][M] (direct K-major load);  TA=0: A is [M][K] (transpose on store).
// EPI=0: C[m,n] = acc + biasM[m]
// EPI=1: C[m,n] = acc + E0[n] + bias1d[l]*E1[n] + sum_g w1[g][l]*E(2+g)[n]
// ============================================================================
constexpr int MLD = 136;                 // smem leading dim (words), 136%32==8
constexpr int TSZ = 16 * MLD;            // one tile array: 2176 floats
constexpr int MMA_SMEM_FLOATS = 2 * 4 * TSZ + 11 * 128;   // buffers + epilogue
constexpr int MMA_SMEM_BYTES  = MMA_SMEM_FLOATS * 4;      // 75264

template<int TA, int EPI>
__global__ __launch_bounds__(256, 1)
void mma_gemm(const float* __restrict__ A, const float* __restrict__ B,
              const float* __restrict__ biasM, float* __restrict__ C,
              int M, int N, int K,
              long long strideA, long long strideB, long long strideC,
              const float* __restrict__ w1, const float* __restrict__ AgWoP,
              const float* __restrict__ AbWoP, const float* __restrict__ wocsP,
              const float* __restrict__ cvec, const float* __restrict__ bias1d) {
  extern __shared__ float sm[];
  A += blockIdx.z * strideA;
  B += blockIdx.z * strideB;
  C += blockIdx.z * strideC;
  const int m0 = blockIdx.y * 128, n0 = blockIdx.x * 128;
  const int tid = threadIdx.x;
  const int wid = tid >> 5, lane = tid & 31;
  const int wm = wid >> 2, wn = wid & 3;       // warp tile: 64 x 32
  const int grp = lane >> 2, tig = lane & 3;

  float* Ep = sm + 2 * 4 * TSZ;  // 6 x 128
  float* Rp = Ep + 6 * 128;      // 5 x 128

  if (EPI == 1 && tid < 128) {
    int bb = (int)(blockIdx.y >> 3);
    int n = n0 + tid;
    Ep[0 * 128 + tid] = AbWoP[bb * 512 + n] + cvec[n];
    Ep[1 * 128 + tid] = wocsP[n];
    Ep[2 * 128 + tid] = AgWoP[(bb * 4 + 0) * 512 + n];
    Ep[3 * 128 + tid] = AgWoP[(bb * 4 + 1) * 512 + n];
    Ep[4 * 128 + tid] = AgWoP[(bb * 4 + 2) * 512 + n];
    Ep[5 * 128 + tid] = AgWoP[(bb * 4 + 3) * 512 + n];
    int l = (m0 & 1023) + tid;
    Rp[0 * 128 + tid] = w1[(bb * 4 + 0) * 1024 + l];
    Rp[1 * 128 + tid] = w1[(bb * 4 + 1) * 1024 + l];
    Rp[2 * 128 + tid] = w1[(bb * 4 + 2) * 1024 + l];
    Rp[3 * 128 + tid] = w1[(bb * 4 + 3) * 1024 + l];
    Rp[4 * 128 + tid] = bias1d[l];
  }

  // global prefetch registers
  float4 ra0, ra1, rb0, rb1;
  const int bkk = tid >> 4, bnn = (tid & 15) * 8;   // B tile & TA=1 A tile indices
  const int amm2 = tid >> 1, akc = (tid & 1) * 8;   // TA=0 A tile indices

  auto loadg = [&](int k0) {
    if (TA) {
      ra0 = *(const float4*)(A + (long long)(k0 + bkk) * M + m0 + bnn);
      ra1 = *(const float4*)(A + (long long)(k0 + bkk) * M + m0 + bnn + 4);
    } else {
      ra0 = *(const float4*)(A + (long long)(m0 + amm2) * K + k0 + akc);
      ra1 = *(const float4*)(A + (long long)(m0 + amm2) * K + k0 + akc + 4);
    }
    rb0 = *(const float4*)(B + (long long)(k0 + bkk) * N + n0 + bnn);
    rb1 = *(const float4*)(B + (long long)(k0 + bkk) * N + n0 + bnn + 4);
  };

  auto store_s = [&](int buf) {
    float* AH = sm + buf * 4 * TSZ;
    float* AL = AH + TSZ;
    float* BH = AL + TSZ;
    float* BL = BH + TSZ;
    if (TA) {
      float4 h0, l0, h1, l1;
      split4(ra0, h0, l0); split4(ra1, h1, l1);
      *(float4*)&AH[bkk * MLD + bnn]     = h0;
      *(float4*)&AH[bkk * MLD + bnn + 4] = h1;
      *(float4*)&AL[bkk * MLD + bnn]     = l0;
      *(float4*)&AL[bkk * MLD + bnn + 4] = l1;
    } else {
      float av[8];
      *(float4*)(av)     = ra0;
      *(float4*)(av + 4) = ra1;
      #pragma unroll
      for (int i = 0; i < 8; i++) {
        float h, l;
        split1(av[i], h, l);
        AH[(akc + i) * MLD + amm2] = h;
        AL[(akc + i) * MLD + amm2] = l;
      }
    }
    {
      float4 h0, l0, h1, l1;
      split4(rb0, h0, l0); split4(rb1, h1, l1);
      *(float4*)&BH[bkk * MLD + bnn]     = h0;
      *(float4*)&BH[bkk * MLD + bnn + 4] = h1;
      *(float4*)&BL[bkk * MLD + bnn]     = l0;
      *(float4*)&BL[bkk * MLD + bnn + 4] = l1;
    }
  };

  float c[4][4][4];
  #pragma unroll
  for (int mi = 0; mi < 4; mi++)
    #pragma unroll
    for (int ni = 0; ni < 4; ni++)
      #pragma unroll
      for (int r = 0; r < 4; r++) c[mi][ni][r] = 0.f;

  loadg(0);
  store_s(0);
  __syncthreads();

  const int KT = K / 16;
  for (int kt = 0; kt < KT; kt++) {
    int buf = kt & 1;
    if (kt + 1 < KT) loadg((kt + 1) * 16);

    const float* AH = sm + buf * 4 * TSZ;
    const float* AL = AH + TSZ;
    const float* BH = AL + TSZ;
    const float* BL = BH + TSZ;

    #pragma unroll
    for (int k8 = 0; k8 < 16; k8 += 8) {
      // B fragments (shared across mi)
      uint32_t bH[4][2], bL[4][2];
      const int kr0 = (k8 + tig) * MLD;
      const int kr1 = (k8 + tig + 4) * MLD;
      #pragma unroll
      for (int ni = 0; ni < 4; ni++) {
        int n = wn * 32 + ni * 8 + grp;
        bH[ni][0] = __float_as_uint(BH[kr0 + n]);
        bH[ni][1] = __float_as_uint(BH[kr1 + n]);
        bL[ni][0] = __float_as_uint(BL[kr0 + n]);
        bL[ni][1] = __float_as_uint(BL[kr1 + n]);
      }
      #pragma unroll
      for (int mi = 0; mi < 4; mi++) {
        int m = wm * 64 + mi * 16 + grp;
        uint32_t aH0 = __float_as_uint(AH[kr0 + m]);
        uint32_t aH1 = __float_as_uint(AH[kr0 + m + 8]);
        uint32_t aH2 = __float_as_uint(AH[kr1 + m]);
        uint32_t aH3 = __float_as_uint(AH[kr1 + m + 8]);
        uint32_t aL0 = __float_as_uint(AL[kr0 + m]);
        uint32_t aL1 = __float_as_uint(AL[kr0 + m + 8]);
        uint32_t aL2 = __float_as_uint(AL[kr1 + m]);
        uint32_t aL3 = __float_as_uint(AL[kr1 + m + 8]);
        #pragma unroll
        for (int ni = 0; ni < 4; ni++) {
          mma_tf32(c[mi][ni], aH0, aH1, aH2, aH3, bH[ni][0], bH[ni][1]);
          mma_tf32(c[mi][ni], aH0, aH1, aH2, aH3, bL[ni][0], bL[ni][1]);
          mma_tf32(c[mi][ni], aL0, aL1, aL2, aL3, bH[ni][0], bH[ni][1]);
        }
      }
    }
    if (kt + 1 < KT) store_s(buf ^ 1);
    __syncthreads();
  }

  // ---- epilogue + store ----
  #pragma unroll
  for (int mi = 0; mi < 4; mi++) {
    #pragma unroll
    for (int half = 0; half < 2; half++) {
      int ml = wm * 64 + mi * 16 + grp + 8 * half;
      int row = m0 + ml;
      float add_m = 0.f, blv = 0.f, w10 = 0.f, w11 = 0.f, w12 = 0.f, w13 = 0.f;
      if (EPI == 0) {
        add_m = biasM[row];
      } else {
        blv = Rp[4 * 128 + ml];
        w10 = Rp[0 * 128 + ml]; w11 = Rp[1 * 128 + ml];
        w12 = Rp[2 * 128 + ml]; w13 = Rp[3 * 128 + ml];
      }
      #pragma unroll
      for (int ni = 0; ni < 4; ni++) {
        int nn = wn * 32 + ni * 8 + 2 * tig;
        float v0 = c[mi][ni][2 * half + 0];
        float v1 = c[mi][ni][2 * half + 1];
        if (EPI == 0) {
          v0 += add_m; v1 += add_m;
        } else {
          v0 += Ep[nn] + blv * Ep[128 + nn]
              + w10 * Ep[2 * 128 + nn] + w11 * Ep[3 * 128 + nn]
              + w12 * Ep[4 * 128 + nn] + w13 * Ep[5 * 128 + nn];
          v1 += Ep[nn + 1] + blv * Ep[128 + nn + 1]
              + w10 * Ep[2 * 128 + nn + 1] + w11 * Ep[3 * 128 + nn + 1]
              + w12 * Ep[4 * 128 + nn + 1] + w13 * Ep[5 * 128 + nn + 1];
        }
        *(float2*)&C[(long long)row * N + n0 + nn] = make_float2(v0, v1);
      }
    }
  }
}

// ---------------- host launcher ----------------
extern "C" void kernel_launch(void* const* d_in, const int* in_sizes, int n_in,
                              void* d_out, int out_size) {
  const float* x      = (const float*)d_in[0];
  const float* ln_w   = (const float*)d_in[1];
  const float* ln_b   = (const float*)d_in[2];
  const float* wq     = (const float*)d_in[3];
  const float* bq     = (const float*)d_in[4];
  const float* wk     = (const float*)d_in[5];
  const float* bk     = (const float*)d_in[6];
  const float* wv     = (const float*)d_in[7];
  const float* bv     = (const float*)d_in[8];
  const float* wo     = (const float*)d_in[9];
  const float* bo     = (const float*)d_in[10];
  const float* off1_w = (const float*)d_in[11];
  const float* off1_b = (const float*)d_in[12];
  const float* off2_w = (const float*)d_in[13];
  const float* bias1d = (const float*)d_in[14];
  const float* wq2    = (const float*)d_in[15];
  const float* bq2    = (const float*)d_in[16];
  const float* wk2    = (const float*)d_in[17];
  const float* bk2    = (const float*)d_in[18];
  const float* wv2    = (const float*)d_in[19];
  const float* bv2    = (const float*)d_in[20];
  const float* wo2    = (const float*)d_in[21];
  const float* bo2    = (const float*)d_in[22];
  const float* offc1w = (const float*)d_in[23];
  const float* offc1b = (const float*)d_in[24];
  const float* offc2w = (const float*)d_in[25];
  const float* bias2d = (const float*)d_in[26];
  const float* write_w= (const float*)d_in[27];
  const float* write_b= (const float*)d_in[28];
  const float* proj_w = (const float*)d_in[29];
  const float* proj_b = (const float*)d_in[30];
  float* out = (float*)d_out;

  float *xn, *y, *x2d, *Z, *w1, *w1sum, *W1X, *Xs, *Qw, *Qs, *Kg, *Vg, *Ag, *Ab;
  float *AgWo, *AbWo, *wocs, *AgWoP, *AbWoP, *wocsP, *cvec, *U, *Weff, *beff, *cB;
  cudaGetSymbolAddress((void**)&xn,    g_xn);
  cudaGetSymbolAddress((void**)&y,     g_y);
  cudaGetSymbolAddress((void**)&x2d,   g_x2d);
  cudaGetSymbolAddress((void**)&Z,     g_Z);
  cudaGetSymbolAddress((void**)&w1,    g_w1);
  cudaGetSymbolAddress((void**)&w1sum, g_w1sum);
  cudaGetSymbolAddress((void**)&W1X,   g_W1X);
  cudaGetSymbolAddress((void**)&Xs,    g_Xs);
  cudaGetSymbolAddress((void**)&Qw,    g_Qw);
  cudaGetSymbolAddress((void**)&Qs,    g_Qs);
  cudaGetSymbolAddress((void**)&Kg,    g_Kg);
  cudaGetSymbolAddress((void**)&Vg,    g_Vg);
  cudaGetSymbolAddress((void**)&Ag,    g_Ag);
  cudaGetSymbolAddress((void**)&Ab,    g_Ab);
  cudaGetSymbolAddress((void**)&AgWo,  g_AgWo);
  cudaGetSymbolAddress((void**)&AbWo,  g_AbWo);
  cudaGetSymbolAddress((void**)&wocs,  g_wocs);
  cudaGetSymbolAddress((void**)&AgWoP, g_AgWoP);
  cudaGetSymbolAddress((void**)&AbWoP, g_AbWoP);
  cudaGetSymbolAddress((void**)&wocsP, g_wocsP);
  cudaGetSymbolAddress((void**)&cvec,  g_cvec);
  cudaGetSymbolAddress((void**)&U,     g_U);
  cudaGetSymbolAddress((void**)&Weff,  g_Weff);
  cudaGetSymbolAddress((void**)&beff,  g_beff);
  cudaGetSymbolAddress((void**)&cB,    g_cB);

  // LayerNorm
  ln_kernel<<<BSZ * SEQ, 256>>>(x, ln_w, ln_b, xn);

  // offset-net folding (tiny)
  weff_kernel<<<1, 128>>>(off1_w, off1_b, off2_w, bq, Weff, beff, cB);
  u_kernel<<<DM, 128>>>(wq, Weff, U);

  // Z = xn @ U, then w1
  z_kernel<<<BSZ * SEQ / 64, 256>>>(xn, U, Z);
  w1_kernel<<<dim3(BSZ * NG, SEQ / 256), 256>>>(Z, beff, cB, w1);

  // reductions over L
  w1x_kernel<<<dim3(BSZ, 4), dim3(128, 4)>>>(xn, w1, W1X, Xs, w1sum);

  // Kg/Vg
  kgvg_kernel<<<BSZ * NG, DM>>>(xn, wk, wv, Kg, Vg);

  // Qw = W1X@wq + w1sum*bq ; Qs = Xs@wq + 1024*bq
  rowgemm2<<<dim3(BSZ * NG, DM / 128), 128>>>(W1X, wq, Qw, DM, DM, w1sum, 0.f, bq);
  rowgemm2<<<dim3(BSZ,      DM / 128), 128>>>(Xs,  wq, Qs, DM, DM, nullptr, 1024.f, bq);

  // channel attention
  attn_kernel<<<dim3(BSZ, NH), CH>>>(Qw, Qs, Kg, Vg, bk, bv, Ag, Ab);

  // fold through wo then P_top
  rowgemm2<<<dim3(BSZ * NG, DM / 128), 128>>>(Ag, wo, AgWo, DM, DM, nullptr, 0.f, nullptr);
  rowgemm2<<<dim3(BSZ,      DM / 128), 128>>>(Ab, wo, AbWo, DM, DM, nullptr, 0.f, nullptr);
  rowgemm2<<<dim3(1,        DM / 128), 128>>>((const float*)nullptr, wo, wocs, DM, DM, nullptr, 0.f, nullptr);
  rowgemm2<<<dim3(BSZ * NG, DM / 128), 128>>>(AgWo, proj_w, AgWoP, DM, DM, nullptr, 0.f, nullptr);
  rowgemm2<<<dim3(BSZ,      DM / 128), 128>>>(AbWo, proj_w, AbWoP, DM, DM, nullptr, 0.f, nullptr);
  rowgemm2<<<dim3(1,        DM / 128), 128>>>(wocs, proj_w, wocsP, DM, DM, nullptr, 0.f, nullptr);
  rowgemm2<<<dim3(1,        DM / 128), 128>>>(bo,   proj_w, cvec,  DM, DM, nullptr, 1.f, proj_b);

  // 2D patch branch -> y
  int patch_smem = (int)sizeof(PatchSmem);
  cudaFuncSetAttribute((const void*)patch_kernel,
                       cudaFuncAttributeMaxDynamicSharedMemorySize, patch_smem);
  patch_kernel<<<BSZ * NP, 256, patch_smem>>>(xn, y, offc1w, offc1b, offc2w,
                                              wq2, bq2, wk2, bk2, wv2, bv2, wo2, bo2, bias2d);

  // x2d = write_w^T @ y + write_b (per batch) — tensor cores, 3x tf32
  cudaFuncSetAttribute((const void*)mma_gemm<1, 0>,
                       cudaFuncAttributeMaxDynamicSharedMemorySize, MMA_SMEM_BYTES);
  mma_gemm<1, 0><<<dim3(DM / 128, SEQ / 128, BSZ), 256, MMA_SMEM_BYTES>>>(
      write_w, y, write_b, x2d, SEQ, DM, P2,
      0, (long long)P2 * DM, (long long)SEQ * DM,
      nullptr, nullptr, nullptr, nullptr, nullptr, nullptr);

  // out = x2d @ P_bot + x1d-epilogue — tensor cores, 3x tf32
  cudaFuncSetAttribute((const void*)mma_gemm<0, 1>,
                       cudaFuncAttributeMaxDynamicSharedMemorySize, MMA_SMEM_BYTES);
  mma_gemm<0, 1><<<dim3(DM / 128, BSZ * SEQ / 128, 1), 256, MMA_SMEM_BYTES>>>(
      x2d, proj_w + (long long)DM * DM, nullptr, out, BSZ * SEQ, DM, DM,
      0, 0, 0,
      w1, AgWoP, AbWoP, wocsP, cvec, bias1d);
}

// round 4
// speedup vs baseline: 1.6487x; 1.2373x over previous
#include <cuda_runtime.h>
#include <cuda_bf16.h>
#include <math.h>
#include <stdint.h>

// ---------------- problem dims ----------------
constexpr int BSZ = 16;
constexpr int SEQ = 1024;
constexpr int DM  = 512;
constexpr int NG  = 4;
constexpr int CG  = 128;
constexpr int NH  = 8;
constexpr int CH  = 64;
constexpr int NP  = 127;
constexpr int PL  = 16;
constexpr int P2  = NP * PL; // 2032

// ---------------- scratch ----------------
__device__ float g_xn [(size_t)BSZ*SEQ*DM];
__device__ float g_y  [(size_t)BSZ*P2*DM];
__device__ float g_x2d[(size_t)BSZ*SEQ*DM];
__device__ float g_Z  [(size_t)BSZ*SEQ*12];
__device__ float g_w1 [BSZ*NG*SEQ];
__device__ float g_w1sum[BSZ*NG];
__device__ float g_W1X[BSZ*NG*DM];
__device__ float g_Xs [BSZ*DM];
__device__ float g_Qw [BSZ*NG*DM];
__device__ float g_Qs [BSZ*DM];
__device__ float g_Kg [BSZ*NG*DM];
__device__ float g_Vg [BSZ*NG*DM];
__device__ float g_Ag [BSZ*NG*DM];
__device__ float g_Ab [BSZ*DM];
__device__ float g_AgWo [BSZ*NG*DM];
__device__ float g_AbWo [BSZ*DM];
__device__ float g_wocs [DM];
__device__ float g_AgWoP[BSZ*NG*DM];
__device__ float g_AbWoP[BSZ*DM];
__device__ float g_wocsP[DM];
__device__ float g_cvec [DM];
__device__ float g_U   [DM*12];
__device__ float g_Weff[3*CG];
__device__ float g_beff[1];
__device__ float g_cB  [12];

__device__ __forceinline__ float warp_sum(float v) {
  #pragma unroll
  for (int o = 16; o; o >>= 1) v += __shfl_xor_sync(0xffffffffu, v, o);
  return v;
}

// ---------------- bf16 split helpers ----------------
__device__ __forceinline__ void split_bf16(float v, uint32_t& hb, uint32_t& lb) {
  __nv_bfloat16 h = __float2bfloat16(v);
  float hf = __bfloat162float(h);
  __nv_bfloat16 l = __float2bfloat16(v - hf);
  hb = (uint32_t)__bfloat16_as_ushort(h);
  lb = (uint32_t)__bfloat16_as_ushort(l);
}
__device__ __forceinline__ void mma_bf16(float* c,
    uint32_t a0, uint32_t a1, uint32_t a2, uint32_t a3,
    uint32_t b0, uint32_t b1) {
  asm volatile(
    "mma.sync.aligned.m16n8k16.row.col.f32.bf16.bf16.f32 "
    "{%0,%1,%2,%3}, {%4,%5,%6,%7}, {%8,%9}, {%0,%1,%2,%3};"
    : "+f"(c[0]), "+f"(c[1]), "+f"(c[2]), "+f"(c[3])
    : "r"(a0), "r"(a1), "r"(a2), "r"(a3), "r"(b0), "r"(b1));
}

// ---------------- LayerNorm ----------------
__global__ void ln_kernel(const float* __restrict__ x,
                          const float* __restrict__ lw,
                          const float* __restrict__ lb,
                          float* __restrict__ xn) {
  long row = blockIdx.x;
  const float* xr = x + row * DM;
  float* o = xn + row * DM;
  int t = threadIdx.x; // 256
  float v0 = xr[t], v1 = xr[t + 256];
  __shared__ float red[8];
  float s = warp_sum(v0 + v1);
  if ((t & 31) == 0) red[t >> 5] = s;
  __syncthreads();
  float tot = 0;
  #pragma unroll
  for (int i = 0; i < 8; i++) tot += red[i];
  float mu = tot * (1.0f / 512.0f);
  __syncthreads();
  float d0 = v0 - mu, d1 = v1 - mu;
  float sq = warp_sum(d0 * d0 + d1 * d1);
  if ((t & 31) == 0) red[t >> 5] = sq;
  __syncthreads();
  float vtot = 0;
  #pragma unroll
  for (int i = 0; i < 8; i++) vtot += red[i];
  float inv = rsqrtf(vtot * (1.0f / 512.0f) + 1e-5f);
  o[t]       = d0 * inv * lw[t]       + lb[t];
  o[t + 256] = d1 * inv * lw[t + 256] + lb[t + 256];
}

// ---------------- fold offset net: Weff, beff, cB ----------------
__global__ void weff_kernel(const float* __restrict__ off1_w,
                            const float* __restrict__ off1_b,
                            const float* __restrict__ off2_w,
                            const float* __restrict__ bq,
                            float* __restrict__ Weff, float* __restrict__ beff,
                            float* __restrict__ cB) {
  int i = threadIdx.x; // 128
  for (int w = 0; w < 3; w++) {
    float s = 0.f;
    for (int o = 0; o < CG; o++) s += off1_w[(w * CG + i) * CG + o] * off2_w[o];
    Weff[w * CG + i] = s;
  }
  if (i == 0) {
    float s = 0.f;
    for (int o = 0; o < CG; o++) s += off1_b[o] * off2_w[o];
    *beff = s;
  }
  __syncthreads();
  if (i < 12) {
    int w = i >> 2, g = i & 3;
    float s = 0.f;
    for (int c = 0; c < CG; c++) s += bq[g * CG + c] * Weff[w * CG + c];
    cB[i] = s;
  }
}

// ---------------- U[d, w*4+g] = sum_i wq[d, g*128+i]*Weff[w,i] ----------------
__global__ void u_kernel(const float* __restrict__ wq, const float* __restrict__ Weff,
                         float* __restrict__ U) {
  int d = blockIdx.x;
  int t = threadIdx.x; // 128
  __shared__ float red[4];
  int warp = t >> 5, lane = t & 31;
  #pragma unroll
  for (int g = 0; g < 4; g++) {
    float wqv = wq[d * DM + g * CG + t];
    #pragma unroll
    for (int w = 0; w < 3; w++) {
      float p = wqv * Weff[w * CG + t];
      p = warp_sum(p);
      if (lane == 0) red[warp] = p;
      __syncthreads();
      if (t == 0) U[d * 12 + w * 4 + g] = red[0] + red[1] + red[2] + red[3];
      __syncthreads();
    }
  }
}

// ---------------- Z = xn @ U : one warp per row, grid 2048 ----------------
__global__ void z_kernel(const float* __restrict__ xn, const float* __restrict__ U,
                         float* __restrict__ Z) {
  __shared__ float Us[DM * 13];
  int tid = threadIdx.x; // 256
  for (int idx = tid; idx < DM * 12; idx += 256) {
    int d = idx / 12, j = idx - d * 12;
    Us[d * 13 + j] = U[idx];
  }
  __syncthreads();
  int warp = tid >> 5, lane = tid & 31;
  long row = (long)blockIdx.x * 8 + warp;
  const float* xr = xn + row * DM;
  float acc[12];
  #pragma unroll
  for (int j = 0; j < 12; j++) acc[j] = 0.f;
  for (int i = lane; i < DM; i += 32) {
    float xv = xr[i];
    #pragma unroll
    for (int j = 0; j < 12; j++) acc[j] += xv * Us[i * 13 + j];
  }
  #pragma unroll
  for (int j = 0; j < 12; j++) acc[j] = warp_sum(acc[j]);
  if (lane == 0) {
    #pragma unroll
    for (int j = 0; j < 12; j++) Z[row * 12 + j] = acc[j];
  }
}

// ---------------- w1 from Z ----------------
__global__ void w1_kernel(const float* __restrict__ Z, const float* __restrict__ beff,
                          const float* __restrict__ cB, float* __restrict__ w1) {
  int bg = blockIdx.x;
  int b = bg >> 2, g = bg & 3;
  int l = blockIdx.y * 256 + threadIdx.x;
  float s = *beff;
  #pragma unroll
  for (int w = 0; w < 3; w++) {
    int lw = l + w - 1;
    if (lw >= 0 && lw < SEQ)
      s += Z[((long)b * SEQ + lw) * 12 + w * 4 + g] + cB[w * 4 + g];
  }
  float off = tanhf(s) * 3.0f;
  float ixv = ((float)l + off) * (1.0f / 1023.0f) - 0.5f;
  w1[bg * SEQ + l] = 1.0f - fabsf(ixv);
}

// ---------------- W1X, Xs, w1sum reductions over L ----------------
__global__ void w1x_kernel(const float* __restrict__ xn, const float* __restrict__ w1,
                           float* __restrict__ W1X, float* __restrict__ Xs,
                           float* __restrict__ w1sum) {
  int b = blockIdx.x, ec = blockIdx.y;
  int e = ec * 128 + threadIdx.x;
  int s = threadIdx.y; // 4 strips
  __shared__ float w1s[NG][SEQ];
  __shared__ float red[4][5][128];
  int t = threadIdx.y * 128 + threadIdx.x;
  for (int idx = t; idx < NG * SEQ; idx += 512) w1s[idx >> 10][idx & 1023] = w1[b * NG * SEQ + idx];
  __syncthreads();
  float a0 = 0, a1 = 0, a2 = 0, a3 = 0, as_ = 0;
  int lbeg = s * 256;
  for (int l = lbeg; l < lbeg + 256; l++) {
    float xv = xn[((long)b * SEQ + l) * DM + e];
    a0 += xv * w1s[0][l]; a1 += xv * w1s[1][l];
    a2 += xv * w1s[2][l]; a3 += xv * w1s[3][l];
    as_ += xv;
  }
  red[s][0][threadIdx.x] = a0; red[s][1][threadIdx.x] = a1;
  red[s][2][threadIdx.x] = a2; red[s][3][threadIdx.x] = a3;
  red[s][4][threadIdx.x] = as_;
  __syncthreads();
  if (s == 0) {
    #pragma unroll
    for (int g = 0; g < 4; g++) {
      float v = red[0][g][threadIdx.x] + red[1][g][threadIdx.x] +
                red[2][g][threadIdx.x] + red[3][g][threadIdx.x];
      W1X[(b * NG + g) * DM + e] = v;
    }
    float vq = red[0][4][threadIdx.x] + red[1][4][threadIdx.x] +
               red[2][4][threadIdx.x] + red[3][4][threadIdx.x];
    Xs[b * DM + e] = vq;
  }
  if (ec == 0 && s == 0 && threadIdx.x < 4) {
    float acc = 0.f;
    for (int l = 0; l < SEQ; l++) acc += w1s[threadIdx.x][l];
    w1sum[b * NG + threadIdx.x] = acc;
  }
}

// ---------------- Kg/Vg ----------------
__global__ void kgvg_kernel(const float* __restrict__ xn,
                            const float* __restrict__ wk, const float* __restrict__ wv,
                            float* __restrict__ Kg, float* __restrict__ Vg) {
  int bg = blockIdx.x; int b = bg >> 2, g = bg & 3;
  int e = threadIdx.x; // 512
  __shared__ float ms[CG];
  if (threadIdx.x < CG)
    ms[threadIdx.x] = 0.5f * (xn[((long)b * SEQ + 511) * DM + g * CG + threadIdx.x] +
                              xn[((long)b * SEQ + 512) * DM + g * CG + threadIdx.x]);
  __syncthreads();
  float sk = 0.f, sv = 0.f;
  for (int c = 0; c < CG; c++) {
    float mv = ms[c];
    sk += mv * wk[(g * CG + c) * DM + e];
    sv += mv * wv[(g * CG + c) * DM + e];
  }
  Kg[bg * DM + e] = sk;
  Vg[bg * DM + e] = sv;
}

// ---------------- generalized small row GEMM ----------------
__global__ void rowgemm2(const float* __restrict__ A, const float* __restrict__ B,
                         float* __restrict__ C, int K, int N,
                         const float* __restrict__ scalev, float cscale,
                         const float* __restrict__ biasv) {
  int r = blockIdx.x;
  int e = blockIdx.y * 128 + threadIdx.x;
  __shared__ float Ar[1024];
  for (int idx = threadIdx.x; idx < K; idx += 128)
    Ar[idx] = A ? A[(long)r * K + idx] : 1.0f;
  __syncthreads();
  float s = 0.f;
  for (int d = 0; d < K; d++) s += Ar[d] * B[(long)d * N + e];
  if (biasv) {
    float sc = scalev ? scalev[r] : cscale;
    s += sc * biasv[e];
  }
  C[(long)r * N + e] = s;
}

// ---------------- channel attention ----------------
__global__ void attn_kernel(const float* __restrict__ Qw, const float* __restrict__ Qs,
                            const float* __restrict__ Kg, const float* __restrict__ Vg,
                            const float* __restrict__ bk, const float* __restrict__ bv,
                            float* __restrict__ Ag, float* __restrict__ Ab) {
  int b = blockIdx.x, h = blockIdx.y;
  int i = threadIdx.x; // 64
  __shared__ float Kgs[NG][CH], Vgs[NG][CH], bks[CH], bvs[CH];
  __shared__ float aa[CH][CH + 1];
  #pragma unroll
  for (int g = 0; g < NG; g++) {
    Kgs[g][i] = Kg[(b * NG + g) * DM + h * CH + i];
    Vgs[g][i] = Vg[(b * NG + g) * DM + h * CH + i];
  }
  bks[i] = bk[h * CH + i];
  bvs[i] = bv[h * CH + i];
  __syncthreads();
  float qw0 = Qw[(b * NG + 0) * DM + h * CH + i];
  float qw1 = Qw[(b * NG + 1) * DM + h * CH + i];
  float qw2 = Qw[(b * NG + 2) * DM + h * CH + i];
  float qw3 = Qw[(b * NG + 3) * DM + h * CH + i];
  float qsv = Qs[b * DM + h * CH + i];
  const float scale = 0.044194173824159216f;
  float mx = -1e30f;
  for (int j = 0; j < CH; j++) {
    float s = (qw0 * Kgs[0][j] + qw1 * Kgs[1][j] + qw2 * Kgs[2][j] + qw3 * Kgs[3][j]
               + qsv * bks[j]) * scale;
    aa[i][j] = s;
    mx = fmaxf(mx, s);
  }
  float sm = 0.f;
  for (int j = 0; j < CH; j++) { float e = expf(aa[i][j] - mx); aa[i][j] = e; sm += e; }
  float inv = 1.0f / sm;
  float ag0 = 0, ag1 = 0, ag2 = 0, ag3 = 0, ab = 0;
  for (int j = 0; j < CH; j++) {
    float w = aa[i][j] * inv;
    ag0 += w * Vgs[0][j]; ag1 += w * Vgs[1][j];
    ag2 += w * Vgs[2][j]; ag3 += w * Vgs[3][j];
    ab  += w * bvs[j];
  }
  Ag[(b * NG + 0) * DM + h * CH + i] = ag0;
  Ag[(b * NG + 1) * DM + h * CH + i] = ag1;
  Ag[(b * NG + 2) * DM + h * CH + i] = ag2;
  Ag[(b * NG + 3) * DM + h * CH + i] = ag3;
  Ab[b * DM + h * CH + i] = ab;
}

// ---------------- per-patch 2D deformable attention ----------------
struct PatchSmem {
  float P[PL][DM + 1];
  float XS[PL][DM + 1];
  float sc[PL][PL + 1];
  float attnb[PL];
  float rsP[PL];
  float rsX[PL];
  float red[2][PL][PL];
};

__global__ void patch_kernel(const float* __restrict__ xn, float* __restrict__ y,
                             const float* __restrict__ offc1w, const float* __restrict__ offc1b,
                             const float* __restrict__ offc2w,
                             const float* __restrict__ wq2, const float* __restrict__ bq2,
                             const float* __restrict__ wk2, const float* __restrict__ bk2,
                             const float* __restrict__ wv2, const float* __restrict__ bv2,
                             const float* __restrict__ wo2, const float* __restrict__ bo2,
                             const float* __restrict__ bias2d) {
  extern __shared__ char smraw[];
  PatchSmem& S = *(PatchSmem*)smraw;
  int pb = blockIdx.x;
  int b = pb / NP, p = pb % NP;
  int tid = threadIdx.x; // 256
  const float* src = xn + ((long)b * SEQ + p * 8) * DM;
  for (int idx = tid; idx < PL * DM; idx += 256) {
    int i = idx >> 9, j = idx & 511;
    S.P[i][j] = src[i * DM + j];
  }
  __syncthreads();

  float WQ2 = *wq2, BQ2 = *bq2;
  float cw[9];
  #pragma unroll
  for (int t = 0; t < 9; t++) cw[t] = offc1w[t];
  float c1b = *offc1b;
  float ow0 = offc2w[0], ow1 = offc2w[1];

  for (int idx = tid; idx < PL * DM; idx += 256) {
    int i = idx >> 9, j = idx & 511;
    float h2 = c1b;
    #pragma unroll
    for (int di = -1; di <= 1; di++) {
      int ii = i + di;
      if (ii < 0 || ii > PL - 1) continue;
      #pragma unroll
      for (int dj = -1; dj <= 1; dj++) {
        int jj = j + dj;
        if (jj < 0 || jj > DM - 1) continue;
        h2 += (WQ2 * S.P[ii][jj] + BQ2) * cw[(di + 1) * 3 + (dj + 1)];
      }
    }
    float ox = tanhf(h2 * ow0) * 3.0f;
    float oy = tanhf(h2 * ow1) * 3.0f;
    float ix = ((float)j + ox) * (512.0f / 511.0f) - 0.5f;
    float iy = ((float)i + oy) * (16.0f / 15.0f) - 0.5f;
    float x0f = floorf(ix), y0f = floorf(iy);
    int x0 = (int)x0f, y0 = (int)y0f;
    float wx = ix - x0f, wy = iy - y0f;
    float acc = 0.f;
    if (x0 >= 0 && x0 < DM && y0 >= 0 && y0 < PL)                 acc += S.P[y0][x0]         * (1 - wx) * (1 - wy);
    if (x0 + 1 >= 0 && x0 + 1 < DM && y0 >= 0 && y0 < PL)         acc += S.P[y0][x0 + 1]     * wx * (1 - wy);
    if (x0 >= 0 && x0 < DM && y0 + 1 >= 0 && y0 + 1 < PL)         acc += S.P[y0 + 1][x0]     * (1 - wx) * wy;
    if (x0 + 1 >= 0 && x0 + 1 < DM && y0 + 1 >= 0 && y0 + 1 < PL) acc += S.P[y0 + 1][x0 + 1] * wx * wy;
    S.XS[i][j] = acc;
  }
  __syncthreads();

  // row sums of P and XS: thread (i, seg) sums 32 elems
  {
    int i = tid >> 4, seg = tid & 15;
    float sp = 0.f, sx = 0.f;
    int w0 = seg * 32;
    for (int w = w0; w < w0 + 32; w++) { sp += S.P[i][w]; sx += S.XS[i][w]; }
    S.red[0][i][seg] = sp;
    S.red[1][i][seg] = sx;
  }
  __syncthreads();
  if (tid < 2 * PL) {
    int arr = tid >> 4, i = tid & 15;
    float s = 0.f;
    #pragma unroll
    for (int seg = 0; seg < 16; seg++) s += S.red[arr][i][seg];
    if (arr == 0) S.rsP[i] = s; else S.rsX[i] = s;
  }
  __syncthreads();

  // sc[i][jj] via affine decomposition
  {
    float WK2 = *wk2, BK2 = *bk2;
    float s1 = WQ2 * WK2, s2 = WQ2 * BK2, s3 = BQ2 * WK2, s4 = 512.0f * BQ2 * BK2;
    int i = tid >> 4, jj = tid & 15;
    float dot = 0.f;
    for (int w = 0; w < DM; w++) dot += S.P[i][w] * S.XS[jj][w];
    S.sc[i][jj] = s1 * dot + s2 * S.rsP[i] + s3 * S.rsX[jj] + s4;
  }
  __syncthreads();
  if (tid < PL) {
    int i = tid;
    float mx = -1e30f;
    for (int jj = 0; jj < PL; jj++) mx = fmaxf(mx, S.sc[i][jj]);
    float sm = 0.f;
    for (int jj = 0; jj < PL; jj++) { float e = expf(S.sc[i][jj] - mx); S.sc[i][jj] = e; sm += e; }
    float inv = 1.0f / sm;
    float ab = 0.f;
    for (int jj = 0; jj < PL; jj++) { S.sc[i][jj] *= inv; ab += S.sc[i][jj] * bias2d[jj]; }
    S.attnb[i] = ab;
  }
  __syncthreads();

  float WV2 = *wv2, BV2 = *bv2, WO2 = *wo2, BO2 = *bo2;
  float* yo = y + ((long)b * P2 + p * PL) * DM;
  for (int idx = tid; idx < PL * DM; idx += 256) {
    int i = idx >> 9, w = idx & 511;
    float s = 0.f;
    #pragma unroll
    for (int jj = 0; jj < PL; jj++) s += S.sc[i][jj] * S.XS[jj][w];
    float o2 = WV2 * s + BV2 + S.attnb[i];
    yo[i * DM + w] = o2 * WO2 + BO2;
  }
}

// ============================================================================
// Tensor-core GEMM: bf16 3x split, mma.sync.m16n8k16, 128x128x16 tiles,
// 8 warps (64x32 per warp), single smem buffer, 2 CTAs/SM.
// Smem layout (uint32): AHp[8][136], ALp, BHp, BLp  (k-pairs packed bf16x2),
// then Ep[6][128], Rp[5][128] floats for EPI=1.
// TA=1: A global [K][M]; TA=0: A global [M][K]. B always [K][N].
// ============================================================================
constexpr int MLDP = 136;              // words per kp row
constexpr int TSZP = 8 * MLDP;         // 1088 words per tile array
constexpr int MMA_SMEM_WORDS = 4 * TSZP + 11 * 128;
constexpr int MMA_SMEM_BYTES = MMA_SMEM_WORDS * 4;   // 23040

template<int TA, int EPI>
__global__ __launch_bounds__(256, 2)
void mma_gemm(const float* __restrict__ A, const float* __restrict__ B,
              const float* __restrict__ biasM, float* __restrict__ C,
              int M, int N, int K,
              long long strideA, long long strideB, long long strideC,
              const float* __restrict__ w1, const float* __restrict__ AgWoP,
              const float* __restrict__ AbWoP, const float* __restrict__ wocsP,
              const float* __restrict__ cvec, const float* __restrict__ bias1d) {
  extern __shared__ uint32_t smu[];
  uint32_t* AHp = smu;
  uint32_t* ALp = smu + TSZP;
  uint32_t* BHp = smu + 2 * TSZP;
  uint32_t* BLp = smu + 3 * TSZP;
  float* Ep = (float*)(smu + 4 * TSZP);
  float* Rp = Ep + 6 * 128;

  A += blockIdx.z * strideA;
  B += blockIdx.z * strideB;
  C += blockIdx.z * strideC;
  const int m0 = blockIdx.y * 128, n0 = blockIdx.x * 128;
  const int tid = threadIdx.x;
  const int wid = tid >> 5, lane = tid & 31;
  const int wm = wid >> 2, wn = wid & 3;   // warp tile 64 x 32
  const int grp = lane >> 2, tig = lane & 3;

  if (EPI == 1 && tid < 128) {
    int bb = (int)(blockIdx.y >> 3);
    int n = n0 + tid;
    Ep[0 * 128 + tid] = AbWoP[bb * 512 + n] + cvec[n];
    Ep[1 * 128 + tid] = wocsP[n];
    Ep[2 * 128 + tid] = AgWoP[(bb * 4 + 0) * 512 + n];
    Ep[3 * 128 + tid] = AgWoP[(bb * 4 + 1) * 512 + n];
    Ep[4 * 128 + tid] = AgWoP[(bb * 4 + 2) * 512 + n];
    Ep[5 * 128 + tid] = AgWoP[(bb * 4 + 3) * 512 + n];
    int l = (m0 & 1023) + tid;
    Rp[0 * 128 + tid] = w1[(bb * 4 + 0) * 1024 + l];
    Rp[1 * 128 + tid] = w1[(bb * 4 + 1) * 1024 + l];
    Rp[2 * 128 + tid] = w1[(bb * 4 + 2) * 1024 + l];
    Rp[3 * 128 + tid] = w1[(bb * 4 + 3) * 1024 + l];
    Rp[4 * 128 + tid] = bias1d[l];
  }

  const int bkk = tid >> 4;              // k row index 0..15
  const int bnn = (tid & 15) * 8;        // column group
  const int amm2 = tid >> 1, akc = (tid & 1) * 8;  // TA=0 indices

  float c[4][4][4];
  #pragma unroll
  for (int mi = 0; mi < 4; mi++)
    #pragma unroll
    for (int ni = 0; ni < 4; ni++)
      #pragma unroll
      for (int r = 0; r < 4; r++) c[mi][ni][r] = 0.f;

  const int KT = K / 16;
  for (int kt = 0; kt < KT; kt++) {
    const int k0 = kt * 16;
    if (kt) __syncthreads();

    // ---- load A tile, split to bf16 H/L, pack k-pairs, store smem ----
    if (TA) {
      // A[k][m]: each thread has one k (= bkk), 8 m's. lanes 0-15 even k, 16-31 odd k.
      float av[8];
      *(float4*)(av)     = *(const float4*)(A + (long long)(k0 + bkk) * M + m0 + bnn);
      *(float4*)(av + 4) = *(const float4*)(A + (long long)(k0 + bkk) * M + m0 + bnn + 4);
      uint32_t hb[8], lb[8];
      #pragma unroll
      for (int i = 0; i < 8; i++) split_bf16(av[i], hb[i], lb[i]);
      #pragma unroll
      for (int i = 0; i < 8; i++) {
        uint32_t ho = __shfl_down_sync(0xffffffffu, hb[i], 16);
        uint32_t lo = __shfl_down_sync(0xffffffffu, lb[i], 16);
        hb[i] |= ho << 16;
        lb[i] |= lo << 16;
      }
      if (lane < 16) {
        int base = wid * MLDP + lane * 8;   // kp = wid (bkk>>1 = tid>>5)
        *(uint4*)&AHp[base]     = make_uint4(hb[0], hb[1], hb[2], hb[3]);
        *(uint4*)&AHp[base + 4] = make_uint4(hb[4], hb[5], hb[6], hb[7]);
        *(uint4*)&ALp[base]     = make_uint4(lb[0], lb[1], lb[2], lb[3]);
        *(uint4*)&ALp[base + 4] = make_uint4(lb[4], lb[5], lb[6], lb[7]);
      }
    } else {
      // A[m][k]: thread has 8 consecutive k at fixed m -> local pairs.
      float av[8];
      *(float4*)(av)     = *(const float4*)(A + (long long)(m0 + amm2) * K + k0 + akc);
      *(float4*)(av + 4) = *(const float4*)(A + (long long)(m0 + amm2) * K + k0 + akc + 4);
      uint32_t hb[8], lb[8];
      #pragma unroll
      for (int i = 0; i < 8; i++) split_bf16(av[i], hb[i], lb[i]);
      int kpb = akc >> 1;
      #pragma unroll
      for (int j = 0; j < 4; j++) {
        AHp[(kpb + j) * MLDP + amm2] = hb[2 * j] | (hb[2 * j + 1] << 16);
        ALp[(kpb + j) * MLDP + amm2] = lb[2 * j] | (lb[2 * j + 1] << 16);
      }
    }
    // ---- B tile [k][n]: same pairing trick as TA=1 ----
    {
      float bv[8];
      *(float4*)(bv)     = *(const float4*)(B + (long long)(k0 + bkk) * N + n0 + bnn);
      *(float4*)(bv + 4) = *(const float4*)(B + (long long)(k0 + bkk) * N + n0 + bnn + 4);
      uint32_t hb[8], lb[8];
      #pragma unroll
      for (int i = 0; i < 8; i++) split_bf16(bv[i], hb[i], lb[i]);
      #pragma unroll
      for (int i = 0; i < 8; i++) {
        uint32_t ho = __shfl_down_sync(0xffffffffu, hb[i], 16);
        uint32_t lo = __shfl_down_sync(0xffffffffu, lb[i], 16);
        hb[i] |= ho << 16;
        lb[i] |= lo << 16;
      }
      if (lane < 16) {
        int base = wid * MLDP + lane * 8;
        *(uint4*)&BHp[base]     = make_uint4(hb[0], hb[1], hb[2], hb[3]);
        *(uint4*)&BHp[base + 4] = make_uint4(hb[4], hb[5], hb[6], hb[7]);
        *(uint4*)&BLp[base]     = make_uint4(lb[0], lb[1], lb[2], lb[3]);
        *(uint4*)&BLp[base + 4] = make_uint4(lb[4], lb[5], lb[6], lb[7]);
      }
    }
    __syncthreads();

    // ---- compute one k16 step ----
    uint32_t bH0[4], bH1[4], bL0[4], bL1[4];
    #pragma unroll
    for (int ni = 0; ni < 4; ni++) {
      int n = wn * 32 + ni * 8 + grp;
      bH0[ni] = BHp[tig * MLDP + n];
      bH1[ni] = BHp[(tig + 4) * MLDP + n];
      bL0[ni] = BLp[tig * MLDP + n];
      bL1[ni] = BLp[(tig + 4) * MLDP + n];
    }
    #pragma unroll
    for (int mi = 0; mi < 4; mi++) {
      int m = wm * 64 + mi * 16 + grp;
      uint32_t aH0 = AHp[tig * MLDP + m];
      uint32_t aH1 = AHp[tig * MLDP + m + 8];
      uint32_t aH2 = AHp[(tig + 4) * MLDP + m];
      uint32_t aH3 = AHp[(tig + 4) * MLDP + m + 8];
      uint32_t aL0 = ALp[tig * MLDP + m];
      uint32_t aL1 = ALp[tig * MLDP + m + 8];
      uint32_t aL2 = ALp[(tig + 4) * MLDP + m];
      uint32_t aL3 = ALp[(tig + 4) * MLDP + m + 8];
      #pragma unroll
      for (int ni = 0; ni < 4; ni++) {
        mma_bf16(c[mi][ni], aH0, aH1, aH2, aH3, bH0[ni], bH1[ni]);
        mma_bf16(c[mi][ni], aH0, aH1, aH2, aH3, bL0[ni], bL1[ni]);
        mma_bf16(c[mi][ni], aL0, aL1, aL2, aL3, bH0[ni], bH1[ni]);
      }
    }
  }
  __syncthreads();

  // ---- epilogue + store ----
  #pragma unroll
  for (int mi = 0; mi < 4; mi++) {
    #pragma unroll
    for (int half = 0; half < 2; half++) {
      int ml = wm * 64 + mi * 16 + grp + 8 * half;
      int row = m0 + ml;
      float add_m = 0.f, blv = 0.f, w10 = 0.f, w11 = 0.f, w12 = 0.f, w13 = 0.f;
      if (EPI == 0) {
        add_m = biasM[row];
      } else {
        blv = Rp[4 * 128 + ml];
        w10 = Rp[0 * 128 + ml]; w11 = Rp[1 * 128 + ml];
        w12 = Rp[2 * 128 + ml]; w13 = Rp[3 * 128 + ml];
      }
      #pragma unroll
      for (int ni = 0; ni < 4; ni++) {
        int nn = wn * 32 + ni * 8 + 2 * tig;
        float v0 = c[mi][ni][2 * half + 0];
        float v1 = c[mi][ni][2 * half + 1];
        if (EPI == 0) {
          v0 += add_m; v1 += add_m;
        } else {
          v0 += Ep[nn] + blv * Ep[128 + nn]
              + w10 * Ep[2 * 128 + nn] + w11 * Ep[3 * 128 + nn]
              + w12 * Ep[4 * 128 + nn] + w13 * Ep[5 * 128 + nn];
          v1 += Ep[nn + 1] + blv * Ep[128 + nn + 1]
              + w10 * Ep[2 * 128 + nn + 1] + w11 * Ep[3 * 128 + nn + 1]
              + w12 * Ep[4 * 128 + nn + 1] + w13 * Ep[5 * 128 + nn + 1];
        }
        *(float2*)&C[(long long)row * N + n0 + nn] = make_float2(v0, v1);
      }
    }
  }
}

// ---------------- host launcher ----------------
extern "C" void kernel_launch(void* const* d_in, const int* in_sizes, int n_in,
                              void* d_out, int out_size) {
  const float* x      = (const float*)d_in[0];
  const float* ln_w   = (const float*)d_in[1];
  const float* ln_b   = (const float*)d_in[2];
  const float* wq     = (const float*)d_in[3];
  const float* bq     = (const float*)d_in[4];
  const float* wk     = (const float*)d_in[5];
  const float* bk     = (const float*)d_in[6];
  const float* wv     = (const float*)d_in[7];
  const float* bv     = (const float*)d_in[8];
  const float* wo     = (const float*)d_in[9];
  const float* bo     = (const float*)d_in[10];
  const float* off1_w = (const float*)d_in[11];
  const float* off1_b = (const float*)d_in[12];
  const float* off2_w = (const float*)d_in[13];
  const float* bias1d = (const float*)d_in[14];
  const float* wq2    = (const float*)d_in[15];
  const float* bq2    = (const float*)d_in[16];
  const float* wk2    = (const float*)d_in[17];
  const float* bk2    = (const float*)d_in[18];
  const float* wv2    = (const float*)d_in[19];
  const float* bv2    = (const float*)d_in[20];
  const float* wo2    = (const float*)d_in[21];
  const float* bo2    = (const float*)d_in[22];
  const float* offc1w = (const float*)d_in[23];
  const float* offc1b = (const float*)d_in[24];
  const float* offc2w = (const float*)d_in[25];
  const float* bias2d = (const float*)d_in[26];
  const float* write_w= (const float*)d_in[27];
  const float* write_b= (const float*)d_in[28];
  const float* proj_w = (const float*)d_in[29];
  const float* proj_b = (const float*)d_in[30];
  float* out = (float*)d_out;

  float *xn, *y, *x2d, *Z, *w1, *w1sum, *W1X, *Xs, *Qw, *Qs, *Kg, *Vg, *Ag, *Ab;
  float *AgWo, *AbWo, *wocs, *AgWoP, *AbWoP, *wocsP, *cvec, *U, *Weff, *beff, *cB;
  cudaGetSymbolAddress((void**)&xn,    g_xn);
  cudaGetSymbolAddress((void**)&y,     g_y);
  cudaGetSymbolAddress((void**)&x2d,   g_x2d);
  cudaGetSymbolAddress((void**)&Z,     g_Z);
  cudaGetSymbolAddress((void**)&w1,    g_w1);
  cudaGetSymbolAddress((void**)&w1sum, g_w1sum);
  cudaGetSymbolAddress((void**)&W1X,   g_W1X);
  cudaGetSymbolAddress((void**)&Xs,    g_Xs);
  cudaGetSymbolAddress((void**)&Qw,    g_Qw);
  cudaGetSymbolAddress((void**)&Qs,    g_Qs);
  cudaGetSymbolAddress((void**)&Kg,    g_Kg);
  cudaGetSymbolAddress((void**)&Vg,    g_Vg);
  cudaGetSymbolAddress((void**)&Ag,    g_Ag);
  cudaGetSymbolAddress((void**)&Ab,    g_Ab);
  cudaGetSymbolAddress((void**)&AgWo,  g_AgWo);
  cudaGetSymbolAddress((void**)&AbWo,  g_AbWo);
  cudaGetSymbolAddress((void**)&wocs,  g_wocs);
  cudaGetSymbolAddress((void**)&AgWoP, g_AgWoP);
  cudaGetSymbolAddress((void**)&AbWoP, g_AbWoP);
  cudaGetSymbolAddress((void**)&wocsP, g_wocsP);
  cudaGetSymbolAddress((void**)&cvec,  g_cvec);
  cudaGetSymbolAddress((void**)&U,     g_U);
  cudaGetSymbolAddress((void**)&Weff,  g_Weff);
  cudaGetSymbolAddress((void**)&beff,  g_beff);
  cudaGetSymbolAddress((void**)&cB,    g_cB);

  // LayerNorm
  ln_kernel<<<BSZ * SEQ, 256>>>(x, ln_w, ln_b, xn);

  // offset-net folding (tiny)
  weff_kernel<<<1, 128>>>(off1_w, off1_b, off2_w, bq, Weff, beff, cB);
  u_kernel<<<DM, 128>>>(wq, Weff, U);

  // Z = xn @ U, then w1
  z_kernel<<<BSZ * SEQ / 8, 256>>>(xn, U, Z);
  w1_kernel<<<dim3(BSZ * NG, SEQ / 256), 256>>>(Z, beff, cB, w1);

  // reductions over L
  w1x_kernel<<<dim3(BSZ, 4), dim3(128, 4)>>>(xn, w1, W1X, Xs, w1sum);

  // Kg/Vg
  kgvg_kernel<<<BSZ * NG, DM>>>(xn, wk, wv, Kg, Vg);

  // Qw = W1X@wq + w1sum*bq ; Qs = Xs@wq + 1024*bq
  rowgemm2<<<dim3(BSZ * NG, DM / 128), 128>>>(W1X, wq, Qw, DM, DM, w1sum, 0.f, bq);
  rowgemm2<<<dim3(BSZ,      DM / 128), 128>>>(Xs,  wq, Qs, DM, DM, nullptr, 1024.f, bq);

  // channel attention
  attn_kernel<<<dim3(BSZ, NH), CH>>>(Qw, Qs, Kg, Vg, bk, bv, Ag, Ab);

  // fold through wo then P_top
  rowgemm2<<<dim3(BSZ * NG, DM / 128), 128>>>(Ag, wo, AgWo, DM, DM, nullptr, 0.f, nullptr);
  rowgemm2<<<dim3(BSZ,      DM / 128), 128>>>(Ab, wo, AbWo, DM, DM, nullptr, 0.f, nullptr);
  rowgemm2<<<dim3(1,        DM / 128), 128>>>((const float*)nullptr, wo, wocs, DM, DM, nullptr, 0.f, nullptr);
  rowgemm2<<<dim3(BSZ * NG, DM / 128), 128>>>(AgWo, proj_w, AgWoP, DM, DM, nullptr, 0.f, nullptr);
  rowgemm2<<<dim3(BSZ,      DM / 128), 128>>>(AbWo, proj_w, AbWoP, DM, DM, nullptr, 0.f, nullptr);
  rowgemm2<<<dim3(1,        DM / 128), 128>>>(wocs, proj_w, wocsP, DM, DM, nullptr, 0.f, nullptr);
  rowgemm2<<<dim3(1,        DM / 128), 128>>>(bo,   proj_w, cvec,  DM, DM, nullptr, 1.f, proj_b);

  // 2D patch branch -> y
  int patch_smem = (int)sizeof(PatchSmem);
  cudaFuncSetAttribute((const void*)patch_kernel,
                       cudaFuncAttributeMaxDynamicSharedMemorySize, patch_smem);
  patch_kernel<<<BSZ * NP, 256, patch_smem>>>(xn, y, offc1w, offc1b, offc2w,
                                              wq2, bq2, wk2, bk2, wv2, bv2, wo2, bo2, bias2d);

  // x2d = write_w^T @ y + write_b (per batch) — bf16x3 tensor cores
  mma_gemm<1, 0><<<dim3(DM / 128, SEQ / 128, BSZ), 256, MMA_SMEM_BYTES>>>(
      write_w, y, write_b, x2d, SEQ, DM, P2,
      0, (long long)P2 * DM, (long long)SEQ * DM,
      nullptr, nullptr, nullptr, nullptr, nullptr, nullptr);

  // out = x2d @ P_bot + x1d-epilogue — bf16x3 tensor cores
  mma_gemm<0, 1><<<dim3(DM / 128, BSZ * SEQ / 128, 1), 256, MMA_SMEM_BYTES>>>(
      x2d, proj_w + (long long)DM * DM, nullptr, out, BSZ * SEQ, DM, DM,
      0, 0, 0,
      w1, AgWoP, AbWoP, wocsP, cvec, bias1d);
}

// round 6
// speedup vs baseline: 1.9078x; 1.1571x over previous
#include <cuda_runtime.h>
#include <cuda_bf16.h>
#include <math.h>
#include <stdint.h>

// ---------------- problem dims ----------------
constexpr int BSZ = 16;
constexpr int SEQ = 1024;
constexpr int DM  = 512;
constexpr int NG  = 4;
constexpr int CG  = 128;
constexpr int NH  = 8;
constexpr int CH  = 64;
constexpr int NP  = 127;
constexpr int PL  = 16;
constexpr int P2  = NP * PL;   // 2032
constexpr int KP2 = P2 / 2;    // 1016 k-pairs for write GEMM

// ---------------- scratch ----------------
__device__ float g_xn [(size_t)BSZ*SEQ*DM];
__device__ float g_Z  [(size_t)BSZ*SEQ*12];
__device__ float g_w1 [BSZ*NG*SEQ];
__device__ float g_w1sum[BSZ*NG];
__device__ float g_W1X[BSZ*NG*DM];
__device__ float g_Xs [BSZ*DM];
__device__ float g_Qw [BSZ*NG*DM];
__device__ float g_Qs [BSZ*DM];
__device__ float g_Kg [BSZ*NG*DM];
__device__ float g_Vg [BSZ*NG*DM];
__device__ float g_Ag [BSZ*NG*DM];
__device__ float g_Ab [BSZ*DM];
__device__ float g_AgWo [BSZ*NG*DM];
__device__ float g_AbWo [BSZ*DM];
__device__ float g_wocs [DM];
__device__ float g_AgWoP[BSZ*NG*DM];
__device__ float g_AbWoP[BSZ*DM];
__device__ float g_wocsP[DM];
__device__ float g_cvec [DM];
__device__ float g_U   [DM*12];
__device__ float g_Weff[3*CG];
__device__ float g_beff[1];
__device__ float g_cB  [12];
// packed bf16-pair operands (uint32 = bf16x2 along k)
__device__ uint32_t g_wtH[(size_t)KP2*SEQ];
__device__ uint32_t g_wtL[(size_t)KP2*SEQ];
__device__ uint32_t g_ytH[(size_t)BSZ*KP2*DM];
__device__ uint32_t g_ytL[(size_t)BSZ*KP2*DM];
__device__ uint32_t g_x2dH[(size_t)(DM/2)*BSZ*SEQ];
__device__ uint32_t g_x2dL[(size_t)(DM/2)*BSZ*SEQ];
__device__ uint32_t g_pbH[(DM/2)*DM];
__device__ uint32_t g_pbL[(DM/2)*DM];

__device__ __forceinline__ float warp_sum(float v) {
  #pragma unroll
  for (int o = 16; o; o >>= 1) v += __shfl_xor_sync(0xffffffffu, v, o);
  return v;
}

__device__ __forceinline__ void split_bf16(float v, uint32_t& hb, uint32_t& lb) {
  __nv_bfloat16 h = __float2bfloat16(v);
  float hf = __bfloat162float(h);
  __nv_bfloat16 l = __float2bfloat16(v - hf);
  hb = (uint32_t)__bfloat16_as_ushort(h);
  lb = (uint32_t)__bfloat16_as_ushort(l);
}
__device__ __forceinline__ void pack_pair(float v0, float v1, uint32_t& hw, uint32_t& lw) {
  uint32_t h0, l0, h1, l1;
  split_bf16(v0, h0, l0);
  split_bf16(v1, h1, l1);
  hw = h0 | (h1 << 16);
  lw = l0 | (l1 << 16);
}
__device__ __forceinline__ void mma_bf16(float* c,
    uint32_t a0, uint32_t a1, uint32_t a2, uint32_t a3,
    uint32_t b0, uint32_t b1) {
  asm volatile(
    "mma.sync.aligned.m16n8k16.row.col.f32.bf16.bf16.f32 "
    "{%0,%1,%2,%3}, {%4,%5,%6,%7}, {%8,%9}, {%0,%1,%2,%3};"
    : "+f"(c[0]), "+f"(c[1]), "+f"(c[2]), "+f"(c[3])
    : "r"(a0), "r"(a1), "r"(a2), "r"(a3), "r"(b0), "r"(b1));
}
__device__ __forceinline__ uint32_t smem_u32(const void* p) {
  uint32_t a;
  asm("{ .reg .u64 t; cvta.to.shared.u64 t, %1; cvt.u32.u64 %0, t; }" : "=r"(a) : "l"(p));
  return a;
}
__device__ __forceinline__ void cp_async16(uint32_t s, const void* g) {
  asm volatile("cp.async.cg.shared.global [%0], [%1], 16;" :: "r"(s), "l"(g));
}

// ---------------- LayerNorm ----------------
__global__ void ln_kernel(const float* __restrict__ x,
                          const float* __restrict__ lw,
                          const float* __restrict__ lb,
                          float* __restrict__ xn) {
  long row = blockIdx.x;
  const float* xr = x + row * DM;
  float* o = xn + row * DM;
  int t = threadIdx.x; // 256
  float v0 = xr[t], v1 = xr[t + 256];
  __shared__ float red[8];
  float s = warp_sum(v0 + v1);
  if ((t & 31) == 0) red[t >> 5] = s;
  __syncthreads();
  float tot = 0;
  #pragma unroll
  for (int i = 0; i < 8; i++) tot += red[i];
  float mu = tot * (1.0f / 512.0f);
  __syncthreads();
  float d0 = v0 - mu, d1 = v1 - mu;
  float sq = warp_sum(d0 * d0 + d1 * d1);
  if ((t & 31) == 0) red[t >> 5] = sq;
  __syncthreads();
  float vtot = 0;
  #pragma unroll
  for (int i = 0; i < 8; i++) vtot += red[i];
  float inv = rsqrtf(vtot * (1.0f / 512.0f) + 1e-5f);
  o[t]       = d0 * inv * lw[t]       + lb[t];
  o[t + 256] = d1 * inv * lw[t + 256] + lb[t + 256];
}

// ---------------- fold offset net ----------------
__global__ void weff_kernel(const float* __restrict__ off1_w,
                            const float* __restrict__ off1_b,
                            const float* __restrict__ off2_w,
                            const float* __restrict__ bq,
                            float* __restrict__ Weff, float* __restrict__ beff,
                            float* __restrict__ cB) {
  int i = threadIdx.x; // 128
  for (int w = 0; w < 3; w++) {
    float s = 0.f;
    for (int o = 0; o < CG; o++) s += off1_w[(w * CG + i) * CG + o] * off2_w[o];
    Weff[w * CG + i] = s;
  }
  if (i == 0) {
    float s = 0.f;
    for (int o = 0; o < CG; o++) s += off1_b[o] * off2_w[o];
    *beff = s;
  }
  __syncthreads();
  if (i < 12) {
    int w = i >> 2, g = i & 3;
    float s = 0.f;
    for (int c = 0; c < CG; c++) s += bq[g * CG + c] * Weff[w * CG + c];
    cB[i] = s;
  }
}

__global__ void u_kernel(const float* __restrict__ wq, const float* __restrict__ Weff,
                         float* __restrict__ U) {
  int d = blockIdx.x;
  int t = threadIdx.x; // 128
  __shared__ float red[4];
  int warp = t >> 5, lane = t & 31;
  #pragma unroll
  for (int g = 0; g < 4; g++) {
    float wqv = wq[d * DM + g * CG + t];
    #pragma unroll
    for (int w = 0; w < 3; w++) {
      float p = wqv * Weff[w * CG + t];
      p = warp_sum(p);
      if (lane == 0) red[warp] = p;
      __syncthreads();
      if (t == 0) U[d * 12 + w * 4 + g] = red[0] + red[1] + red[2] + red[3];
      __syncthreads();
    }
  }
}

__global__ void z_kernel(const float* __restrict__ xn, const float* __restrict__ U,
                         float* __restrict__ Z) {
  __shared__ float Us[DM * 13];
  int tid = threadIdx.x; // 256
  for (int idx = tid; idx < DM * 12; idx += 256) {
    int d = idx / 12, j = idx - d * 12;
    Us[d * 13 + j] = U[idx];
  }
  __syncthreads();
  int warp = tid >> 5, lane = tid & 31;
  long row = (long)blockIdx.x * 8 + warp;
  const float* xr = xn + row * DM;
  float acc[12];
  #pragma unroll
  for (int j = 0; j < 12; j++) acc[j] = 0.f;
  for (int i = lane; i < DM; i += 32) {
    float xv = xr[i];
    #pragma unroll
    for (int j = 0; j < 12; j++) acc[j] += xv * Us[i * 13 + j];
  }
  #pragma unroll
  for (int j = 0; j < 12; j++) acc[j] = warp_sum(acc[j]);
  if (lane == 0) {
    #pragma unroll
    for (int j = 0; j < 12; j++) Z[row * 12 + j] = acc[j];
  }
}

__global__ void w1_kernel(const float* __restrict__ Z, const float* __restrict__ beff,
                          const float* __restrict__ cB, float* __restrict__ w1) {
  int bg = blockIdx.x;
  int b = bg >> 2, g = bg & 3;
  int l = blockIdx.y * 256 + threadIdx.x;
  float s = *beff;
  #pragma unroll
  for (int w = 0; w < 3; w++) {
    int lw = l + w - 1;
    if (lw >= 0 && lw < SEQ)
      s += Z[((long)b * SEQ + lw) * 12 + w * 4 + g] + cB[w * 4 + g];
  }
  float off = tanhf(s) * 3.0f;
  float ixv = ((float)l + off) * (1.0f / 1023.0f) - 0.5f;
  w1[bg * SEQ + l] = 1.0f - fabsf(ixv);
}

__global__ void w1x_kernel(const float* __restrict__ xn, const float* __restrict__ w1,
                           float* __restrict__ W1X, float* __restrict__ Xs,
                           float* __restrict__ w1sum) {
  int b = blockIdx.x, ec = blockIdx.y;
  int e = ec * 128 + threadIdx.x;
  int s = threadIdx.y; // 4 strips
  __shared__ float w1s[NG][SEQ];
  __shared__ float red[4][5][128];
  int t = threadIdx.y * 128 + threadIdx.x;
  for (int idx = t; idx < NG * SEQ; idx += 512) w1s[idx >> 10][idx & 1023] = w1[b * NG * SEQ + idx];
  __syncthreads();
  float a0 = 0, a1 = 0, a2 = 0, a3 = 0, as_ = 0;
  int lbeg = s * 256;
  for (int l = lbeg; l < lbeg + 256; l++) {
    float xv = xn[((long)b * SEQ + l) * DM + e];
    a0 += xv * w1s[0][l]; a1 += xv * w1s[1][l];
    a2 += xv * w1s[2][l]; a3 += xv * w1s[3][l];
    as_ += xv;
  }
  red[s][0][threadIdx.x] = a0; red[s][1][threadIdx.x] = a1;
  red[s][2][threadIdx.x] = a2; red[s][3][threadIdx.x] = a3;
  red[s][4][threadIdx.x] = as_;
  __syncthreads();
  if (s == 0) {
    #pragma unroll
    for (int g = 0; g < 4; g++) {
      float v = red[0][g][threadIdx.x] + red[1][g][threadIdx.x] +
                red[2][g][threadIdx.x] + red[3][g][threadIdx.x];
      W1X[(b * NG + g) * DM + e] = v;
    }
    float vq = red[0][4][threadIdx.x] + red[1][4][threadIdx.x] +
               red[2][4][threadIdx.x] + red[3][4][threadIdx.x];
    Xs[b * DM + e] = vq;
  }
  if (ec == 0 && s == 0 && threadIdx.x < 4) {
    float acc = 0.f;
    for (int l = 0; l < SEQ; l++) acc += w1s[threadIdx.x][l];
    w1sum[b * NG + threadIdx.x] = acc;
  }
}

__global__ void kgvg_kernel(const float* __restrict__ xn,
                            const float* __restrict__ wk, const float* __restrict__ wv,
                            float* __restrict__ Kg, float* __restrict__ Vg) {
  int bg = blockIdx.x; int b = bg >> 2, g = bg & 3;
  int e = threadIdx.x; // 512
  __shared__ float ms[CG];
  if (threadIdx.x < CG)
    ms[threadIdx.x] = 0.5f * (xn[((long)b * SEQ + 511) * DM + g * CG + threadIdx.x] +
                              xn[((long)b * SEQ + 512) * DM + g * CG + threadIdx.x]);
  __syncthreads();
  float sk = 0.f, sv = 0.f;
  for (int c = 0; c < CG; c++) {
    float mv = ms[c];
    sk += mv * wk[(g * CG + c) * DM + e];
    sv += mv * wv[(g * CG + c) * DM + e];
  }
  Kg[bg * DM + e] = sk;
  Vg[bg * DM + e] = sv;
}

__global__ void rowgemm2(const float* __restrict__ A, const float* __restrict__ B,
                         float* __restrict__ C, int K, int N,
                         const float* __restrict__ scalev, float cscale,
                         const float* __restrict__ biasv) {
  int r = blockIdx.x;
  int e = blockIdx.y * 128 + threadIdx.x;
  __shared__ float Ar[1024];
  for (int idx = threadIdx.x; idx < K; idx += 128)
    Ar[idx] = A ? A[(long)r * K + idx] : 1.0f;
  __syncthreads();
  float s = 0.f;
  for (int d = 0; d < K; d++) s += Ar[d] * B[(long)d * N + e];
  if (biasv) {
    float sc = scalev ? scalev[r] : cscale;
    s += sc * biasv[e];
  }
  C[(long)r * N + e] = s;
}

__global__ void attn_kernel(const float* __restrict__ Qw, const float* __restrict__ Qs,
                            const float* __restrict__ Kg, const float* __restrict__ Vg,
                            const float* __restrict__ bk, const float* __restrict__ bv,
                            float* __restrict__ Ag, float* __restrict__ Ab) {
  int b = blockIdx.x, h = blockIdx.y;
  int i = threadIdx.x; // 64
  __shared__ float Kgs[NG][CH], Vgs[NG][CH], bks[CH], bvs[CH];
  __shared__ float aa[CH][CH + 1];
  #pragma unroll
  for (int g = 0; g < NG; g++) {
    Kgs[g][i] = Kg[(b * NG + g) * DM + h * CH + i];
    Vgs[g][i] = Vg[(b * NG + g) * DM + h * CH + i];
  }
  bks[i] = bk[h * CH + i];
  bvs[i] = bv[h * CH + i];
  __syncthreads();
  float qw0 = Qw[(b * NG + 0) * DM + h * CH + i];
  float qw1 = Qw[(b * NG + 1) * DM + h * CH + i];
  float qw2 = Qw[(b * NG + 2) * DM + h * CH + i];
  float qw3 = Qw[(b * NG + 3) * DM + h * CH + i];
  float qsv = Qs[b * DM + h * CH + i];
  const float scale = 0.044194173824159216f;
  float mx = -1e30f;
  for (int j = 0; j < CH; j++) {
    float s = (qw0 * Kgs[0][j] + qw1 * Kgs[1][j] + qw2 * Kgs[2][j] + qw3 * Kgs[3][j]
               + qsv * bks[j]) * scale;
    aa[i][j] = s;
    mx = fmaxf(mx, s);
  }
  float sm = 0.f;
  for (int j = 0; j < CH; j++) { float e = expf(aa[i][j] - mx); aa[i][j] = e; sm += e; }
  float inv = 1.0f / sm;
  float ag0 = 0, ag1 = 0, ag2 = 0, ag3 = 0, ab = 0;
  for (int j = 0; j < CH; j++) {
    float w = aa[i][j] * inv;
    ag0 += w * Vgs[0][j]; ag1 += w * Vgs[1][j];
    ag2 += w * Vgs[2][j]; ag3 += w * Vgs[3][j];
    ab  += w * bvs[j];
  }
  Ag[(b * NG + 0) * DM + h * CH + i] = ag0;
  Ag[(b * NG + 1) * DM + h * CH + i] = ag1;
  Ag[(b * NG + 2) * DM + h * CH + i] = ag2;
  Ag[(b * NG + 3) * DM + h * CH + i] = ag3;
  Ab[b * DM + h * CH + i] = ab;
}

// ---------------- per-patch 2D deformable attention ----------------
// Epilogue writes k-pair-packed bf16 H/L directly: yt[b][kp][w], kp = p*8 + i/2.
struct PatchSmem {
  float P[PL][DM + 1];
  float XS[PL][DM + 1];
  float sc[PL][PL + 1];
  float attnb[PL];
  float rsP[PL];
  float rsX[PL];
  float red[2][PL][PL];
};

__global__ void patch_kernel(const float* __restrict__ xn,
                             uint32_t* __restrict__ ytH, uint32_t* __restrict__ ytL,
                             const float* __restrict__ offc1w, const float* __restrict__ offc1b,
                             const float* __restrict__ offc2w,
                             const float* __restrict__ wq2, const float* __restrict__ bq2,
                             const float* __restrict__ wk2, const float* __restrict__ bk2,
                             const float* __restrict__ wv2, const float* __restrict__ bv2,
                             const float* __restrict__ wo2, const float* __restrict__ bo2,
                             const float* __restrict__ bias2d) {
  extern __shared__ char smraw[];
  PatchSmem& S = *(PatchSmem*)smraw;
  int pb = blockIdx.x;
  int b = pb / NP, p = pb % NP;
  int tid = threadIdx.x; // 256
  const float* src = xn + ((long)b * SEQ + p * 8) * DM;
  for (int idx = tid; idx < PL * DM; idx += 256) {
    int i = idx >> 9, j = idx & 511;
    S.P[i][j] = src[i * DM + j];
  }
  __syncthreads();

  float WQ2 = *wq2, BQ2 = *bq2;
  float cw[9];
  #pragma unroll
  for (int t = 0; t < 9; t++) cw[t] = offc1w[t];
  float c1b = *offc1b;
  float ow0 = offc2w[0], ow1 = offc2w[1];

  for (int idx = tid; idx < PL * DM; idx += 256) {
    int i = idx >> 9, j = idx & 511;
    float h2 = c1b;
    #pragma unroll
    for (int di = -1; di <= 1; di++) {
      int ii = i + di;
      if (ii < 0 || ii > PL - 1) continue;
      #pragma unroll
      for (int dj = -1; dj <= 1; dj++) {
        int jj = j + dj;
        if (jj < 0 || jj > DM - 1) continue;
        h2 += (WQ2 * S.P[ii][jj] + BQ2) * cw[(di + 1) * 3 + (dj + 1)];
      }
    }
    float ox = tanhf(h2 * ow0) * 3.0f;
    float oy = tanhf(h2 * ow1) * 3.0f;
    float ix = ((float)j + ox) * (512.0f / 511.0f) - 0.5f;
    float iy = ((float)i + oy) * (16.0f / 15.0f) - 0.5f;
    float x0f = floorf(ix), y0f = floorf(iy);
    int x0 = (int)x0f, y0 = (int)y0f;
    float wx = ix - x0f, wy = iy - y0f;
    float acc = 0.f;
    if (x0 >= 0 && x0 < DM && y0 >= 0 && y0 < PL)                 acc += S.P[y0][x0]         * (1 - wx) * (1 - wy);
    if (x0 + 1 >= 0 && x0 + 1 < DM && y0 >= 0 && y0 < PL)         acc += S.P[y0][x0 + 1]     * wx * (1 - wy);
    if (x0 >= 0 && x0 < DM && y0 + 1 >= 0 && y0 + 1 < PL)         acc += S.P[y0 + 1][x0]     * (1 - wx) * wy;
    if (x0 + 1 >= 0 && x0 + 1 < DM && y0 + 1 >= 0 && y0 + 1 < PL) acc += S.P[y0 + 1][x0 + 1] * wx * wy;
    S.XS[i][j] = acc;
  }
  __syncthreads();

  {
    int i = tid >> 4, seg = tid & 15;
    float sp = 0.f, sx = 0.f;
    int w0 = seg * 32;
    for (int w = w0; w < w0 + 32; w++) { sp += S.P[i][w]; sx += S.XS[i][w]; }
    S.red[0][i][seg] = sp;
    S.red[1][i][seg] = sx;
  }
  __syncthreads();
  if (tid < 2 * PL) {
    int arr = tid >> 4, i = tid & 15;
    float s = 0.f;
    #pragma unroll
    for (int seg = 0; seg < 16; seg++) s += S.red[arr][i][seg];
    if (arr == 0) S.rsP[i] = s; else S.rsX[i] = s;
  }
  __syncthreads();

  {
    float WK2 = *wk2, BK2 = *bk2;
    float s1 = WQ2 * WK2, s2 = WQ2 * BK2, s3 = BQ2 * WK2, s4 = 512.0f * BQ2 * BK2;
    int i = tid >> 4, jj = tid & 15;
    float dot = 0.f;
    for (int w = 0; w < DM; w++) dot += S.P[i][w] * S.XS[jj][w];
    S.sc[i][jj] = s1 * dot + s2 * S.rsP[i] + s3 * S.rsX[jj] + s4;
  }
  __syncthreads();
  if (tid < PL) {
    int i = tid;
    float mx = -1e30f;
    for (int jj = 0; jj < PL; jj++) mx = fmaxf(mx, S.sc[i][jj]);
    float sm = 0.f;
    for (int jj = 0; jj < PL; jj++) { float e = expf(S.sc[i][jj] - mx); S.sc[i][jj] = e; sm += e; }
    float inv = 1.0f / sm;
    float ab = 0.f;
    for (int jj = 0; jj < PL; jj++) { S.sc[i][jj] *= inv; ab += S.sc[i][jj] * bias2d[jj]; }
    S.attnb[i] = ab;
  }
  __syncthreads();

  float WV2 = *wv2, BV2 = *bv2, WO2 = *wo2, BO2 = *bo2;
  // each thread computes two consecutive rows (a k-pair) at one w
  for (int idx = tid; idx < 8 * DM; idx += 256) {
    int i2 = (idx >> 9) * 2;    // 0,2,...,14
    int w = idx & 511;
    float s0 = 0.f, s1 = 0.f;
    #pragma unroll
    for (int jj = 0; jj < PL; jj++) {
      float xv = S.XS[jj][w];
      s0 += S.sc[i2][jj] * xv;
      s1 += S.sc[i2 + 1][jj] * xv;
    }
    float o0 = (WV2 * s0 + BV2 + S.attnb[i2]) * WO2 + BO2;
    float o1 = (WV2 * s1 + BV2 + S.attnb[i2 + 1]) * WO2 + BO2;
    uint32_t hw, lw;
    pack_pair(o0, o1, hw, lw);
    long kp = (long)b * KP2 + p * 8 + (i2 >> 1);
    ytH[kp * DM + w] = hw;
    ytL[kp * DM + w] = lw;
  }
}

// ---------------- convert float [K][N] -> packed bf16-pair H/L [K/2][N] ----
__global__ void convPair_kernel(const float* __restrict__ src,
                                uint32_t* __restrict__ dH, uint32_t* __restrict__ dL,
                                int N, int logN) {
  long idx = (long)blockIdx.x * 256 + threadIdx.x;
  int n = (int)(idx & (N - 1));
  long kp = idx >> logN;
  float v0 = src[(2 * kp) * N + n];
  float v1 = src[(2 * kp + 1) * N + n];
  uint32_t hw, lw;
  pack_pair(v0, v1, hw, lw);
  dH[idx] = hw;
  dL[idx] = lw;
}

// ============================================================================
// bf16x3 mma.sync GEMM with pre-packed operands + cp.async double buffering.
// A: [K/2][lda] packed pairs (col = m), B: [K/2][ldb] (col = n).
// Tiles 128x128xK16, 8 warps 64x32, smem [8][136] per array, 2 stages.
// EPI=0: v = acc + biasM[m0+m]; pack (n,n+1) pairs -> CH/CL [(n)/2][zb + row]
// EPI=1: v = acc + rank-6 epilogue -> Cf float [row][N]
// ============================================================================
constexpr int MLDP = 136;
constexpr int TSZP = 8 * MLDP;                       // 1088 words
constexpr int G_SMEM_WORDS = 2 * 4 * TSZP + 11 * 128; // 10112
constexpr int G_SMEM_BYTES = G_SMEM_WORDS * 4;        // 40448

template<int EPI>
__global__ __launch_bounds__(256, 2)
void mma_gemm2(const uint32_t* __restrict__ AHg, const uint32_t* __restrict__ ALg, int lda,
               const uint32_t* __restrict__ BHg, const uint32_t* __restrict__ BLg, int ldb,
               long long sB, int N, int K,
               const float* __restrict__ biasM,
               float* __restrict__ Cf,
               uint32_t* __restrict__ CH, uint32_t* __restrict__ CL, int ldc, int zMul,
               const float* __restrict__ w1, const float* __restrict__ AgWoP,
               const float* __restrict__ AbWoP, const float* __restrict__ wocsP,
               const float* __restrict__ cvec, const float* __restrict__ bias1d) {
  extern __shared__ uint32_t smu[];
  float* Ep = (float*)(smu + 8 * TSZP);
  float* Rp = Ep + 6 * 128;

  BHg += blockIdx.z * sB;
  BLg += blockIdx.z * sB;
  const int m0 = blockIdx.y * 128, n0 = blockIdx.x * 128;
  const int tid = threadIdx.x;
  const int wid = tid >> 5, lane = tid & 31;
  const int wm = wid >> 2, wn = wid & 3;
  const int grp = lane >> 2, tig = lane & 3;
  const uint32_t smb = smem_u32(smu);

  if (EPI == 1 && tid < 128) {
    int bb = (int)(blockIdx.y >> 3);
    int n = n0 + tid;
    Ep[0 * 128 + tid] = AbWoP[bb * 512 + n] + cvec[n];
    Ep[1 * 128 + tid] = wocsP[n];
    Ep[2 * 128 + tid] = AgWoP[(bb * 4 + 0) * 512 + n];
    Ep[3 * 128 + tid] = AgWoP[(bb * 4 + 1) * 512 + n];
    Ep[4 * 128 + tid] = AgWoP[(bb * 4 + 2) * 512 + n];
    Ep[5 * 128 + tid] = AgWoP[(bb * 4 + 3) * 512 + n];
    int l = (m0 & 1023) + tid;
    Rp[0 * 128 + tid] = w1[(bb * 4 + 0) * 1024 + l];
    Rp[1 * 128 + tid] = w1[(bb * 4 + 1) * 1024 + l];
    Rp[2 * 128 + tid] = w1[(bb * 4 + 2) * 1024 + l];
    Rp[3 * 128 + tid] = w1[(bb * 4 + 3) * 1024 + l];
    Rp[4 * 128 + tid] = bias1d[l];
  }

  const int r = tid >> 5;          // kp row 0..7
  const int cc = (tid & 31) * 4;   // col group
  auto issue_stage = [&](int kt, int buf) {
    long kp0 = (long)kt * 8 + r;
    uint32_t sd = smb + (uint32_t)(buf * 4 * TSZP + r * MLDP + cc) * 4;
    cp_async16(sd,                    AHg + kp0 * lda + m0 + cc);
    cp_async16(sd + TSZP * 4,         ALg + kp0 * lda + m0 + cc);
    cp_async16(sd + 2 * TSZP * 4,     BHg + kp0 * ldb + n0 + cc);
    cp_async16(sd + 3 * TSZP * 4,     BLg + kp0 * ldb + n0 + cc);
    asm volatile("cp.async.commit_group;");
  };

  float c[4][4][4];
  #pragma unroll
  for (int mi = 0; mi < 4; mi++)
    #pragma unroll
    for (int ni = 0; ni < 4; ni++)
      #pragma unroll
      for (int q = 0; q < 4; q++) c[mi][ni][q] = 0.f;

  const int KT = K / 16;
  issue_stage(0, 0);
  for (int kt = 0; kt < KT; kt++) {
    int buf = kt & 1;
    if (kt + 1 < KT) {
      issue_stage(kt + 1, buf ^ 1);
      asm volatile("cp.async.wait_group 1;");
    } else {
      asm volatile("cp.async.wait_group 0;");
    }
    __syncthreads();

    const uint32_t* AHs = smu + buf * 4 * TSZP;
    const uint32_t* ALs = AHs + TSZP;
    const uint32_t* BHs = AHs + 2 * TSZP;
    const uint32_t* BLs = AHs + 3 * TSZP;

    uint32_t bH0[4], bH1[4], bL0[4], bL1[4];
    #pragma unroll
    for (int ni = 0; ni < 4; ni++) {
      int n = wn * 32 + ni * 8 + grp;
      bH0[ni] = BHs[tig * MLDP + n];
      bH1[ni] = BHs[(tig + 4) * MLDP + n];
      bL0[ni] = BLs[tig * MLDP + n];
      bL1[ni] = BLs[(tig + 4) * MLDP + n];
    }
    #pragma unroll
    for (int mi = 0; mi < 4; mi++) {
      int m = wm * 64 + mi * 16 + grp;
      uint32_t aH0 = AHs[tig * MLDP + m];
      uint32_t aH1 = AHs[tig * MLDP + m + 8];
      uint32_t aH2 = AHs[(tig + 4) * MLDP + m];
      uint32_t aH3 = AHs[(tig + 4) * MLDP + m + 8];
      uint32_t aL0 = ALs[tig * MLDP + m];
      uint32_t aL1 = ALs[tig * MLDP + m + 8];
      uint32_t aL2 = ALs[(tig + 4) * MLDP + m];
      uint32_t aL3 = ALs[(tig + 4) * MLDP + m + 8];
      #pragma unroll
      for (int ni = 0; ni < 4; ni++) {
        mma_bf16(c[mi][ni], aH0, aH1, aH2, aH3, bH0[ni], bH1[ni]);
        mma_bf16(c[mi][ni], aH0, aH1, aH2, aH3, bL0[ni], bL1[ni]);
        mma_bf16(c[mi][ni], aL0, aL1, aL2, aL3, bH0[ni], bH1[ni]);
      }
    }
    __syncthreads();
  }

  // ---- epilogue ----
  const int zb = (int)blockIdx.z * zMul;
  #pragma unroll
  for (int mi = 0; mi < 4; mi++) {
    #pragma unroll
    for (int half = 0; half < 2; half++) {
      int ml = wm * 64 + mi * 16 + grp + 8 * half;
      int row = m0 + ml;
      if (EPI == 0) {
        float bm = biasM[row];
        #pragma unroll
        for (int ni = 0; ni < 4; ni++) {
          int nn = wn * 32 + ni * 8 + 2 * tig;
          float v0 = c[mi][ni][2 * half + 0] + bm;
          float v1 = c[mi][ni][2 * half + 1] + bm;
          uint32_t hw, lw;
          pack_pair(v0, v1, hw, lw);
          long o = (long)((n0 + nn) >> 1) * ldc + zb + row;
          CH[o] = hw;
          CL[o] = lw;
        }
      } else {
        float blv = Rp[4 * 128 + ml];
        float w10 = Rp[0 * 128 + ml], w11 = Rp[1 * 128 + ml];
        float w12 = Rp[2 * 128 + ml], w13 = Rp[3 * 128 + ml];
        #pragma unroll
        for (int ni = 0; ni < 4; ni++) {
          int nn = wn * 32 + ni * 8 + 2 * tig;
          float v0 = c[mi][ni][2 * half + 0]
                   + Ep[nn] + blv * Ep[128 + nn]
                   + w10 * Ep[2 * 128 + nn] + w11 * Ep[3 * 128 + nn]
                   + w12 * Ep[4 * 128 + nn] + w13 * Ep[5 * 128 + nn];
          float v1 = c[mi][ni][2 * half + 1]
                   + Ep[nn + 1] + blv * Ep[128 + nn + 1]
                   + w10 * Ep[2 * 128 + nn + 1] + w11 * Ep[3 * 128 + nn + 1]
                   + w12 * Ep[4 * 128 + nn + 1] + w13 * Ep[5 * 128 + nn + 1];
          *(float2*)&Cf[(long)row * N + n0 + nn] = make_float2(v0, v1);
        }
      }
    }
  }
}

// ---------------- host launcher ----------------
extern "C" void kernel_launch(void* const* d_in, const int* in_sizes, int n_in,
                              void* d_out, int out_size) {
  const float* x      = (const float*)d_in[0];
  const float* ln_w   = (const float*)d_in[1];
  const float* ln_b   = (const float*)d_in[2];
  const float* wq     = (const float*)d_in[3];
  const float* bq     = (const float*)d_in[4];
  const float* wk     = (const float*)d_in[5];
  const float* bk     = (const float*)d_in[6];
  const float* wv     = (const float*)d_in[7];
  const float* bv     = (const float*)d_in[8];
  const float* wo     = (const float*)d_in[9];
  const float* bo     = (const float*)d_in[10];
  const float* off1_w = (const float*)d_in[11];
  const float* off1_b = (const float*)d_in[12];
  const float* off2_w = (const float*)d_in[13];
  const float* bias1d = (const float*)d_in[14];
  const float* wq2    = (const float*)d_in[15];
  const float* bq2    = (const float*)d_in[16];
  const float* wk2    = (const float*)d_in[17];
  const float* bk2    = (const float*)d_in[18];
  const float* wv2    = (const float*)d_in[19];
  const float* bv2    = (const float*)d_in[20];
  const float* wo2    = (const float*)d_in[21];
  const float* bo2    = (const float*)d_in[22];
  const float* offc1w = (const float*)d_in[23];
  const float* offc1b = (const float*)d_in[24];
  const float* offc2w = (const float*)d_in[25];
  const float* bias2d = (const float*)d_in[26];
  const float* write_w= (const float*)d_in[27];
  const float* write_b= (const float*)d_in[28];
  const float* proj_w = (const float*)d_in[29];
  const float* proj_b = (const float*)d_in[30];
  float* out = (float*)d_out;

  float *xn, *Z, *w1, *w1sum, *W1X, *Xs, *Qw, *Qs, *Kg, *Vg, *Ag, *Ab;
  float *AgWo, *AbWo, *wocs, *AgWoP, *AbWoP, *wocsP, *cvec, *U, *Weff, *beff, *cB;
  uint32_t *wtH, *wtL, *ytH, *ytL, *x2dH, *x2dL, *pbH, *pbL;
  cudaGetSymbolAddress((void**)&xn,    g_xn);
  cudaGetSymbolAddress((void**)&Z,     g_Z);
  cudaGetSymbolAddress((void**)&w1,    g_w1);
  cudaGetSymbolAddress((void**)&w1sum, g_w1sum);
  cudaGetSymbolAddress((void**)&W1X,   g_W1X);
  cudaGetSymbolAddress((void**)&Xs,    g_Xs);
  cudaGetSymbolAddress((void**)&Qw,    g_Qw);
  cudaGetSymbolAddress((void**)&Qs,    g_Qs);
  cudaGetSymbolAddress((void**)&Kg,    g_Kg);
  cudaGetSymbolAddress((void**)&Vg,    g_Vg);
  cudaGetSymbolAddress((void**)&Ag,    g_Ag);
  cudaGetSymbolAddress((void**)&Ab,    g_Ab);
  cudaGetSymbolAddress((void**)&AgWo,  g_AgWo);
  cudaGetSymbolAddress((void**)&AbWo,  g_AbWo);
  cudaGetSymbolAddress((void**)&wocs,  g_wocs);
  cudaGetSymbolAddress((void**)&AgWoP, g_AgWoP);
  cudaGetSymbolAddress((void**)&AbWoP, g_AbWoP);
  cudaGetSymbolAddress((void**)&wocsP, g_wocsP);
  cudaGetSymbolAddress((void**)&cvec,  g_cvec);
  cudaGetSymbolAddress((void**)&U,     g_U);
  cudaGetSymbolAddress((void**)&Weff,  g_Weff);
  cudaGetSymbolAddress((void**)&beff,  g_beff);
  cudaGetSymbolAddress((void**)&cB,    g_cB);
  cudaGetSymbolAddress((void**)&wtH,   g_wtH);
  cudaGetSymbolAddress((void**)&wtL,   g_wtL);
  cudaGetSymbolAddress((void**)&ytH,   g_ytH);
  cudaGetSymbolAddress((void**)&ytL,   g_ytL);
  cudaGetSymbolAddress((void**)&x2dH,  g_x2dH);
  cudaGetSymbolAddress((void**)&x2dL,  g_x2dL);
  cudaGetSymbolAddress((void**)&pbH,   g_pbH);
  cudaGetSymbolAddress((void**)&pbL,   g_pbL);

  // LayerNorm
  ln_kernel<<<BSZ * SEQ, 256>>>(x, ln_w, ln_b, xn);

  // pack constant operands (independent)
  convPair_kernel<<<(KP2 * SEQ) / 256, 256>>>(write_w, wtH, wtL, SEQ, 10);
  convPair_kernel<<<((DM / 2) * DM) / 256, 256>>>(proj_w + (long long)DM * DM, pbH, pbL, DM, 9);

  // offset-net folding
  weff_kernel<<<1, 128>>>(off1_w, off1_b, off2_w, bq, Weff, beff, cB);
  u_kernel<<<DM, 128>>>(wq, Weff, U);

  // Z = xn @ U, then w1
  z_kernel<<<BSZ * SEQ / 8, 256>>>(xn, U, Z);
  w1_kernel<<<dim3(BSZ * NG, SEQ / 256), 256>>>(Z, beff, cB, w1);

  // reductions over L
  w1x_kernel<<<dim3(BSZ, 4), dim3(128, 4)>>>(xn, w1, W1X, Xs, w1sum);

  // Kg/Vg
  kgvg_kernel<<<BSZ * NG, DM>>>(xn, wk, wv, Kg, Vg);

  // Qw/Qs
  rowgemm2<<<dim3(BSZ * NG, DM / 128), 128>>>(W1X, wq, Qw, DM, DM, w1sum, 0.f, bq);
  rowgemm2<<<dim3(BSZ,      DM / 128), 128>>>(Xs,  wq, Qs, DM, DM, nullptr, 1024.f, bq);

  // channel attention
  attn_kernel<<<dim3(BSZ, NH), CH>>>(Qw, Qs, Kg, Vg, bk, bv, Ag, Ab);

  // fold through wo then P_top
  rowgemm2<<<dim3(BSZ * NG, DM / 128), 128>>>(Ag, wo, AgWo, DM, DM, nullptr, 0.f, nullptr);
  rowgemm2<<<dim3(BSZ,      DM / 128), 128>>>(Ab, wo, AbWo, DM, DM, nullptr, 0.f, nullptr);
  rowgemm2<<<dim3(1,        DM / 128), 128>>>((const float*)nullptr, wo, wocs, DM, DM, nullptr, 0.f, nullptr);
  rowgemm2<<<dim3(BSZ * NG, DM / 128), 128>>>(AgWo, proj_w, AgWoP, DM, DM, nullptr, 0.f, nullptr);
  rowgemm2<<<dim3(BSZ,      DM / 128), 128>>>(AbWo, proj_w, AbWoP, DM, DM, nullptr, 0.f, nullptr);
  rowgemm2<<<dim3(1,        DM / 128), 128>>>(wocs, proj_w, wocsP, DM, DM, nullptr, 0.f, nullptr);
  rowgemm2<<<dim3(1,        DM / 128), 128>>>(bo,   proj_w, cvec,  DM, DM, nullptr, 1.f, proj_b);

  // 2D patch branch -> packed yt
  int patch_smem = (int)sizeof(PatchSmem);
  cudaFuncSetAttribute((const void*)patch_kernel,
                       cudaFuncAttributeMaxDynamicSharedMemorySize, patch_smem);
  patch_kernel<<<BSZ * NP, 256, patch_smem>>>(xn, ytH, ytL, offc1w, offc1b, offc2w,
                                              wq2, bq2, wk2, bk2, wv2, bv2, wo2, bo2, bias2d);

  // x2d = write_w^T @ y + write_b   (packed transposed output)
  mma_gemm2<0><<<dim3(DM / 128, SEQ / 128, BSZ), 256, G_SMEM_BYTES>>>(
      wtH, wtL, SEQ, ytH, ytL, DM, (long long)KP2 * DM, DM, P2,
      write_b, nullptr, x2dH, x2dL, BSZ * SEQ, SEQ,
      nullptr, nullptr, nullptr, nullptr, nullptr, nullptr);

  // out = x2d @ P_bot + x1d epilogue
  mma_gemm2<1><<<dim3(DM / 128, BSZ * SEQ / 128, 1), 256, G_SMEM_BYTES>>>(
      x2dH, x2dL, BSZ * SEQ, pbH, pbL, DM, 0, DM, DM,
      nullptr, out, nullptr, nullptr, 0, 0,
      w1, AgWoP, AbWoP, wocsP, cvec, bias1d);
}

// round 8
// speedup vs baseline: 2.4059x; 1.2611x over previous
#include <cuda_runtime.h>
#include <cuda_bf16.h>
#include <math.h>
#include <stdint.h>

// ---------------- problem dims ----------------
constexpr int BSZ = 16;
constexpr int SEQ = 1024;
constexpr int DM  = 512;
constexpr int NG  = 4;
constexpr int CG  = 128;
constexpr int NH  = 8;
constexpr int CH  = 64;
constexpr int NP  = 127;
constexpr int PL  = 16;
constexpr int P2  = NP * PL;   // 2032
constexpr int KP2 = P2 / 2;    // 1016 k-pairs for write GEMM

// ---------------- scratch ----------------
__device__ float g_xn [(size_t)BSZ*SEQ*DM];
__device__ float g_Z  [(size_t)BSZ*SEQ*12];
__device__ float g_w1 [BSZ*NG*SEQ];
__device__ float g_U   [DM*12];
__device__ float g_Weff[3*CG];
__device__ float g_beff[1];
__device__ float g_cB  [12];
// concatenated row-chain buffers
__device__ float g_cat0[80*DM];   // W1X (64) | Xs (16)
__device__ float g_sclq[80];      // w1sum | 1024
__device__ float g_qcat[80*DM];   // Qw | Qs
__device__ float g_cat1[81*DM];   // Ag (64) | Ab (16) | ones (1)
__device__ float g_cat2[82*DM];   // cat1@wo (81) | bo (1)
__device__ float g_scl2[82];      // 0 x81 | 1
__device__ float g_cat3[82*DM];   // AgWoP | AbWoP | wocsP | cvec
__device__ float g_Kg2[BSZ*NG*DM];
__device__ float g_Vg2[BSZ*NG*DM];
// packed bf16-pair operands (uint32 = bf16x2 along k)
__device__ uint32_t g_wtH[(size_t)KP2*SEQ];
__device__ uint32_t g_wtL[(size_t)KP2*SEQ];
__device__ uint32_t g_ytH[(size_t)BSZ*KP2*DM];
__device__ uint32_t g_ytL[(size_t)BSZ*KP2*DM];
__device__ uint32_t g_x2dH[(size_t)(DM/2)*BSZ*SEQ];
__device__ uint32_t g_x2dL[(size_t)(DM/2)*BSZ*SEQ];
__device__ uint32_t g_pbH[(DM/2)*DM];
__device__ uint32_t g_pbL[(DM/2)*DM];

__device__ __forceinline__ float warp_sum(float v) {
  #pragma unroll
  for (int o = 16; o; o >>= 1) v += __shfl_xor_sync(0xffffffffu, v, o);
  return v;
}

__device__ __forceinline__ void split_bf16(float v, uint32_t& hb, uint32_t& lb) {
  __nv_bfloat16 h = __float2bfloat16(v);
  float hf = __bfloat162float(h);
  __nv_bfloat16 l = __float2bfloat16(v - hf);
  hb = (uint32_t)__bfloat16_as_ushort(h);
  lb = (uint32_t)__bfloat16_as_ushort(l);
}
__device__ __forceinline__ void pack_pair(float v0, float v1, uint32_t& hw, uint32_t& lw) {
  uint32_t h0, l0, h1, l1;
  split_bf16(v0, h0, l0);
  split_bf16(v1, h1, l1);
  hw = h0 | (h1 << 16);
  lw = l0 | (l1 << 16);
}
__device__ __forceinline__ void mma_bf16(float* c,
    uint32_t a0, uint32_t a1, uint32_t a2, uint32_t a3,
    uint32_t b0, uint32_t b1) {
  asm volatile(
    "mma.sync.aligned.m16n8k16.row.col.f32.bf16.bf16.f32 "
    "{%0,%1,%2,%3}, {%4,%5,%6,%7}, {%8,%9}, {%0,%1,%2,%3};"
    : "+f"(c[0]), "+f"(c[1]), "+f"(c[2]), "+f"(c[3])
    : "r"(a0), "r"(a1), "r"(a2), "r"(a3), "r"(b0), "r"(b1));
}
__device__ __forceinline__ uint32_t smem_u32(const void* p) {
  uint32_t a;
  asm("{ .reg .u64 t; cvta.to.shared.u64 t, %1; cvt.u32.u64 %0, t; }" : "=r"(a) : "l"(p));
  return a;
}
__device__ __forceinline__ void cp_async16(uint32_t s, const void* g) {
  asm volatile("cp.async.cg.shared.global [%0], [%1], 16;" :: "r"(s), "l"(g));
}

// ---------------- LayerNorm ----------------
__global__ void ln_kernel(const float* __restrict__ x,
                          const float* __restrict__ lw,
                          const float* __restrict__ lb,
                          float* __restrict__ xn) {
  long row = blockIdx.x;
  const float* xr = x + row * DM;
  float* o = xn + row * DM;
  int t = threadIdx.x; // 256
  float v0 = xr[t], v1 = xr[t + 256];
  __shared__ float red[8];
  float s = warp_sum(v0 + v1);
  if ((t & 31) == 0) red[t >> 5] = s;
  __syncthreads();
  float tot = 0;
  #pragma unroll
  for (int i = 0; i < 8; i++) tot += red[i];
  float mu = tot * (1.0f / 512.0f);
  __syncthreads();
  float d0 = v0 - mu, d1 = v1 - mu;
  float sq = warp_sum(d0 * d0 + d1 * d1);
  if ((t & 31) == 0) red[t >> 5] = sq;
  __syncthreads();
  float vtot = 0;
  #pragma unroll
  for (int i = 0; i < 8; i++) vtot += red[i];
  float inv = rsqrtf(vtot * (1.0f / 512.0f) + 1e-5f);
  o[t]       = d0 * inv * lw[t]       + lb[t];
  o[t + 256] = d1 * inv * lw[t + 256] + lb[t + 256];
}

// ---------------- Weff: one block per output element ----------------
__global__ void weff_kernel(const float* __restrict__ off1_w,
                            const float* __restrict__ off2_w,
                            float* __restrict__ Weff) {
  int outi = blockIdx.x;        // 0..383 : (w*128 + i)
  int t = threadIdx.x;          // 128
  __shared__ float red[4];
  float p = off1_w[(long)outi * CG + t] * off2_w[t];
  p = warp_sum(p);
  if ((t & 31) == 0) red[t >> 5] = p;
  __syncthreads();
  if (t == 0) Weff[outi] = red[0] + red[1] + red[2] + red[3];
}

// ---------------- constants: cB, beff, scale vectors, ones/bo rows --------
__global__ void cb_kernel(const float* __restrict__ off1_b,
                          const float* __restrict__ off2_w,
                          const float* __restrict__ bq,
                          const float* __restrict__ bo,
                          const float* __restrict__ Weff,
                          float* __restrict__ beff, float* __restrict__ cB,
                          float* __restrict__ sclq, float* __restrict__ scl2,
                          float* __restrict__ cat1, float* __restrict__ cat2) {
  int t = threadIdx.x; // 128
  if (t < 12) {
    int w = t >> 2, g = t & 3;
    float s = 0.f;
    for (int c = 0; c < CG; c++) s += bq[g * CG + c] * Weff[w * CG + c];
    cB[t] = s;
  } else if (t == 12) {
    float s = 0.f;
    for (int o = 0; o < CG; o++) s += off1_b[o] * off2_w[o];
    *beff = s;
  }
  if (t < 16) sclq[64 + t] = 1024.f;
  if (t < 82) scl2[t] = (t == 81) ? 1.f : 0.f;
  for (int j = t; j < DM; j += 128) {
    cat1[80 * DM + j] = 1.f;      // ones row
    cat2[81 * DM + j] = bo[j];    // bo row
  }
}

// ---------------- U: warp per d, no block syncs ----------------
__global__ void u_kernel(const float* __restrict__ wq, const float* __restrict__ Weff,
                         float* __restrict__ U) {
  int tid = threadIdx.x; // 256
  int warp = tid >> 5, lane = tid & 31;
  int d = blockIdx.x * 8 + warp;
  float wqv[16], we[12];
  #pragma unroll
  for (int g = 0; g < 4; g++)
    #pragma unroll
    for (int k = 0; k < 4; k++)
      wqv[g * 4 + k] = wq[d * DM + g * CG + k * 32 + lane];
  #pragma unroll
  for (int w = 0; w < 3; w++)
    #pragma unroll
    for (int k = 0; k < 4; k++)
      we[w * 4 + k] = Weff[w * CG + k * 32 + lane];
  #pragma unroll
  for (int w = 0; w < 3; w++) {
    #pragma unroll
    for (int g = 0; g < 4; g++) {
      float s = 0.f;
      #pragma unroll
      for (int k = 0; k < 4; k++) s += wqv[g * 4 + k] * we[w * 4 + k];
      s = warp_sum(s);
      if (lane == 0) U[d * 12 + w * 4 + g] = s;
    }
  }
}

__global__ void z_kernel(const float* __restrict__ xn, const float* __restrict__ U,
                         float* __restrict__ Z) {
  __shared__ float Us[DM * 13];
  int tid = threadIdx.x; // 256
  for (int idx = tid; idx < DM * 12; idx += 256) {
    int d = idx / 12, j = idx - d * 12;
    Us[d * 13 + j] = U[idx];
  }
  __syncthreads();
  int warp = tid >> 5, lane = tid & 31;
  long row = (long)blockIdx.x * 8 + warp;
  const float* xr = xn + row * DM;
  float acc[12];
  #pragma unroll
  for (int j = 0; j < 12; j++) acc[j] = 0.f;
  for (int i = lane; i < DM; i += 32) {
    float xv = xr[i];
    #pragma unroll
    for (int j = 0; j < 12; j++) acc[j] += xv * Us[i * 13 + j];
  }
  #pragma unroll
  for (int j = 0; j < 12; j++) acc[j] = warp_sum(acc[j]);
  if (lane == 0) {
    #pragma unroll
    for (int j = 0; j < 12; j++) Z[row * 12 + j] = acc[j];
  }
}

__global__ void w1_kernel(const float* __restrict__ Z, const float* __restrict__ beff,
                          const float* __restrict__ cB, float* __restrict__ w1) {
  int bg = blockIdx.x;
  int b = bg >> 2, g = bg & 3;
  int l = blockIdx.y * 256 + threadIdx.x;
  float s = *beff;
  #pragma unroll
  for (int w = 0; w < 3; w++) {
    int lw = l + w - 1;
    if (lw >= 0 && lw < SEQ)
      s += Z[((long)b * SEQ + lw) * 12 + w * 4 + g] + cB[w * 4 + g];
  }
  float off = tanhf(s) * 3.0f;
  float ixv = ((float)l + off) * (1.0f / 1023.0f) - 0.5f;
  w1[bg * SEQ + l] = 1.0f - fabsf(ixv);
}

// ---------------- W1X|Xs -> cat0, w1sum -> sclq ----------------
__global__ void w1x_kernel(const float* __restrict__ xn, const float* __restrict__ w1,
                           float* __restrict__ cat0, float* __restrict__ sclq) {
  int b = blockIdx.x, ec = blockIdx.y;
  int e = ec * 128 + threadIdx.x;
  int s = threadIdx.y; // 4 strips
  __shared__ float w1s[NG][SEQ];
  __shared__ float red[4][5][128];
  int t = threadIdx.y * 128 + threadIdx.x;
  for (int idx = t; idx < NG * SEQ; idx += 512) w1s[idx >> 10][idx & 1023] = w1[b * NG * SEQ + idx];
  __syncthreads();
  float a0 = 0, a1 = 0, a2 = 0, a3 = 0, as_ = 0;
  int lbeg = s * 256;
  for (int l = lbeg; l < lbeg + 256; l++) {
    float xv = xn[((long)b * SEQ + l) * DM + e];
    a0 += xv * w1s[0][l]; a1 += xv * w1s[1][l];
    a2 += xv * w1s[2][l]; a3 += xv * w1s[3][l];
    as_ += xv;
  }
  red[s][0][threadIdx.x] = a0; red[s][1][threadIdx.x] = a1;
  red[s][2][threadIdx.x] = a2; red[s][3][threadIdx.x] = a3;
  red[s][4][threadIdx.x] = as_;
  __syncthreads();
  if (s == 0) {
    #pragma unroll
    for (int g = 0; g < 4; g++) {
      float v = red[0][g][threadIdx.x] + red[1][g][threadIdx.x] +
                red[2][g][threadIdx.x] + red[3][g][threadIdx.x];
      cat0[(b * NG + g) * DM + e] = v;
    }
    float vq = red[0][4][threadIdx.x] + red[1][4][threadIdx.x] +
               red[2][4][threadIdx.x] + red[3][4][threadIdx.x];
    cat0[(64 + b) * DM + e] = vq;
  }
  if (ec == 0 && s == 0 && threadIdx.x < 4) {
    float acc = 0.f;
    for (int l = 0; l < SEQ; l++) acc += w1s[threadIdx.x][l];
    sclq[b * NG + threadIdx.x] = acc;
  }
}

__global__ void kgvg_kernel(const float* __restrict__ xn,
                            const float* __restrict__ wk, const float* __restrict__ wv,
                            float* __restrict__ Kg, float* __restrict__ Vg) {
  int bg = blockIdx.x; int b = bg >> 2, g = bg & 3;
  int e = threadIdx.x; // 512
  __shared__ float ms[CG];
  if (threadIdx.x < CG)
    ms[threadIdx.x] = 0.5f * (xn[((long)b * SEQ + 511) * DM + g * CG + threadIdx.x] +
                              xn[((long)b * SEQ + 512) * DM + g * CG + threadIdx.x]);
  __syncthreads();
  float sk = 0.f, sv = 0.f;
  for (int c = 0; c < CG; c++) {
    float mv = ms[c];
    sk += mv * wk[(g * CG + c) * DM + e];
    sv += mv * wv[(g * CG + c) * DM + e];
  }
  Kg[bg * DM + e] = sk;
  Vg[bg * DM + e] = sv;
}

__global__ void rowgemm2(const float* __restrict__ A, const float* __restrict__ B,
                         float* __restrict__ C, int K, int N,
                         const float* __restrict__ scalev, float cscale,
                         const float* __restrict__ biasv) {
  int r = blockIdx.x;
  int e = blockIdx.y * 128 + threadIdx.x;
  __shared__ float Ar[1024];
  for (int idx = threadIdx.x; idx < K; idx += 128)
    Ar[idx] = A ? A[(long)r * K + idx] : 1.0f;
  __syncthreads();
  float s = 0.f;
  for (int d = 0; d < K; d++) s += Ar[d] * B[(long)d * N + e];
  if (biasv) {
    float sc = scalev ? scalev[r] : cscale;
    s += sc * biasv[e];
  }
  C[(long)r * N + e] = s;
}

__global__ void attn_kernel(const float* __restrict__ qcat,
                            const float* __restrict__ Kg, const float* __restrict__ Vg,
                            const float* __restrict__ bk, const float* __restrict__ bv,
                            float* __restrict__ cat1) {
  int b = blockIdx.x, h = blockIdx.y;
  int i = threadIdx.x; // 64
  __shared__ float Kgs[NG][CH], Vgs[NG][CH], bks[CH], bvs[CH];
  __shared__ float aa[CH][CH + 1];
  #pragma unroll
  for (int g = 0; g < NG; g++) {
    Kgs[g][i] = Kg[(b * NG + g) * DM + h * CH + i];
    Vgs[g][i] = Vg[(b * NG + g) * DM + h * CH + i];
  }
  bks[i] = bk[h * CH + i];
  bvs[i] = bv[h * CH + i];
  __syncthreads();
  float qw0 = qcat[(b * NG + 0) * DM + h * CH + i];
  float qw1 = qcat[(b * NG + 1) * DM + h * CH + i];
  float qw2 = qcat[(b * NG + 2) * DM + h * CH + i];
  float qw3 = qcat[(b * NG + 3) * DM + h * CH + i];
  float qsv = qcat[(64 + b) * DM + h * CH + i];
  const float scale = 0.044194173824159216f;
  float mx = -1e30f;
  for (int j = 0; j < CH; j++) {
    float s = (qw0 * Kgs[0][j] + qw1 * Kgs[1][j] + qw2 * Kgs[2][j] + qw3 * Kgs[3][j]
               + qsv * bks[j]) * scale;
    aa[i][j] = s;
    mx = fmaxf(mx, s);
  }
  float sm = 0.f;
  for (int j = 0; j < CH; j++) { float e = expf(aa[i][j] - mx); aa[i][j] = e; sm += e; }
  float inv = 1.0f / sm;
  float ag0 = 0, ag1 = 0, ag2 = 0, ag3 = 0, ab = 0;
  for (int j = 0; j < CH; j++) {
    float w = aa[i][j] * inv;
    ag0 += w * Vgs[0][j]; ag1 += w * Vgs[1][j];
    ag2 += w * Vgs[2][j]; ag3 += w * Vgs[3][j];
    ab  += w * bvs[j];
  }
  cat1[(b * NG + 0) * DM + h * CH + i] = ag0;
  cat1[(b * NG + 1) * DM + h * CH + i] = ag1;
  cat1[(b * NG + 2) * DM + h * CH + i] = ag2;
  cat1[(b * NG + 3) * DM + h * CH + i] = ag3;
  cat1[(64 + b) * DM + h * CH + i] = ab;
}

// ---------------- per-patch 2D deformable attention (float4 phases) -------
constexpr int PDW = DM + 4;   // 516, 16B-aligned rows
struct PatchSmem {
  float P[PL][PDW];
  float XS[PL][PDW];
  float sc[PL][PL + 1];
  float attnb[PL];
  float rsP[PL];
  float rsX[PL];
  float red[2][PL][PL];
};

__global__ void patch_kernel(const float* __restrict__ xn,
                             uint32_t* __restrict__ ytH, uint32_t* __restrict__ ytL,
                             const float* __restrict__ offc1w, const float* __restrict__ offc1b,
                             const float* __restrict__ offc2w,
                             const float* __restrict__ wq2, const float* __restrict__ bq2,
                             const float* __restrict__ wk2, const float* __restrict__ bk2,
                             const float* __restrict__ wv2, const float* __restrict__ bv2,
                             const float* __restrict__ wo2, const float* __restrict__ bo2,
                             const float* __restrict__ bias2d) {
  extern __shared__ char smraw[];
  PatchSmem& S = *(PatchSmem*)smraw;
  int pb = blockIdx.x;
  int b = pb / NP, p = pb % NP;
  int tid = threadIdx.x; // 256
  const float* src = xn + ((long)b * SEQ + p * 8) * DM;
  for (int idx = tid; idx < PL * DM / 4; idx += 256) {
    int i = idx >> 7, j4 = (idx & 127) * 4;
    *(float4*)&S.P[i][j4] = *(const float4*)(src + i * DM + j4);
  }
  __syncthreads();

  float WQ2 = *wq2, BQ2 = *bq2;
  float cw[9];
  #pragma unroll
  for (int t = 0; t < 9; t++) cw[t] = offc1w[t];
  float c1b = *offc1b;
  float ow0 = offc2w[0], ow1 = offc2w[1];

  for (int idx = tid; idx < PL * DM; idx += 256) {
    int i = idx >> 9, j = idx & 511;
    float h2 = c1b;
    #pragma unroll
    for (int di = -1; di <= 1; di++) {
      int ii = i + di;
      if (ii < 0 || ii > PL - 1) continue;
      #pragma unroll
      for (int dj = -1; dj <= 1; dj++) {
        int jj = j + dj;
        if (jj < 0 || jj > DM - 1) continue;
        h2 += (WQ2 * S.P[ii][jj] + BQ2) * cw[(di + 1) * 3 + (dj + 1)];
      }
    }
    float ox = tanhf(h2 * ow0) * 3.0f;
    float oy = tanhf(h2 * ow1) * 3.0f;
    float ix = ((float)j + ox) * (512.0f / 511.0f) - 0.5f;
    float iy = ((float)i + oy) * (16.0f / 15.0f) - 0.5f;
    float x0f = floorf(ix), y0f = floorf(iy);
    int x0 = (int)x0f, y0 = (int)y0f;
    float wx = ix - x0f, wy = iy - y0f;
    float acc = 0.f;
    if (x0 >= 0 && x0 < DM && y0 >= 0 && y0 < PL)                 acc += S.P[y0][x0]         * (1 - wx) * (1 - wy);
    if (x0 + 1 >= 0 && x0 + 1 < DM && y0 >= 0 && y0 < PL)         acc += S.P[y0][x0 + 1]     * wx * (1 - wy);
    if (x0 >= 0 && x0 < DM && y0 + 1 >= 0 && y0 + 1 < PL)         acc += S.P[y0 + 1][x0]     * (1 - wx) * wy;
    if (x0 + 1 >= 0 && x0 + 1 < DM && y0 + 1 >= 0 && y0 + 1 < PL) acc += S.P[y0 + 1][x0 + 1] * wx * wy;
    S.XS[i][j] = acc;
  }
  __syncthreads();

  {
    int i = tid >> 4, seg = tid & 15;
    float sp = 0.f, sx = 0.f;
    int w0 = seg * 32;
    for (int w = w0; w < w0 + 32; w++) { sp += S.P[i][w]; sx += S.XS[i][w]; }
    S.red[0][i][seg] = sp;
    S.red[1][i][seg] = sx;
  }
  __syncthreads();
  if (tid < 2 * PL) {
    int arr = tid >> 4, i = tid & 15;
    float s = 0.f;
    #pragma unroll
    for (int seg = 0; seg < 16; seg++) s += S.red[arr][i][seg];
    if (arr == 0) S.rsP[i] = s; else S.rsX[i] = s;
  }
  __syncthreads();

  // sc via affine decomposition, float4 dot
  {
    float WK2 = *wk2, BK2 = *bk2;
    float s1 = WQ2 * WK2, s2 = WQ2 * BK2, s3 = BQ2 * WK2, s4 = 512.0f * BQ2 * BK2;
    int i = tid >> 4, jj = tid & 15;
    const float4* pr = (const float4*)S.P[i];
    const float4* xr = (const float4*)S.XS[jj];
    float dx = 0.f, dy = 0.f, dz = 0.f, dw = 0.f;
    #pragma unroll 4
    for (int w4 = 0; w4 < 128; w4++) {
      float4 a = pr[w4], c = xr[w4];
      dx += a.x * c.x; dy += a.y * c.y; dz += a.z * c.z; dw += a.w * c.w;
    }
    float dot = (dx + dy) + (dz + dw);
    S.sc[i][jj] = s1 * dot + s2 * S.rsP[i] + s3 * S.rsX[jj] + s4;
  }
  __syncthreads();
  if (tid < PL) {
    int i = tid;
    float mx = -1e30f;
    for (int jj = 0; jj < PL; jj++) mx = fmaxf(mx, S.sc[i][jj]);
    float sm = 0.f;
    for (int jj = 0; jj < PL; jj++) { float e = expf(S.sc[i][jj] - mx); S.sc[i][jj] = e; sm += e; }
    float inv = 1.0f / sm;
    float ab = 0.f;
    for (int jj = 0; jj < PL; jj++) { S.sc[i][jj] *= inv; ab += S.sc[i][jj] * bias2d[jj]; }
    S.attnb[i] = ab;
  }
  __syncthreads();

  float WV2 = *wv2, BV2 = *bv2, WO2 = *wo2, BO2 = *bo2;
  // thread computes a row-pair (i2,i2+1) x 4 consecutive w, packed uint4 store
  for (int idx = tid; idx < 8 * 128; idx += 256) {
    int i2 = (idx >> 7) * 2;
    int w4 = (idx & 127) * 4;
    float4 s0 = {0, 0, 0, 0}, s1 = {0, 0, 0, 0};
    #pragma unroll
    for (int jj = 0; jj < PL; jj++) {
      float a0 = S.sc[i2][jj], a1 = S.sc[i2 + 1][jj];
      float4 xv = *(const float4*)&S.XS[jj][w4];
      s0.x += a0 * xv.x; s0.y += a0 * xv.y; s0.z += a0 * xv.z; s0.w += a0 * xv.w;
      s1.x += a1 * xv.x; s1.y += a1 * xv.y; s1.z += a1 * xv.z; s1.w += a1 * xv.w;
    }
    float c0 = BV2 + S.attnb[i2], c1 = BV2 + S.attnb[i2 + 1];
    float o0x = (WV2 * s0.x + c0) * WO2 + BO2, o1x = (WV2 * s1.x + c1) * WO2 + BO2;
    float o0y = (WV2 * s0.y + c0) * WO2 + BO2, o1y = (WV2 * s1.y + c1) * WO2 + BO2;
    float o0z = (WV2 * s0.z + c0) * WO2 + BO2, o1z = (WV2 * s1.z + c1) * WO2 + BO2;
    float o0w = (WV2 * s0.w + c0) * WO2 + BO2, o1w = (WV2 * s1.w + c1) * WO2 + BO2;
    uint4 hv, lv;
    pack_pair(o0x, o1x, hv.x, lv.x);
    pack_pair(o0y, o1y, hv.y, lv.y);
    pack_pair(o0z, o1z, hv.z, lv.z);
    pack_pair(o0w, o1w, hv.w, lv.w);
    long kp = (long)b * KP2 + p * 8 + (i2 >> 1);
    *(uint4*)&ytH[kp * DM + w4] = hv;
    *(uint4*)&ytL[kp * DM + w4] = lv;
  }
}

// ---------------- convert float [K][N] -> packed bf16-pair H/L [K/2][N] ----
__global__ void convPair_kernel(const float* __restrict__ src,
                                uint32_t* __restrict__ dH, uint32_t* __restrict__ dL,
                                int N, int logN) {
  long idx = (long)blockIdx.x * 256 + threadIdx.x;
  int n = (int)(idx & (N - 1));
  long kp = idx >> logN;
  float v0 = src[(2 * kp) * N + n];
  float v1 = src[(2 * kp + 1) * N + n];
  uint32_t hw, lw;
  pack_pair(v0, v1, hw, lw);
  dH[idx] = hw;
  dL[idx] = lw;
}

// ============================================================================
// bf16x3 mma.sync GEMM, pre-packed operands, 3-stage cp.async pipeline,
// one __syncthreads per k-tile.
// ============================================================================
constexpr int MLDP = 136;
constexpr int TSZP = 8 * MLDP;                        // 1088 words
constexpr int G_SMEM_WORDS = 3 * 4 * TSZP + 11 * 128; // 14464
constexpr int G_SMEM_BYTES = G_SMEM_WORDS * 4;        // 57856

template<int EPI>
__global__ __launch_bounds__(256, 2)
void mma_gemm2(const uint32_t* __restrict__ AHg, const uint32_t* __restrict__ ALg, int lda,
               const uint32_t* __restrict__ BHg, const uint32_t* __restrict__ BLg, int ldb,
               long long sB, int N, int K,
               const float* __restrict__ biasM,
               float* __restrict__ Cf,
               uint32_t* __restrict__ CH, uint32_t* __restrict__ CL, int ldc, int zMul,
               const float* __restrict__ w1, const float* __restrict__ cat3,
               const float* __restrict__ bias1d) {
  extern __shared__ uint32_t smu[];
  float* Ep = (float*)(smu + 12 * TSZP);
  float* Rp = Ep + 6 * 128;

  BHg += blockIdx.z * sB;
  BLg += blockIdx.z * sB;
  const int m0 = blockIdx.y * 128, n0 = blockIdx.x * 128;
  const int tid = threadIdx.x;
  const int wid = tid >> 5, lane = tid & 31;
  const int wm = wid >> 2, wn = wid & 3;
  const int grp = lane >> 2, tig = lane & 3;
  const uint32_t smb = smem_u32(smu);

  if (EPI == 1 && tid < 128) {
    int bb = (int)(blockIdx.y >> 3);
    int n = n0 + tid;
    Ep[0 * 128 + tid] = cat3[(64 + bb) * 512 + n] + cat3[81 * 512 + n];
    Ep[1 * 128 + tid] = cat3[80 * 512 + n];
    Ep[2 * 128 + tid] = cat3[(bb * 4 + 0) * 512 + n];
    Ep[3 * 128 + tid] = cat3[(bb * 4 + 1) * 512 + n];
    Ep[4 * 128 + tid] = cat3[(bb * 4 + 2) * 512 + n];
    Ep[5 * 128 + tid] = cat3[(bb * 4 + 3) * 512 + n];
    int l = (m0 & 1023) + tid;
    Rp[0 * 128 + tid] = w1[(bb * 4 + 0) * 1024 + l];
    Rp[1 * 128 + tid] = w1[(bb * 4 + 1) * 1024 + l];
    Rp[2 * 128 + tid] = w1[(bb * 4 + 2) * 1024 + l];
    Rp[3 * 128 + tid] = w1[(bb * 4 + 3) * 1024 + l];
    Rp[4 * 128 + tid] = bias1d[l];
  }

  const int r = tid >> 5;
  const int cc = (tid & 31) * 4;
  auto issue_stage = [&](int kt, int buf) {
    long kp0 = (long)kt * 8 + r;
    uint32_t sd = smb + (uint32_t)(buf * 4 * TSZP + r * MLDP + cc) * 4;
    cp_async16(sd,                AHg + kp0 * lda + m0 + cc);
    cp_async16(sd + TSZP * 4,     ALg + kp0 * lda + m0 + cc);
    cp_async16(sd + 2 * TSZP * 4, BHg + kp0 * ldb + n0 + cc);
    cp_async16(sd + 3 * TSZP * 4, BLg + kp0 * ldb + n0 + cc);
    asm volatile("cp.async.commit_group;");
  };

  float c[4][4][4];
  #pragma unroll
  for (int mi = 0; mi < 4; mi++)
    #pragma unroll
    for (int ni = 0; ni < 4; ni++)
      #pragma unroll
      for (int q = 0; q < 4; q++) c[mi][ni][q] = 0.f;

  const int KT = K / 16;
  issue_stage(0, 0);
  issue_stage(1, 1);
  int buf = 0;
  for (int kt = 0; kt < KT; kt++) {
    if (kt + 1 < KT) {
      asm volatile("cp.async.wait_group 1;");
    } else {
      asm volatile("cp.async.wait_group 0;");
    }
    __syncthreads();
    if (kt + 2 < KT) issue_stage(kt + 2, (kt + 2) % 3);

    const uint32_t* AHs = smu + buf * 4 * TSZP;
    const uint32_t* ALs = AHs + TSZP;
    const uint32_t* BHs = AHs + 2 * TSZP;
    const uint32_t* BLs = AHs + 3 * TSZP;

    uint32_t bH0[4], bH1[4], bL0[4], bL1[4];
    #pragma unroll
    for (int ni = 0; ni < 4; ni++) {
      int n = wn * 32 + ni * 8 + grp;
      bH0[ni] = BHs[tig * MLDP + n];
      bH1[ni] = BHs[(tig + 4) * MLDP + n];
      bL0[ni] = BLs[tig * MLDP + n];
      bL1[ni] = BLs[(tig + 4) * MLDP + n];
    }
    #pragma unroll
    for (int mi = 0; mi < 4; mi++) {
      int m = wm * 64 + mi * 16 + grp;
      uint32_t aH0 = AHs[tig * MLDP + m];
      uint32_t aH1 = AHs[tig * MLDP + m + 8];
      uint32_t aH2 = AHs[(tig + 4) * MLDP + m];
      uint32_t aH3 = AHs[(tig + 4) * MLDP + m + 8];
      uint32_t aL0 = ALs[tig * MLDP + m];
      uint32_t aL1 = ALs[tig * MLDP + m + 8];
      uint32_t aL2 = ALs[(tig + 4) * MLDP + m];
      uint32_t aL3 = ALs[(tig + 4) * MLDP + m + 8];
      #pragma unroll
      for (int ni = 0; ni < 4; ni++) {
        mma_bf16(c[mi][ni], aH0, aH1, aH2, aH3, bH0[ni], bH1[ni]);
        mma_bf16(c[mi][ni], aH0, aH1, aH2, aH3, bL0[ni], bL1[ni]);
        mma_bf16(c[mi][ni], aL0, aL1, aL2, aL3, bH0[ni], bH1[ni]);
      }
    }
    buf = (buf + 1 == 3) ? 0 : buf + 1;
  }

  // ---- epilogue ----
  const int zb = (int)blockIdx.z * zMul;
  #pragma unroll
  for (int mi = 0; mi < 4; mi++) {
    #pragma unroll
    for (int half = 0; half < 2; half++) {
      int ml = wm * 64 + mi * 16 + grp + 8 * half;
      int row = m0 + ml;
      if (EPI == 0) {
        float bm = biasM[row];
        #pragma unroll
        for (int ni = 0; ni < 4; ni++) {
          int nn = wn * 32 + ni * 8 + 2 * tig;
          float v0 = c[mi][ni][2 * half + 0] + bm;
          float v1 = c[mi][ni][2 * half + 1] + bm;
          uint32_t hw, lw;
          pack_pair(v0, v1, hw, lw);
          long o = (long)((n0 + nn) >> 1) * ldc + zb + row;
          CH[o] = hw;
          CL[o] = lw;
        }
      } else {
        float blv = Rp[4 * 128 + ml];
        float w10 = Rp[0 * 128 + ml], w11 = Rp[1 * 128 + ml];
        float w12 = Rp[2 * 128 + ml], w13 = Rp[3 * 128 + ml];
        #pragma unroll
        for (int ni = 0; ni < 4; ni++) {
          int nn = wn * 32 + ni * 8 + 2 * tig;
          float v0 = c[mi][ni][2 * half + 0]
                   + Ep[nn] + blv * Ep[128 + nn]
                   + w10 * Ep[2 * 128 + nn] + w11 * Ep[3 * 128 + nn]
                   + w12 * Ep[4 * 128 + nn] + w13 * Ep[5 * 128 + nn];
          float v1 = c[mi][ni][2 * half + 1]
                   + Ep[nn + 1] + blv * Ep[128 + nn + 1]
                   + w10 * Ep[2 * 128 + nn + 1] + w11 * Ep[3 * 128 + nn + 1]
                   + w12 * Ep[4 * 128 + nn + 1] + w13 * Ep[5 * 128 + nn + 1];
          *(float2*)&Cf[(long)row * N + n0 + nn] = make_float2(v0, v1);
        }
      }
    }
  }
}

// ---------------- host launcher ----------------
extern "C" void kernel_launch(void* const* d_in, const int* in_sizes, int n_in,
                              void* d_out, int out_size) {
  const float* x      = (const float*)d_in[0];
  const float* ln_w   = (const float*)d_in[1];
  const float* ln_b   = (const float*)d_in[2];
  const float* wq     = (const float*)d_in[3];
  const float* bq     = (const float*)d_in[4];
  const float* wk     = (const float*)d_in[5];
  const float* bk     = (const float*)d_in[6];
  const float* wv     = (const float*)d_in[7];
  const float* bv     = (const float*)d_in[8];
  const float* wo     = (const float*)d_in[9];
  const float* bo     = (const float*)d_in[10];
  const float* off1_w = (const float*)d_in[11];
  const float* off1_b = (const float*)d_in[12];
  const float* off2_w = (const float*)d_in[13];
  const float* bias1d = (const float*)d_in[14];
  const float* wq2    = (const float*)d_in[15];
  const float* bq2    = (const float*)d_in[16];
  const float* wk2    = (const float*)d_in[17];
  const float* bk2    = (const float*)d_in[18];
  const float* wv2    = (const float*)d_in[19];
  const float* bv2    = (const float*)d_in[20];
  const float* wo2    = (const float*)d_in[21];
  const float* bo2    = (const float*)d_in[22];
  const float* offc1w = (const float*)d_in[23];
  const float* offc1b = (const float*)d_in[24];
  const float* offc2w = (const float*)d_in[25];
  const float* bias2d = (const float*)d_in[26];
  const float* write_w= (const float*)d_in[27];
  const float* write_b= (const float*)d_in[28];
  const float* proj_w = (const float*)d_in[29];
  const float* proj_b = (const float*)d_in[30];
  float* out = (float*)d_out;

  float *xn, *Z, *w1, *U, *Weff, *beff, *cB;
  float *cat0, *sclq, *qcat, *cat1, *cat2, *scl2, *cat3;
  float *Kg, *Vg;
  uint32_t *wtH, *wtL, *ytH, *ytL, *x2dH, *x2dL, *pbH, *pbL;
  cudaGetSymbolAddress((void**)&xn,    g_xn);
  cudaGetSymbolAddress((void**)&Z,     g_Z);
  cudaGetSymbolAddress((void**)&w1,    g_w1);
  cudaGetSymbolAddress((void**)&U,     g_U);
  cudaGetSymbolAddress((void**)&Weff,  g_Weff);
  cudaGetSymbolAddress((void**)&beff,  g_beff);
  cudaGetSymbolAddress((void**)&cB,    g_cB);
  cudaGetSymbolAddress((void**)&cat0,  g_cat0);
  cudaGetSymbolAddress((void**)&sclq,  g_sclq);
  cudaGetSymbolAddress((void**)&qcat,  g_qcat);
  cudaGetSymbolAddress((void**)&cat1,  g_cat1);
  cudaGetSymbolAddress((void**)&cat2,  g_cat2);
  cudaGetSymbolAddress((void**)&scl2,  g_scl2);
  cudaGetSymbolAddress((void**)&cat3,  g_cat3);
  cudaGetSymbolAddress((void**)&Kg,    g_Kg2);
  cudaGetSymbolAddress((void**)&Vg,    g_Vg2);
  cudaGetSymbolAddress((void**)&wtH,   g_wtH);
  cudaGetSymbolAddress((void**)&wtL,   g_wtL);
  cudaGetSymbolAddress((void**)&ytH,   g_ytH);
  cudaGetSymbolAddress((void**)&ytL,   g_ytL);
  cudaGetSymbolAddress((void**)&x2dH,  g_x2dH);
  cudaGetSymbolAddress((void**)&x2dL,  g_x2dL);
  cudaGetSymbolAddress((void**)&pbH,   g_pbH);
  cudaGetSymbolAddress((void**)&pbL,   g_pbL);

  // LayerNorm
  ln_kernel<<<BSZ * SEQ, 256>>>(x, ln_w, ln_b, xn);

  // pack constant operands
  convPair_kernel<<<(KP2 * SEQ) / 256, 256>>>(write_w, wtH, wtL, SEQ, 10);
  convPair_kernel<<<((DM / 2) * DM) / 256, 256>>>(proj_w + (long long)DM * DM, pbH, pbL, DM, 9);

  // offset-net folding + constants
  weff_kernel<<<3 * CG, 128>>>(off1_w, off2_w, Weff);
  cb_kernel<<<1, 128>>>(off1_b, off2_w, bq, bo, Weff, beff, cB, sclq, scl2, cat1, cat2);
  u_kernel<<<DM / 8, 256>>>(wq, Weff, U);

  // Z, w1
  z_kernel<<<BSZ * SEQ / 8, 256>>>(xn, U, Z);
  w1_kernel<<<dim3(BSZ * NG, SEQ / 256), 256>>>(Z, beff, cB, w1);

  // reductions over L -> cat0, sclq
  w1x_kernel<<<dim3(BSZ, 4), dim3(128, 4)>>>(xn, w1, cat0, sclq);

  // Kg/Vg
  kgvg_kernel<<<BSZ * NG, DM>>>(xn, wk, wv, Kg, Vg);

  // qcat = cat0 @ wq + sclq*bq
  rowgemm2<<<dim3(80, DM / 128), 128>>>(cat0, wq, qcat, DM, DM, sclq, 0.f, bq);

  // channel attention -> cat1 (rows 0..79; ones row 80 pre-set)
  attn_kernel<<<dim3(BSZ, NH), CH>>>(qcat, Kg, Vg, bk, bv, cat1);

  // cat2 = cat1 @ wo (rows 0..80; bo row 81 pre-set)
  rowgemm2<<<dim3(81, DM / 128), 128>>>(cat1, wo, cat2, DM, DM, nullptr, 0.f, nullptr);

  // cat3 = cat2 @ P_top + scl2*proj_b (82 rows)
  rowgemm2<<<dim3(82, DM / 128), 128>>>(cat2, proj_w, cat3, DM, DM, scl2, 0.f, proj_b);

  // 2D patch branch -> packed yt
  int patch_smem = (int)sizeof(PatchSmem);
  cudaFuncSetAttribute((const void*)patch_kernel,
                       cudaFuncAttributeMaxDynamicSharedMemorySize, patch_smem);
  patch_kernel<<<BSZ * NP, 256, patch_smem>>>(xn, ytH, ytL, offc1w, offc1b, offc2w,
                                              wq2, bq2, wk2, bk2, wv2, bv2, wo2, bo2, bias2d);

  // x2d = write_w^T @ y + write_b (packed transposed output)
  cudaFuncSetAttribute((const void*)mma_gemm2<0>,
                       cudaFuncAttributeMaxDynamicSharedMemorySize, G_SMEM_BYTES);
  mma_gemm2<0><<<dim3(DM / 128, SEQ / 128, BSZ), 256, G_SMEM_BYTES>>>(
      wtH, wtL, SEQ, ytH, ytL, DM, (long long)KP2 * DM, DM, P2,
      write_b, nullptr, x2dH, x2dL, BSZ * SEQ, SEQ,
      nullptr, nullptr, nullptr);

  // out = x2d @ P_bot + x1d epilogue
  cudaFuncSetAttribute((const void*)mma_gemm2<1>,
                       cudaFuncAttributeMaxDynamicSharedMemorySize, G_SMEM_BYTES);
  mma_gemm2<1><<<dim3(DM / 128, BSZ * SEQ / 128, 1), 256, G_SMEM_BYTES>>>(
      x2dH, x2dL, BSZ * SEQ, pbH, pbL, DM, 0, DM, DM,
      nullptr, out, nullptr, nullptr, 0, 0,
      w1, cat3, bias1d);
}